// round 8
// baseline (speedup 1.0000x reference)
#include <cuda_runtime.h>
#include <cuda_bf16.h>
#include <math.h>
#include <stdint.h>

#define B_   4096
#define IN_  1024
#define H_   1024
#define F_   128
#define T_   3
#define G_   4096      // 4*H
#define K2_  256       // stored split-bf16 K (hi|lo)
#define LN_EPS 1e-5f

// ---------------- scratch (no allocations allowed) ----------------
__device__ __align__(16) __nv_bfloat16 g_x2[2][2][(size_t)B_ * IN_];  // x/hx hi,lo planes
__device__ __align__(16) __nv_bfloat16 g_wc2[2][2][(size_t)F_ * IN_]; // wc hi,lo planes
__device__ __align__(16) __nv_bfloat16 g_a2[2][(size_t)B_ * K2_];     // stage1 out (hi|lo)
__device__ __align__(16) __nv_bfloat16 g_w2[2][(size_t)G_ * K2_];     // w_*_a  (hi|lo)
__device__ float g_ig[(size_t)B_ * G_];
__device__ float g_hg[(size_t)B_ * G_];

__device__ __forceinline__ uint32_t smem_u32(const void* p) {
    uint32_t a;
    asm("{ .reg .u64 t; cvta.to.shared.u64 t, %1; cvt.u32.u64 %0, t; }"
        : "=r"(a) : "l"(p));
    return a;
}
__device__ __forceinline__ void cp16(uint32_t dst, const void* src) {
    asm volatile("cp.async.cg.shared.global [%0], [%1], 16;"
                 :: "r"(dst), "l"(src));
}
#define CP_COMMIT()  asm volatile("cp.async.commit_group;")
#define CP_WAIT(n)   asm volatile("cp.async.wait_group %0;" :: "n"(n))

__device__ __forceinline__ float f4c(const float4& v, int c) {
    return reinterpret_cast<const float*>(&v)[c];
}

// =====================================================================
// convert_x: x / hx fp32 [4096,1024] -> bf16 hi,lo planes. grid (B_,2)x256
// =====================================================================
__global__ __launch_bounds__(256) void convert_x_kernel(
    const float* __restrict__ xi, const float* __restrict__ xh)
{
    const int path = blockIdx.y, row = blockIdx.x, tid = threadIdx.x;
    const float* x = path ? xh : xi;
    float4 v = reinterpret_cast<const float4*>(x + (size_t)row * IN_)[tid];
    __nv_bfloat16 hx_ = __float2bfloat16(v.x);
    __nv_bfloat16 hy_ = __float2bfloat16(v.y);
    __nv_bfloat16 hz_ = __float2bfloat16(v.z);
    __nv_bfloat16 hw_ = __float2bfloat16(v.w);
    __nv_bfloat162* hi = reinterpret_cast<__nv_bfloat162*>(
        g_x2[path][0] + (size_t)row * IN_);
    __nv_bfloat162* lo = reinterpret_cast<__nv_bfloat162*>(
        g_x2[path][1] + (size_t)row * IN_);
    hi[tid*2]   = __nv_bfloat162(hx_, hy_);
    hi[tid*2+1] = __nv_bfloat162(hz_, hw_);
    lo[tid*2]   = __nv_bfloat162(__float2bfloat16(v.x - __bfloat162float(hx_)),
                                 __float2bfloat16(v.y - __bfloat162float(hy_)));
    lo[tid*2+1] = __nv_bfloat162(__float2bfloat16(v.z - __bfloat162float(hz_)),
                                 __float2bfloat16(v.w - __bfloat162float(hw_)));
}

// =====================================================================
// convert_wc: wc fp32 [128,1024] -> bf16 hi,lo planes. grid (F_,2)x256
// =====================================================================
__global__ __launch_bounds__(256) void convert_wc_kernel(
    const float* __restrict__ wi, const float* __restrict__ wh)
{
    const int path = blockIdx.y, row = blockIdx.x, tid = threadIdx.x;
    const float* w = path ? wh : wi;
    float4 v = reinterpret_cast<const float4*>(w + (size_t)row * IN_)[tid];
    __nv_bfloat16 hx_ = __float2bfloat16(v.x);
    __nv_bfloat16 hy_ = __float2bfloat16(v.y);
    __nv_bfloat16 hz_ = __float2bfloat16(v.z);
    __nv_bfloat16 hw_ = __float2bfloat16(v.w);
    __nv_bfloat162* hi = reinterpret_cast<__nv_bfloat162*>(
        g_wc2[path][0] + (size_t)row * IN_);
    __nv_bfloat162* lo = reinterpret_cast<__nv_bfloat162*>(
        g_wc2[path][1] + (size_t)row * IN_);
    hi[tid*2]   = __nv_bfloat162(hx_, hy_);
    hi[tid*2+1] = __nv_bfloat162(hz_, hw_);
    lo[tid*2]   = __nv_bfloat162(__float2bfloat16(v.x - __bfloat162float(hx_)),
                                 __float2bfloat16(v.y - __bfloat162float(hy_)));
    lo[tid*2+1] = __nv_bfloat162(__float2bfloat16(v.z - __bfloat162float(hz_)),
                                 __float2bfloat16(v.w - __bfloat162float(hw_)));
}

// =====================================================================
// convert_wa: w_*_a fp32 [4096,128] -> bf16 hi|lo [4096,256]. grid (512,2)x256
// =====================================================================
__global__ __launch_bounds__(256) void convert_wa_kernel(
    const float* __restrict__ wi, const float* __restrict__ wh)
{
    const int path = blockIdx.y;
    const int idx  = blockIdx.x * 256 + threadIdx.x;   // float4 index
    const float* w = path ? wh : wi;
    float4 v = reinterpret_cast<const float4*>(w)[idx];
    int n = idx >> 5;            // row (128 cols = 32 float4)
    int f = (idx & 31) * 4;
    __nv_bfloat16 hx_ = __float2bfloat16(v.x);
    __nv_bfloat16 hy_ = __float2bfloat16(v.y);
    __nv_bfloat16 hz_ = __float2bfloat16(v.z);
    __nv_bfloat16 hw_ = __float2bfloat16(v.w);
    __nv_bfloat162* dhi = reinterpret_cast<__nv_bfloat162*>(
        g_w2[path] + (size_t)n * K2_ + f);
    __nv_bfloat162* dlo = reinterpret_cast<__nv_bfloat162*>(
        g_w2[path] + (size_t)n * K2_ + 128 + f);
    dhi[0] = __nv_bfloat162(hx_, hy_);
    dhi[1] = __nv_bfloat162(hz_, hw_);
    dlo[0] = __nv_bfloat162(__float2bfloat16(v.x - __bfloat162float(hx_)),
                            __float2bfloat16(v.y - __bfloat162float(hy_)));
    dlo[1] = __nv_bfloat162(__float2bfloat16(v.z - __bfloat162float(hz_)),
                            __float2bfloat16(v.w - __bfloat162float(hw_)));
}

// =====================================================================
// Stage 1 (mma): C[b,f] = (sum_k x[b,k]*wc[f,k]) * scale(b,f), 3-term comp.
// Tile M=64 x N=128, K chunks of 128 (x8), cp.async double buffer.
// grid (B_/64, 2) = 128 CTAs, 512 thr = 16 warps (4(M) x 4(N)), warp 16x32.
// =====================================================================
#define S1_LD   264
#define S1_ABUF (64 * S1_LD)
#define S1_WBUF (128 * S1_LD)
#define S1_TOT  ((2 * S1_ABUF + 2 * S1_WBUF) * 2)   // 202752 bytes

__device__ __forceinline__ void s1_load_chunk(
    int j, uint32_t aBase, uint32_t wBase,
    const __nv_bfloat16* __restrict__ Ahi, const __nv_bfloat16* __restrict__ Alo,
    const __nv_bfloat16* __restrict__ Whi, const __nv_bfloat16* __restrict__ Wlo,
    int row0, int tid)
{
    #pragma unroll
    for (int it = 0; it < 4; it++) {               // A: 64 rows x 32 chunks
        int idx = tid + it * 512;
        int r = idx >> 5, c = idx & 31;
        int half = c >> 4, cc = c & 15;
        const __nv_bfloat16* src =
            (half ? Alo : Ahi) + (size_t)(row0 + r) * IN_ + j * 128 + cc * 8;
        cp16(aBase + (uint32_t)(r * S1_LD + c * 8) * 2, src);
    }
    #pragma unroll
    for (int it = 0; it < 8; it++) {               // W: 128 rows x 32 chunks
        int idx = tid + it * 512;
        int r = idx >> 5, c = idx & 31;
        int half = c >> 4, cc = c & 15;
        const __nv_bfloat16* src =
            (half ? Wlo : Whi) + (size_t)r * IN_ + j * 128 + cc * 8;
        cp16(wBase + (uint32_t)(r * S1_LD + c * 8) * 2, src);
    }
}

__global__ __launch_bounds__(512) void stage1_mma_kernel(
    const float* __restrict__ topic,
    const float* __restrict__ thw_i, const float* __restrict__ thb_i,
    const float* __restrict__ wb_i,
    const float* __restrict__ thw_h, const float* __restrict__ thb_h,
    const float* __restrict__ wb_h)
{
    extern __shared__ __nv_bfloat16 sm1[];
    __shared__ float sTheta[64][4];

    const int tid  = threadIdx.x;
    const int lane = tid & 31;
    const int wid  = tid >> 5;
    const int path = blockIdx.y;
    const int row0 = blockIdx.x * 64;

    const __nv_bfloat16* __restrict__ Ahi = g_x2[path][0];
    const __nv_bfloat16* __restrict__ Alo = g_x2[path][1];
    const __nv_bfloat16* __restrict__ Whi = g_wc2[path][0];
    const __nv_bfloat16* __restrict__ Wlo = g_wc2[path][1];
    const float* __restrict__ thw = path ? thw_h : thw_i;
    const float* __restrict__ thb = path ? thb_h : thb_i;
    const float* __restrict__ wb  = path ? wb_h  : wb_i;
    __nv_bfloat16* __restrict__ outp = g_a2[path];

    if (tid < 192) {
        int r = tid / 3, t = tid - r * 3;
        const float* tp = topic + (size_t)(row0 + r) * T_;
        sTheta[r][t] = thb[t] + tp[0]*thw[t*T_+0] + tp[1]*thw[t*T_+1] + tp[2]*thw[t*T_+2];
    }

    uint32_t aB[2] = { smem_u32(sm1), smem_u32(sm1 + S1_ABUF) };
    uint32_t wB[2] = { smem_u32(sm1 + 2 * S1_ABUF),
                       smem_u32(sm1 + 2 * S1_ABUF + S1_WBUF) };

    s1_load_chunk(0, aB[0], wB[0], Ahi, Alo, Whi, Wlo, row0, tid);
    CP_COMMIT();

    const int wm = (wid & 3) * 16;                 // 4 M-warps cover 64 rows
    const int wn = (wid >> 2) * 32;                // 4 N-warps cover 128 cols
    const int lr  = lane & 7;
    const int seg = lane >> 3;
    const int l16 = lane & 15;

    float acc[4][4];
    #pragma unroll
    for (int nt = 0; nt < 4; nt++)
        #pragma unroll
        for (int j = 0; j < 4; j++) acc[nt][j] = 0.f;

    for (int j = 0; j < 8; j++) {
        const int bf = j & 1;
        if (j < 7) {
            s1_load_chunk(j + 1, aB[(j+1)&1], wB[(j+1)&1],
                          Ahi, Alo, Whi, Wlo, row0, tid);
            CP_COMMIT();
            CP_WAIT(1);
        } else {
            CP_WAIT(0);
        }
        __syncthreads();

        #pragma unroll
        for (int t = 0; t < 3; t++) {
            #pragma unroll
            for (int s = 0; s < 8; s++) {
                const int acol = ((t == 1) ? 128 : 0) + s * 16 + ((seg >> 1) << 3);
                const int bcol = ((t == 2) ? 128 : 0) + s * 16 + ((l16 >> 3) << 3);

                uint32_t a[4];
                {
                    int arow = wm + lr + ((seg & 1) << 3);
                    uint32_t addr = aB[bf] + (uint32_t)(arow * S1_LD + acol) * 2;
                    asm volatile("ldmatrix.sync.aligned.m8n8.x4.shared.b16 {%0,%1,%2,%3}, [%4];"
                                 : "=r"(a[0]), "=r"(a[1]), "=r"(a[2]), "=r"(a[3])
                                 : "r"(addr));
                }
                uint32_t b[4][2];
                #pragma unroll
                for (int nt = 0; nt < 4; nt++) {
                    int brow = wn + nt * 8 + (l16 & 7);
                    uint32_t addr = wB[bf] + (uint32_t)(brow * S1_LD + bcol) * 2;
                    asm volatile("ldmatrix.sync.aligned.m8n8.x2.shared.b16 {%0,%1}, [%2];"
                                 : "=r"(b[nt][0]), "=r"(b[nt][1])
                                 : "r"(addr));
                }
                #pragma unroll
                for (int nt = 0; nt < 4; nt++) {
                    asm volatile(
                        "mma.sync.aligned.m16n8k16.row.col.f32.bf16.bf16.f32 "
                        "{%0,%1,%2,%3}, {%4,%5,%6,%7}, {%8,%9}, {%0,%1,%2,%3};"
                        : "+f"(acc[nt][0]), "+f"(acc[nt][1]),
                          "+f"(acc[nt][2]), "+f"(acc[nt][3])
                        : "r"(a[0]), "r"(a[1]), "r"(a[2]), "r"(a[3]),
                          "r"(b[nt][0]), "r"(b[nt][1]));
                }
            }
        }
        __syncthreads();
    }

    // ---- epilogue: scale by theta·wb, split hi|lo, write bf162 pairs ----
    const int em = lane >> 2;
    const int en = (lane & 3) * 2;
    #pragma unroll
    for (int nt = 0; nt < 4; nt++) {
        const int n = wn + nt * 8 + en;
        float w0a = wb[n*T_+0],     w1a = wb[n*T_+1],     w2a = wb[n*T_+2];
        float w0b = wb[(n+1)*T_+0], w1b = wb[(n+1)*T_+1], w2b = wb[(n+1)*T_+2];
        #pragma unroll
        for (int half = 0; half < 2; half++) {
            int m = wm + em + half * 8;
            float th0 = sTheta[m][0], th1 = sTheta[m][1], th2 = sTheta[m][2];
            float sc0 = th0*w0a + th1*w1a + th2*w2a;
            float sc1 = th0*w0b + th1*w1b + th2*w2b;
            float v0 = acc[nt][half*2 + 0] * sc0;
            float v1 = acc[nt][half*2 + 1] * sc1;
            __nv_bfloat16 h0 = __float2bfloat16(v0);
            __nv_bfloat16 h1 = __float2bfloat16(v1);
            size_t base = (size_t)(row0 + m) * K2_ + n;
            *reinterpret_cast<__nv_bfloat162*>(&outp[base]) =
                __nv_bfloat162(h0, h1);
            *reinterpret_cast<__nv_bfloat162*>(&outp[base + 128]) =
                __nv_bfloat162(__float2bfloat16(v0 - __bfloat162float(h0)),
                               __float2bfloat16(v1 - __bfloat162float(h1)));
        }
    }
}

// =====================================================================
// Stage 2: bf16 mma GEMM, 3-term via column maps. A-resident, W-streamed.
// Each CTA: one 128-row block, NCT=4 col tiles; W double-buffered cp.async.
// grid = (8, 32, 2), 512 thr = 16 warps (4(M) x 4(N)), warp tile 32x32.
// smem: A[128x264] + 2x W[128x264] = 202752 bytes.
// =====================================================================
#define S2_LD   264
#define S2_TILE (128 * S2_LD)
#define S2_TOT  (3 * S2_TILE * 2)
#define NCT     4

__device__ __forceinline__ void s2_load_w(
    const __nv_bfloat16* __restrict__ W, int col0, uint32_t base, int tid)
{
    #pragma unroll
    for (int it = 0; it < 8; it++) {
        int idx = tid + it * 512;
        int r = idx >> 5, c = idx & 31;
        cp16(base + (uint32_t)(r * S2_LD + c * 8) * 2,
             W + (size_t)(col0 + r) * K2_ + c * 8);
    }
}

__global__ __launch_bounds__(512) void stage2_mma_kernel()
{
    extern __shared__ __nv_bfloat16 sm2[];

    const int tid  = threadIdx.x;
    const int lane = tid & 31;
    const int wid  = tid >> 5;
    const int path = blockIdx.z;
    const int row0 = blockIdx.y * 128;
    const int ct0  = blockIdx.x * NCT;          // first col tile

    const __nv_bfloat16* __restrict__ A = g_a2[path];
    const __nv_bfloat16* __restrict__ W = g_w2[path];
    float* __restrict__ O = path ? g_hg : g_ig;

    const uint32_t as_base = smem_u32(sm2);
    uint32_t wBuf[2] = { smem_u32(sm2 + S2_TILE), smem_u32(sm2 + 2 * S2_TILE) };

    // A tile (stays resident)
    #pragma unroll
    for (int it = 0; it < 8; it++) {
        int idx = tid + it * 512;
        int r = idx >> 5, c = idx & 31;
        cp16(as_base + (uint32_t)(r * S2_LD + c * 8) * 2,
             A + (size_t)(row0 + r) * K2_ + c * 8);
    }
    s2_load_w(W, ct0 * 128, wBuf[0], tid);
    CP_COMMIT();                                 // group: A + W0

    const int wm = (wid & 3) * 32;               // 4 M-warps cover 128 rows
    const int wn = (wid >> 2) * 32;              // 4 N-warps cover 128 cols
    const int lr  = lane & 7;
    const int seg = lane >> 3;
    const int l16 = lane & 15;
    const int em = lane >> 2;
    const int en = (lane & 3) * 2;

    for (int it = 0; it < NCT; it++) {
        const int buf = it & 1;
        if (it + 1 < NCT) {
            s2_load_w(W, (ct0 + it + 1) * 128, wBuf[(it + 1) & 1], tid);
            CP_COMMIT();
            CP_WAIT(1);
        } else {
            CP_WAIT(0);
        }
        __syncthreads();

        float acc[2][4][4];
        #pragma unroll
        for (int mt = 0; mt < 2; mt++)
            #pragma unroll
            for (int nt = 0; nt < 4; nt++)
                #pragma unroll
                for (int j = 0; j < 4; j++) acc[mt][nt][j] = 0.f;

        const uint32_t bs_base = wBuf[buf];
        #pragma unroll
        for (int t = 0; t < 3; t++) {
            #pragma unroll
            for (int s = 0; s < 8; s++) {
                const int acol = ((t == 1) ? 128 : 0) + s * 16 + ((seg >> 1) << 3);
                const int bcol = ((t == 2) ? 128 : 0) + s * 16 + ((l16 >> 3) << 3);

                uint32_t a[2][4];
                #pragma unroll
                for (int mt = 0; mt < 2; mt++) {
                    int arow = wm + mt * 16 + lr + ((seg & 1) << 3);
                    uint32_t addr = as_base + (uint32_t)(arow * S2_LD + acol) * 2;
                    asm volatile("ldmatrix.sync.aligned.m8n8.x4.shared.b16 {%0,%1,%2,%3}, [%4];"
                                 : "=r"(a[mt][0]), "=r"(a[mt][1]),
                                   "=r"(a[mt][2]), "=r"(a[mt][3])
                                 : "r"(addr));
                }
                uint32_t b[4][2];
                #pragma unroll
                for (int nt = 0; nt < 4; nt++) {
                    int brow = wn + nt * 8 + (l16 & 7);
                    uint32_t addr = bs_base + (uint32_t)(brow * S2_LD + bcol) * 2;
                    asm volatile("ldmatrix.sync.aligned.m8n8.x2.shared.b16 {%0,%1}, [%2];"
                                 : "=r"(b[nt][0]), "=r"(b[nt][1])
                                 : "r"(addr));
                }
                #pragma unroll
                for (int mt = 0; mt < 2; mt++)
                    #pragma unroll
                    for (int nt = 0; nt < 4; nt++) {
                        asm volatile(
                            "mma.sync.aligned.m16n8k16.row.col.f32.bf16.bf16.f32 "
                            "{%0,%1,%2,%3}, {%4,%5,%6,%7}, {%8,%9}, {%0,%1,%2,%3};"
                            : "+f"(acc[mt][nt][0]), "+f"(acc[mt][nt][1]),
                              "+f"(acc[mt][nt][2]), "+f"(acc[mt][nt][3])
                            : "r"(a[mt][0]), "r"(a[mt][1]), "r"(a[mt][2]), "r"(a[mt][3]),
                              "r"(b[nt][0]), "r"(b[nt][1]));
                    }
            }
        }

        // ---- epilogue for this col tile ----
        const int col0 = (ct0 + it) * 128;
        #pragma unroll
        for (int mt = 0; mt < 2; mt++) {
            #pragma unroll
            for (int nt = 0; nt < 4; nt++) {
                int m = row0 + wm + mt * 16 + em;
                int n = col0 + wn + nt * 8 + en;
                *reinterpret_cast<float2*>(&O[(size_t)m * G_ + n]) =
                    make_float2(acc[mt][nt][0], acc[mt][nt][1]);
                *reinterpret_cast<float2*>(&O[(size_t)(m + 8) * G_ + n]) =
                    make_float2(acc[mt][nt][2], acc[mt][nt][3]);
            }
        }
        __syncthreads();
    }
}

// =====================================================================
// Stage 3: per-row LN(igates)+LN(hgates), gates, cell update, LN(cell).
// Fully float4-vectorized. One CTA (256 thr) per batch row.
// =====================================================================
__device__ __forceinline__ float sigm(float x) { return 1.f / (1.f + expf(-x)); }

__device__ __forceinline__ float2 block_reduce2(float s, float q, float* red)
{
    __syncthreads();
    #pragma unroll
    for (int o = 16; o > 0; o >>= 1) {
        s += __shfl_xor_sync(0xffffffffu, s, o);
        q += __shfl_xor_sync(0xffffffffu, q, o);
    }
    int w = threadIdx.x >> 5, l = threadIdx.x & 31;
    if (l == 0) { red[w] = s; red[8 + w] = q; }
    __syncthreads();
    if (w == 0) {
        s = (l < 8) ? red[l] : 0.f;
        q = (l < 8) ? red[8 + l] : 0.f;
        #pragma unroll
        for (int o = 4; o > 0; o >>= 1) {
            s += __shfl_xor_sync(0xffffffffu, s, o);
            q += __shfl_xor_sync(0xffffffffu, q, o);
        }
        if (l == 0) { red[0] = s; red[1] = q; }
    }
    __syncthreads();
    return make_float2(red[0], red[1]);
}

__global__ __launch_bounds__(256) void stage3_kernel(
    const float* __restrict__ cx,
    const float* __restrict__ lniw, const float* __restrict__ lnib,
    const float* __restrict__ lnhw, const float* __restrict__ lnhb,
    const float* __restrict__ lncw, const float* __restrict__ lncb,
    float* __restrict__ out)
{
    __shared__ float4 s_ig[1024];
    __shared__ float4 s_hg[1024];
    __shared__ float red[16];

    const int r   = blockIdx.x;
    const int tid = threadIdx.x;
    const float4* __restrict__ ig4 = reinterpret_cast<const float4*>(g_ig + (size_t)r * G_);
    const float4* __restrict__ hg4 = reinterpret_cast<const float4*>(g_hg + (size_t)r * G_);

    float s = 0.f, q = 0.f;
    #pragma unroll
    for (int i = 0; i < 4; i++) {
        int n = tid + i * 256;
        float4 v = ig4[n];
        s_ig[n] = v;
        s += v.x + v.y + v.z + v.w;
        q += v.x*v.x + v.y*v.y + v.z*v.z + v.w*v.w;
    }
    float2 ri = block_reduce2(s, q, red);
    float mu_i = ri.x * (1.f / G_);
    float rstd_i = rsqrtf(ri.y * (1.f / G_) - mu_i * mu_i + LN_EPS);

    s = 0.f; q = 0.f;
    #pragma unroll
    for (int i = 0; i < 4; i++) {
        int n = tid + i * 256;
        float4 v = hg4[n];
        s_hg[n] = v;
        s += v.x + v.y + v.z + v.w;
        q += v.x*v.x + v.y*v.y + v.z*v.z + v.w*v.w;
    }
    float2 rh = block_reduce2(s, q, red);
    float mu_h = rh.x * (1.f / G_);
    float rstd_h = rsqrtf(rh.y * (1.f / G_) - mu_h * mu_h + LN_EPS);

    const float4* lniw4 = reinterpret_cast<const float4*>(lniw);
    const float4* lnib4 = reinterpret_cast<const float4*>(lnib);
    const float4* lnhw4 = reinterpret_cast<const float4*>(lnhw);
    const float4* lnhb4 = reinterpret_cast<const float4*>(lnhb);

    float4 gi_v[4], gh_v[4], wi_v[4], bi_v[4], wh_v[4], bh_v[4];
    #pragma unroll
    for (int g = 0; g < 4; g++) {
        int n = tid + g * 256;
        gi_v[g] = s_ig[n];  gh_v[g] = s_hg[n];
        wi_v[g] = lniw4[n]; bi_v[g] = lnib4[n];
        wh_v[g] = lnhw4[n]; bh_v[g] = lnhb4[n];
    }
    float4 cxv = reinterpret_cast<const float4*>(cx + (size_t)r * H_)[tid];

    float cc[4], oo[4];
    float cs = 0.f, cq = 0.f;
    #pragma unroll
    for (int c = 0; c < 4; c++) {
        #define GVAL(g) ((f4c(gi_v[g],c) - mu_i) * rstd_i * f4c(wi_v[g],c) + f4c(bi_v[g],c) + \
                         (f4c(gh_v[g],c) - mu_h) * rstd_h * f4c(wh_v[g],c) + f4c(bh_v[g],c))
        float gi = sigm(GVAL(0));
        float gf = sigm(GVAL(1));
        float gg = tanhf(GVAL(2));
        float go = sigm(GVAL(3));
        #undef GVAL
        float c_ = gf * f4c(cxv, c) + gi * gg;
        cc[c] = c_; oo[c] = go;
        cs += c_; cq += c_ * c_;
    }
    float2 rc = block_reduce2(cs, cq, red);
    float mu_c = rc.x * (1.f / H_);
    float rstd_c = rsqrtf(rc.y * (1.f / H_) - mu_c * mu_c + LN_EPS);

    float4 wcv = reinterpret_cast<const float4*>(lncw)[tid];
    float4 bcv = reinterpret_cast<const float4*>(lncb)[tid];
    float4 hyv, cyv;
    #pragma unroll
    for (int c = 0; c < 4; c++) {
        float cy = (cc[c] - mu_c) * rstd_c * f4c(wcv, c) + f4c(bcv, c);
        reinterpret_cast<float*>(&cyv)[c] = cy;
        reinterpret_cast<float*>(&hyv)[c] = oo[c] * tanhf(cy);
    }
    float4* out4 = reinterpret_cast<float4*>(out);
    out4[(size_t)r * 256 + tid] = hyv;
    out4[(size_t)B_ * 256 + (size_t)r * 256 + tid] = cyv;
}

// =====================================================================
extern "C" void kernel_launch(void* const* d_in, const int* in_sizes, int n_in,
                              void* d_out, int out_size)
{
    const float* input_ = (const float*)d_in[0];
    const float* hx     = (const float*)d_in[1];
    const float* cx     = (const float*)d_in[2];
    const float* topic  = (const float*)d_in[3];
    const float* w_ih_a = (const float*)d_in[4];
    const float* w_ih_b = (const float*)d_in[5];
    const float* w_ih_c = (const float*)d_in[6];
    const float* w_hh_a = (const float*)d_in[7];
    const float* w_hh_b = (const float*)d_in[8];
    const float* w_hh_c = (const float*)d_in[9];
    const float* th_ih_w = (const float*)d_in[10];
    const float* th_ih_b = (const float*)d_in[11];
    const float* th_hh_w = (const float*)d_in[12];
    const float* th_hh_b = (const float*)d_in[13];
    const float* ln_i_w  = (const float*)d_in[14];
    const float* ln_i_b  = (const float*)d_in[15];
    const float* ln_h_w  = (const float*)d_in[16];
    const float* ln_h_b  = (const float*)d_in[17];
    const float* ln_c_w  = (const float*)d_in[18];
    const float* ln_c_b  = (const float*)d_in[19];

    cudaFuncSetAttribute(stage1_mma_kernel,
                         cudaFuncAttributeMaxDynamicSharedMemorySize, S1_TOT);
    cudaFuncSetAttribute(stage2_mma_kernel,
                         cudaFuncAttributeMaxDynamicSharedMemorySize, S2_TOT);

    convert_x_kernel<<<dim3(B_, 2), 256>>>(input_, hx);
    convert_wc_kernel<<<dim3(F_, 2), 256>>>(w_ih_c, w_hh_c);
    convert_wa_kernel<<<dim3(512, 2), 256>>>(w_ih_a, w_hh_a);

    stage1_mma_kernel<<<dim3(B_ / 64, 2), 512, S1_TOT>>>(
        topic, th_ih_w, th_ih_b, w_ih_b, th_hh_w, th_hh_b, w_hh_b);

    stage2_mma_kernel<<<dim3(G_ / 128 / NCT, B_ / 128, 2), 512, S2_TOT>>>();

    stage3_kernel<<<B_, 256>>>(cx, ln_i_w, ln_i_b, ln_h_w, ln_h_b,
                               ln_c_w, ln_c_b, (float*)d_out);
}

// round 9
// speedup vs baseline: 1.5347x; 1.5347x over previous
#include <cuda_runtime.h>
#include <cuda_bf16.h>
#include <cuda_fp16.h>
#include <math.h>
#include <stdint.h>

#define B_   4096
#define IN_  1024
#define H_   1024
#define F_   128
#define T_   3
#define G_   4096      // 4*H
#define LN_EPS 1e-5f

// ---------------- scratch (no allocations allowed) ----------------
__device__ __align__(16) __nv_bfloat16 g_x2[2][2][(size_t)B_ * IN_];  // x/hx hi,lo planes
__device__ __align__(16) __nv_bfloat16 g_wc2[2][2][(size_t)F_ * IN_]; // wc hi,lo planes
__device__ __align__(16) __half g_a2h[2][(size_t)B_ * F_];            // stage1 out (fp16)
__device__ __align__(16) __half g_w2h[2][(size_t)G_ * F_];            // w_*_a  (fp16)
__device__ float g_ig[(size_t)B_ * G_];
__device__ float g_hg[(size_t)B_ * G_];

__device__ __forceinline__ uint32_t smem_u32(const void* p) {
    uint32_t a;
    asm("{ .reg .u64 t; cvta.to.shared.u64 t, %1; cvt.u32.u64 %0, t; }"
        : "=r"(a) : "l"(p));
    return a;
}
__device__ __forceinline__ void cp16(uint32_t dst, const void* src) {
    asm volatile("cp.async.cg.shared.global [%0], [%1], 16;"
                 :: "r"(dst), "l"(src));
}
#define CP_COMMIT()  asm volatile("cp.async.commit_group;")
#define CP_WAIT(n)   asm volatile("cp.async.wait_group %0;" :: "n"(n))

__device__ __forceinline__ float f4c(const float4& v, int c) {
    return reinterpret_cast<const float*>(&v)[c];
}

// =====================================================================
// convert_x: x / hx fp32 [4096,1024] -> bf16 hi,lo planes. grid (B_,2)x256
// =====================================================================
__global__ __launch_bounds__(256) void convert_x_kernel(
    const float* __restrict__ xi, const float* __restrict__ xh)
{
    const int path = blockIdx.y, row = blockIdx.x, tid = threadIdx.x;
    const float* x = path ? xh : xi;
    float4 v = reinterpret_cast<const float4*>(x + (size_t)row * IN_)[tid];
    __nv_bfloat16 hx_ = __float2bfloat16(v.x);
    __nv_bfloat16 hy_ = __float2bfloat16(v.y);
    __nv_bfloat16 hz_ = __float2bfloat16(v.z);
    __nv_bfloat16 hw_ = __float2bfloat16(v.w);
    __nv_bfloat162* hi = reinterpret_cast<__nv_bfloat162*>(
        g_x2[path][0] + (size_t)row * IN_);
    __nv_bfloat162* lo = reinterpret_cast<__nv_bfloat162*>(
        g_x2[path][1] + (size_t)row * IN_);
    hi[tid*2]   = __nv_bfloat162(hx_, hy_);
    hi[tid*2+1] = __nv_bfloat162(hz_, hw_);
    lo[tid*2]   = __nv_bfloat162(__float2bfloat16(v.x - __bfloat162float(hx_)),
                                 __float2bfloat16(v.y - __bfloat162float(hy_)));
    lo[tid*2+1] = __nv_bfloat162(__float2bfloat16(v.z - __bfloat162float(hz_)),
                                 __float2bfloat16(v.w - __bfloat162float(hw_)));
}

// =====================================================================
// convert_wc: wc fp32 [128,1024] -> bf16 hi,lo planes. grid (F_,2)x256
// =====================================================================
__global__ __launch_bounds__(256) void convert_wc_kernel(
    const float* __restrict__ wi, const float* __restrict__ wh)
{
    const int path = blockIdx.y, row = blockIdx.x, tid = threadIdx.x;
    const float* w = path ? wh : wi;
    float4 v = reinterpret_cast<const float4*>(w + (size_t)row * IN_)[tid];
    __nv_bfloat16 hx_ = __float2bfloat16(v.x);
    __nv_bfloat16 hy_ = __float2bfloat16(v.y);
    __nv_bfloat16 hz_ = __float2bfloat16(v.z);
    __nv_bfloat16 hw_ = __float2bfloat16(v.w);
    __nv_bfloat162* hi = reinterpret_cast<__nv_bfloat162*>(
        g_wc2[path][0] + (size_t)row * IN_);
    __nv_bfloat162* lo = reinterpret_cast<__nv_bfloat162*>(
        g_wc2[path][1] + (size_t)row * IN_);
    hi[tid*2]   = __nv_bfloat162(hx_, hy_);
    hi[tid*2+1] = __nv_bfloat162(hz_, hw_);
    lo[tid*2]   = __nv_bfloat162(__float2bfloat16(v.x - __bfloat162float(hx_)),
                                 __float2bfloat16(v.y - __bfloat162float(hy_)));
    lo[tid*2+1] = __nv_bfloat162(__float2bfloat16(v.z - __bfloat162float(hz_)),
                                 __float2bfloat16(v.w - __bfloat162float(hw_)));
}

// =====================================================================
// convert_wa: w_*_a fp32 [4096,128] -> fp16 [4096,128]. grid (512,2)x256
// =====================================================================
__global__ __launch_bounds__(256) void convert_wa_kernel(
    const float* __restrict__ wi, const float* __restrict__ wh)
{
    const int path = blockIdx.y;
    const int idx  = blockIdx.x * 256 + threadIdx.x;   // float4 index
    const float* w = path ? wh : wi;
    float4 v = reinterpret_cast<const float4*>(w)[idx];
    __half2* d = reinterpret_cast<__half2*>(g_w2h[path]);
    d[idx * 2]     = __floats2half2_rn(v.x, v.y);
    d[idx * 2 + 1] = __floats2half2_rn(v.z, v.w);
}

// =====================================================================
// Stage 1 (mma): C[b,f] = (sum_k x[b,k]*wc[f,k]) * scale(b,f), 3-term comp
// bf16. Tile M=64 x N=128, K chunks of 128 (x8), cp.async double buffer.
// grid (B_/64, 2) = 128 CTAs, 256 thr (8 warps: 2(M) x 4(N)).
// Epilogue writes fp16 single plane into g_a2h.
// =====================================================================
#define S1_LD   264
#define S1_ABUF (64 * S1_LD)
#define S1_WBUF (128 * S1_LD)
#define S1_TOT  ((2 * S1_ABUF + 2 * S1_WBUF) * 2)   // 202752 bytes

__device__ __forceinline__ void s1_load_chunk(
    int j, uint32_t aBase, uint32_t wBase,
    const __nv_bfloat16* __restrict__ Ahi, const __nv_bfloat16* __restrict__ Alo,
    const __nv_bfloat16* __restrict__ Whi, const __nv_bfloat16* __restrict__ Wlo,
    int row0, int tid)
{
    #pragma unroll
    for (int it = 0; it < 8; it++) {               // A: 64 rows x 32 chunks
        int idx = tid + it * 256;
        int r = idx >> 5, c = idx & 31;
        int half = c >> 4, cc = c & 15;
        const __nv_bfloat16* src =
            (half ? Alo : Ahi) + (size_t)(row0 + r) * IN_ + j * 128 + cc * 8;
        cp16(aBase + (uint32_t)(r * S1_LD + c * 8) * 2, src);
    }
    #pragma unroll
    for (int it = 0; it < 16; it++) {              // W: 128 rows x 32 chunks
        int idx = tid + it * 256;
        int r = idx >> 5, c = idx & 31;
        int half = c >> 4, cc = c & 15;
        const __nv_bfloat16* src =
            (half ? Wlo : Whi) + (size_t)r * IN_ + j * 128 + cc * 8;
        cp16(wBase + (uint32_t)(r * S1_LD + c * 8) * 2, src);
    }
}

__global__ __launch_bounds__(256) void stage1_mma_kernel(
    const float* __restrict__ topic,
    const float* __restrict__ thw_i, const float* __restrict__ thb_i,
    const float* __restrict__ wb_i,
    const float* __restrict__ thw_h, const float* __restrict__ thb_h,
    const float* __restrict__ wb_h)
{
    extern __shared__ __nv_bfloat16 sm1[];
    __shared__ float sTheta[64][4];

    const int tid  = threadIdx.x;
    const int lane = tid & 31;
    const int wid  = tid >> 5;
    const int path = blockIdx.y;
    const int row0 = blockIdx.x * 64;

    const __nv_bfloat16* __restrict__ Ahi = g_x2[path][0];
    const __nv_bfloat16* __restrict__ Alo = g_x2[path][1];
    const __nv_bfloat16* __restrict__ Whi = g_wc2[path][0];
    const __nv_bfloat16* __restrict__ Wlo = g_wc2[path][1];
    const float* __restrict__ thw = path ? thw_h : thw_i;
    const float* __restrict__ thb = path ? thb_h : thb_i;
    const float* __restrict__ wb  = path ? wb_h  : wb_i;
    __half* __restrict__ outp = g_a2h[path];

    if (tid < 192) {
        int r = tid / 3, t = tid - r * 3;
        const float* tp = topic + (size_t)(row0 + r) * T_;
        sTheta[r][t] = thb[t] + tp[0]*thw[t*T_+0] + tp[1]*thw[t*T_+1] + tp[2]*thw[t*T_+2];
    }

    uint32_t aB[2] = { smem_u32(sm1), smem_u32(sm1 + S1_ABUF) };
    uint32_t wB[2] = { smem_u32(sm1 + 2 * S1_ABUF),
                       smem_u32(sm1 + 2 * S1_ABUF + S1_WBUF) };

    s1_load_chunk(0, aB[0], wB[0], Ahi, Alo, Whi, Wlo, row0, tid);
    CP_COMMIT();

    const int wm = (wid & 1) * 32;                 // 2 M-warps cover 64 rows
    const int wn = (wid >> 1) * 32;                // 4 N-warps cover 128 cols
    const int lr  = lane & 7;
    const int seg = lane >> 3;
    const int l16 = lane & 15;

    float acc[2][4][4];
    #pragma unroll
    for (int mt = 0; mt < 2; mt++)
        #pragma unroll
        for (int nt = 0; nt < 4; nt++)
            #pragma unroll
            for (int j = 0; j < 4; j++) acc[mt][nt][j] = 0.f;

    for (int j = 0; j < 8; j++) {
        const int bf = j & 1;
        if (j < 7) {
            s1_load_chunk(j + 1, aB[(j+1)&1], wB[(j+1)&1],
                          Ahi, Alo, Whi, Wlo, row0, tid);
            CP_COMMIT();
            CP_WAIT(1);
        } else {
            CP_WAIT(0);
        }
        __syncthreads();

        #pragma unroll
        for (int t = 0; t < 3; t++) {
            #pragma unroll
            for (int s = 0; s < 8; s++) {
                const int acol = ((t == 1) ? 128 : 0) + s * 16 + ((seg >> 1) << 3);
                const int bcol = ((t == 2) ? 128 : 0) + s * 16 + ((l16 >> 3) << 3);

                uint32_t a[2][4];
                #pragma unroll
                for (int mt = 0; mt < 2; mt++) {
                    int arow = wm + mt * 16 + lr + ((seg & 1) << 3);
                    uint32_t addr = aB[bf] + (uint32_t)(arow * S1_LD + acol) * 2;
                    asm volatile("ldmatrix.sync.aligned.m8n8.x4.shared.b16 {%0,%1,%2,%3}, [%4];"
                                 : "=r"(a[mt][0]), "=r"(a[mt][1]),
                                   "=r"(a[mt][2]), "=r"(a[mt][3])
                                 : "r"(addr));
                }
                uint32_t b[4][2];
                #pragma unroll
                for (int nt = 0; nt < 4; nt++) {
                    int brow = wn + nt * 8 + (l16 & 7);
                    uint32_t addr = wB[bf] + (uint32_t)(brow * S1_LD + bcol) * 2;
                    asm volatile("ldmatrix.sync.aligned.m8n8.x2.shared.b16 {%0,%1}, [%2];"
                                 : "=r"(b[nt][0]), "=r"(b[nt][1])
                                 : "r"(addr));
                }
                #pragma unroll
                for (int mt = 0; mt < 2; mt++)
                    #pragma unroll
                    for (int nt = 0; nt < 4; nt++) {
                        asm volatile(
                            "mma.sync.aligned.m16n8k16.row.col.f32.bf16.bf16.f32 "
                            "{%0,%1,%2,%3}, {%4,%5,%6,%7}, {%8,%9}, {%0,%1,%2,%3};"
                            : "+f"(acc[mt][nt][0]), "+f"(acc[mt][nt][1]),
                              "+f"(acc[mt][nt][2]), "+f"(acc[mt][nt][3])
                            : "r"(a[mt][0]), "r"(a[mt][1]), "r"(a[mt][2]), "r"(a[mt][3]),
                              "r"(b[nt][0]), "r"(b[nt][1]));
                    }
            }
        }
        __syncthreads();
    }

    // ---- epilogue: scale by theta·wb, write fp16 pairs ----
    const int em = lane >> 2;
    const int en = (lane & 3) * 2;
    #pragma unroll
    for (int nt = 0; nt < 4; nt++) {
        const int n = wn + nt * 8 + en;
        float w0a = wb[n*T_+0],     w1a = wb[n*T_+1],     w2a = wb[n*T_+2];
        float w0b = wb[(n+1)*T_+0], w1b = wb[(n+1)*T_+1], w2b = wb[(n+1)*T_+2];
        #pragma unroll
        for (int mt = 0; mt < 2; mt++) {
            #pragma unroll
            for (int half = 0; half < 2; half++) {
                int m = wm + mt * 16 + em + half * 8;
                float th0 = sTheta[m][0], th1 = sTheta[m][1], th2 = sTheta[m][2];
                float sc0 = th0*w0a + th1*w1a + th2*w2a;
                float sc1 = th0*w0b + th1*w1b + th2*w2b;
                float v0 = acc[mt][nt][half*2 + 0] * sc0;
                float v1 = acc[mt][nt][half*2 + 1] * sc1;
                *reinterpret_cast<__half2*>(&outp[(size_t)(row0 + m) * F_ + n]) =
                    __floats2half2_rn(v0, v1);
            }
        }
    }
}

// =====================================================================
// Stage 2: fp16 mma GEMM, single term, K=128. A-resident, W-streamed.
// Each CTA: 128-row block, NCT=4 col tiles; W double-buffered cp.async.
// grid = (8, 32, 2), 256 thr (8 warps 2x4), warp tile 64x32.
// smem: A[128x136] + 2x W[128x136] fp16 = 104448 bytes (2 CTAs/SM).
// =====================================================================
#define S2_LD   136
#define S2_TILE (128 * S2_LD)
#define S2_TOT  (3 * S2_TILE * 2)      // 104448
#define NCT     4

__device__ __forceinline__ void s2_load_w(
    const __half* __restrict__ W, int col0, uint32_t base, int tid)
{
    #pragma unroll
    for (int it = 0; it < 8; it++) {
        int idx = tid + it * 256;
        int r = idx >> 4, c = idx & 15;
        cp16(base + (uint32_t)(r * S2_LD + c * 8) * 2,
             W + (size_t)(col0 + r) * F_ + c * 8);
    }
}

__global__ __launch_bounds__(256, 2) void stage2_mma_kernel()
{
    extern __shared__ __half sm2[];

    const int tid  = threadIdx.x;
    const int lane = tid & 31;
    const int wid  = tid >> 5;
    const int path = blockIdx.z;
    const int row0 = blockIdx.y * 128;
    const int ct0  = blockIdx.x * NCT;          // first col tile

    const __half* __restrict__ A = g_a2h[path];
    const __half* __restrict__ W = g_w2h[path];
    float* __restrict__ O = path ? g_hg : g_ig;

    const uint32_t as_base = smem_u32(sm2);
    uint32_t wBuf[2] = { smem_u32(sm2 + S2_TILE), smem_u32(sm2 + 2 * S2_TILE) };

    // A tile (stays resident): 128 rows x 16 chunks
    #pragma unroll
    for (int it = 0; it < 8; it++) {
        int idx = tid + it * 256;
        int r = idx >> 4, c = idx & 15;
        cp16(as_base + (uint32_t)(r * S2_LD + c * 8) * 2,
             A + (size_t)(row0 + r) * F_ + c * 8);
    }
    s2_load_w(W, ct0 * 128, wBuf[0], tid);
    CP_COMMIT();                                 // group: A + W0

    const int wm = (wid & 1) * 64;               // 2 M-warps cover 128 rows
    const int wn = (wid >> 1) * 32;              // 4 N-warps cover 128 cols
    const int lr  = lane & 7;
    const int seg = lane >> 3;
    const int l16 = lane & 15;
    const int em = lane >> 2;
    const int en = (lane & 3) * 2;

    for (int it = 0; it < NCT; it++) {
        const int buf = it & 1;
        if (it + 1 < NCT) {
            s2_load_w(W, (ct0 + it + 1) * 128, wBuf[(it + 1) & 1], tid);
            CP_COMMIT();
            CP_WAIT(1);
        } else {
            CP_WAIT(0);
        }
        __syncthreads();

        float acc[4][4][4];
        #pragma unroll
        for (int mt = 0; mt < 4; mt++)
            #pragma unroll
            for (int nt = 0; nt < 4; nt++)
                #pragma unroll
                for (int j = 0; j < 4; j++) acc[mt][nt][j] = 0.f;

        const uint32_t bs_base = wBuf[buf];
        #pragma unroll
        for (int s = 0; s < 8; s++) {
            const int acol = s * 16 + ((seg >> 1) << 3);
            const int bcol = s * 16 + ((l16 >> 3) << 3);

            uint32_t a[4][4];
            #pragma unroll
            for (int mt = 0; mt < 4; mt++) {
                int arow = wm + mt * 16 + lr + ((seg & 1) << 3);
                uint32_t addr = as_base + (uint32_t)(arow * S2_LD + acol) * 2;
                asm volatile("ldmatrix.sync.aligned.m8n8.x4.shared.b16 {%0,%1,%2,%3}, [%4];"
                             : "=r"(a[mt][0]), "=r"(a[mt][1]),
                               "=r"(a[mt][2]), "=r"(a[mt][3])
                             : "r"(addr));
            }
            uint32_t b[4][2];
            #pragma unroll
            for (int nt = 0; nt < 4; nt++) {
                int brow = wn + nt * 8 + (l16 & 7);
                uint32_t addr = bs_base + (uint32_t)(brow * S2_LD + bcol) * 2;
                asm volatile("ldmatrix.sync.aligned.m8n8.x2.shared.b16 {%0,%1}, [%2];"
                             : "=r"(b[nt][0]), "=r"(b[nt][1])
                             : "r"(addr));
            }
            #pragma unroll
            for (int mt = 0; mt < 4; mt++)
                #pragma unroll
                for (int nt = 0; nt < 4; nt++) {
                    asm volatile(
                        "mma.sync.aligned.m16n8k16.row.col.f32.f16.f16.f32 "
                        "{%0,%1,%2,%3}, {%4,%5,%6,%7}, {%8,%9}, {%0,%1,%2,%3};"
                        : "+f"(acc[mt][nt][0]), "+f"(acc[mt][nt][1]),
                          "+f"(acc[mt][nt][2]), "+f"(acc[mt][nt][3])
                        : "r"(a[mt][0]), "r"(a[mt][1]), "r"(a[mt][2]), "r"(a[mt][3]),
                          "r"(b[nt][0]), "r"(b[nt][1]));
                }
        }

        // ---- epilogue for this col tile ----
        const int col0 = (ct0 + it) * 128;
        #pragma unroll
        for (int mt = 0; mt < 4; mt++) {
            #pragma unroll
            for (int nt = 0; nt < 4; nt++) {
                int m = row0 + wm + mt * 16 + em;
                int n = col0 + wn + nt * 8 + en;
                *reinterpret_cast<float2*>(&O[(size_t)m * G_ + n]) =
                    make_float2(acc[mt][nt][0], acc[mt][nt][1]);
                *reinterpret_cast<float2*>(&O[(size_t)(m + 8) * G_ + n]) =
                    make_float2(acc[mt][nt][2], acc[mt][nt][3]);
            }
        }
        __syncthreads();
    }
}

// =====================================================================
// Stage 3: per-row LN(igates)+LN(hgates), gates, cell update, LN(cell).
// Fully float4-vectorized. One CTA (256 thr) per batch row.
// =====================================================================
__device__ __forceinline__ float sigm(float x) { return 1.f / (1.f + expf(-x)); }

__device__ __forceinline__ float2 block_reduce2(float s, float q, float* red)
{
    __syncthreads();
    #pragma unroll
    for (int o = 16; o > 0; o >>= 1) {
        s += __shfl_xor_sync(0xffffffffu, s, o);
        q += __shfl_xor_sync(0xffffffffu, q, o);
    }
    int w = threadIdx.x >> 5, l = threadIdx.x & 31;
    if (l == 0) { red[w] = s; red[8 + w] = q; }
    __syncthreads();
    if (w == 0) {
        s = (l < 8) ? red[l] : 0.f;
        q = (l < 8) ? red[8 + l] : 0.f;
        #pragma unroll
        for (int o = 4; o > 0; o >>= 1) {
            s += __shfl_xor_sync(0xffffffffu, s, o);
            q += __shfl_xor_sync(0xffffffffu, q, o);
        }
        if (l == 0) { red[0] = s; red[1] = q; }
    }
    __syncthreads();
    return make_float2(red[0], red[1]);
}

__global__ __launch_bounds__(256) void stage3_kernel(
    const float* __restrict__ cx,
    const float* __restrict__ lniw, const float* __restrict__ lnib,
    const float* __restrict__ lnhw, const float* __restrict__ lnhb,
    const float* __restrict__ lncw, const float* __restrict__ lncb,
    float* __restrict__ out)
{
    __shared__ float4 s_ig[1024];
    __shared__ float4 s_hg[1024];
    __shared__ float red[16];

    const int r   = blockIdx.x;
    const int tid = threadIdx.x;
    const float4* __restrict__ ig4 = reinterpret_cast<const float4*>(g_ig + (size_t)r * G_);
    const float4* __restrict__ hg4 = reinterpret_cast<const float4*>(g_hg + (size_t)r * G_);

    float s = 0.f, q = 0.f;
    #pragma unroll
    for (int i = 0; i < 4; i++) {
        int n = tid + i * 256;
        float4 v = ig4[n];
        s_ig[n] = v;
        s += v.x + v.y + v.z + v.w;
        q += v.x*v.x + v.y*v.y + v.z*v.z + v.w*v.w;
    }
    float2 ri = block_reduce2(s, q, red);
    float mu_i = ri.x * (1.f / G_);
    float rstd_i = rsqrtf(ri.y * (1.f / G_) - mu_i * mu_i + LN_EPS);

    s = 0.f; q = 0.f;
    #pragma unroll
    for (int i = 0; i < 4; i++) {
        int n = tid + i * 256;
        float4 v = hg4[n];
        s_hg[n] = v;
        s += v.x + v.y + v.z + v.w;
        q += v.x*v.x + v.y*v.y + v.z*v.z + v.w*v.w;
    }
    float2 rh = block_reduce2(s, q, red);
    float mu_h = rh.x * (1.f / G_);
    float rstd_h = rsqrtf(rh.y * (1.f / G_) - mu_h * mu_h + LN_EPS);

    const float4* lniw4 = reinterpret_cast<const float4*>(lniw);
    const float4* lnib4 = reinterpret_cast<const float4*>(lnib);
    const float4* lnhw4 = reinterpret_cast<const float4*>(lnhw);
    const float4* lnhb4 = reinterpret_cast<const float4*>(lnhb);

    float4 gi_v[4], gh_v[4], wi_v[4], bi_v[4], wh_v[4], bh_v[4];
    #pragma unroll
    for (int g = 0; g < 4; g++) {
        int n = tid + g * 256;
        gi_v[g] = s_ig[n];  gh_v[g] = s_hg[n];
        wi_v[g] = lniw4[n]; bi_v[g] = lnib4[n];
        wh_v[g] = lnhw4[n]; bh_v[g] = lnhb4[n];
    }
    float4 cxv = reinterpret_cast<const float4*>(cx + (size_t)r * H_)[tid];

    float cc[4], oo[4];
    float cs = 0.f, cq = 0.f;
    #pragma unroll
    for (int c = 0; c < 4; c++) {
        #define GVAL(g) ((f4c(gi_v[g],c) - mu_i) * rstd_i * f4c(wi_v[g],c) + f4c(bi_v[g],c) + \
                         (f4c(gh_v[g],c) - mu_h) * rstd_h * f4c(wh_v[g],c) + f4c(bh_v[g],c))
        float gi = sigm(GVAL(0));
        float gf = sigm(GVAL(1));
        float gg = tanhf(GVAL(2));
        float go = sigm(GVAL(3));
        #undef GVAL
        float c_ = gf * f4c(cxv, c) + gi * gg;
        cc[c] = c_; oo[c] = go;
        cs += c_; cq += c_ * c_;
    }
    float2 rc = block_reduce2(cs, cq, red);
    float mu_c = rc.x * (1.f / H_);
    float rstd_c = rsqrtf(rc.y * (1.f / H_) - mu_c * mu_c + LN_EPS);

    float4 wcv = reinterpret_cast<const float4*>(lncw)[tid];
    float4 bcv = reinterpret_cast<const float4*>(lncb)[tid];
    float4 hyv, cyv;
    #pragma unroll
    for (int c = 0; c < 4; c++) {
        float cy = (cc[c] - mu_c) * rstd_c * f4c(wcv, c) + f4c(bcv, c);
        reinterpret_cast<float*>(&cyv)[c] = cy;
        reinterpret_cast<float*>(&hyv)[c] = oo[c] * tanhf(cy);
    }
    float4* out4 = reinterpret_cast<float4*>(out);
    out4[(size_t)r * 256 + tid] = hyv;
    out4[(size_t)B_ * 256 + (size_t)r * 256 + tid] = cyv;
}

// =====================================================================
extern "C" void kernel_launch(void* const* d_in, const int* in_sizes, int n_in,
                              void* d_out, int out_size)
{
    const float* input_ = (const float*)d_in[0];
    const float* hx     = (const float*)d_in[1];
    const float* cx     = (const float*)d_in[2];
    const float* topic  = (const float*)d_in[3];
    const float* w_ih_a = (const float*)d_in[4];
    const float* w_ih_b = (const float*)d_in[5];
    const float* w_ih_c = (const float*)d_in[6];
    const float* w_hh_a = (const float*)d_in[7];
    const float* w_hh_b = (const float*)d_in[8];
    const float* w_hh_c = (const float*)d_in[9];
    const float* th_ih_w = (const float*)d_in[10];
    const float* th_ih_b = (const float*)d_in[11];
    const float* th_hh_w = (const float*)d_in[12];
    const float* th_hh_b = (const float*)d_in[13];
    const float* ln_i_w  = (const float*)d_in[14];
    const float* ln_i_b  = (const float*)d_in[15];
    const float* ln_h_w  = (const float*)d_in[16];
    const float* ln_h_b  = (const float*)d_in[17];
    const float* ln_c_w  = (const float*)d_in[18];
    const float* ln_c_b  = (const float*)d_in[19];

    cudaFuncSetAttribute(stage1_mma_kernel,
                         cudaFuncAttributeMaxDynamicSharedMemorySize, S1_TOT);
    cudaFuncSetAttribute(stage2_mma_kernel,
                         cudaFuncAttributeMaxDynamicSharedMemorySize, S2_TOT);

    convert_x_kernel<<<dim3(B_, 2), 256>>>(input_, hx);
    convert_wc_kernel<<<dim3(F_, 2), 256>>>(w_ih_c, w_hh_c);
    convert_wa_kernel<<<dim3(512, 2), 256>>>(w_ih_a, w_hh_a);

    stage1_mma_kernel<<<dim3(B_ / 64, 2), 256, S1_TOT>>>(
        topic, th_ih_w, th_ih_b, w_ih_b, th_hh_w, th_hh_b, w_hh_b);

    stage2_mma_kernel<<<dim3(G_ / 128 / NCT, B_ / 128, 2), 256, S2_TOT>>>();

    stage3_kernel<<<B_, 256>>>(cx, ln_i_w, ln_i_b, ln_h_w, ln_h_b,
                               ln_c_w, ln_c_b, (float*)d_out);
}

// round 10
// speedup vs baseline: 1.7322x; 1.1287x over previous
#include <cuda_runtime.h>
#include <cuda_bf16.h>
#include <cuda_fp16.h>
#include <math.h>
#include <stdint.h>

#define B_   4096
#define IN_  1024
#define H_   1024
#define F_   128
#define T_   3
#define G_   4096      // 4*H
#define LN_EPS 1e-5f

// ---------------- scratch (no allocations allowed) ----------------
__device__ __align__(16) __half g_xh[2][(size_t)B_ * IN_];   // x/hx fp16
__device__ __align__(16) __half g_wch[2][(size_t)F_ * IN_];  // wc fp16
__device__ __align__(16) __half g_a2h[2][(size_t)B_ * F_];   // stage1 out (fp16)
__device__ __align__(16) __half g_w2h[2][(size_t)G_ * F_];   // w_*_a  (fp16)
__device__ __align__(16) __half g_gates[2][(size_t)B_ * G_]; // ig / hg (fp16)

__device__ __forceinline__ uint32_t smem_u32(const void* p) {
    uint32_t a;
    asm("{ .reg .u64 t; cvta.to.shared.u64 t, %1; cvt.u32.u64 %0, t; }"
        : "=r"(a) : "l"(p));
    return a;
}
__device__ __forceinline__ void cp16(uint32_t dst, const void* src) {
    asm volatile("cp.async.cg.shared.global [%0], [%1], 16;"
                 :: "r"(dst), "l"(src));
}
#define CP_COMMIT()  asm volatile("cp.async.commit_group;")
#define CP_WAIT(n)   asm volatile("cp.async.wait_group %0;" :: "n"(n))

__device__ __forceinline__ float f4c(const float4& v, int c) {
    return reinterpret_cast<const float*>(&v)[c];
}

// =====================================================================
// convert_x: x / hx fp32 [4096,1024] -> fp16. grid (B_,2)x256
// =====================================================================
__global__ __launch_bounds__(256) void convert_x_kernel(
    const float* __restrict__ xi, const float* __restrict__ xh)
{
    const int path = blockIdx.y, row = blockIdx.x, tid = threadIdx.x;
    const float* x = path ? xh : xi;
    float4 v = reinterpret_cast<const float4*>(x + (size_t)row * IN_)[tid];
    __half2* d = reinterpret_cast<__half2*>(g_xh[path] + (size_t)row * IN_);
    d[tid*2]   = __floats2half2_rn(v.x, v.y);
    d[tid*2+1] = __floats2half2_rn(v.z, v.w);
}

// =====================================================================
// convert_wc: wc fp32 [128,1024] -> fp16. grid (F_,2)x256
// =====================================================================
__global__ __launch_bounds__(256) void convert_wc_kernel(
    const float* __restrict__ wi, const float* __restrict__ wh)
{
    const int path = blockIdx.y, row = blockIdx.x, tid = threadIdx.x;
    const float* w = path ? wh : wi;
    float4 v = reinterpret_cast<const float4*>(w + (size_t)row * IN_)[tid];
    __half2* d = reinterpret_cast<__half2*>(g_wch[path] + (size_t)row * IN_);
    d[tid*2]   = __floats2half2_rn(v.x, v.y);
    d[tid*2+1] = __floats2half2_rn(v.z, v.w);
}

// =====================================================================
// convert_wa: w_*_a fp32 [4096,128] -> fp16 [4096,128]. grid (512,2)x256
// =====================================================================
__global__ __launch_bounds__(256) void convert_wa_kernel(
    const float* __restrict__ wi, const float* __restrict__ wh)
{
    const int path = blockIdx.y;
    const int idx  = blockIdx.x * 256 + threadIdx.x;   // float4 index
    const float* w = path ? wh : wi;
    float4 v = reinterpret_cast<const float4*>(w)[idx];
    __half2* d = reinterpret_cast<__half2*>(g_w2h[path]);
    d[idx * 2]     = __floats2half2_rn(v.x, v.y);
    d[idx * 2 + 1] = __floats2half2_rn(v.z, v.w);
}

// =====================================================================
// Stage 1 (mma, fp16 single term): C[b,f] = (x @ wc^T)[b,f] * scale(b,f).
// Tile M=64 x N=128, K=1024 in chunks of 128 (x8), cp.async double buffer.
// grid (B_/64, 2) = 128 CTAs, 256 thr (8 warps: 2(M) x 4(N)).
// smem: 2 x (A 64x136 + W 128x136) fp16 = 104448 bytes.
// =====================================================================
#define S1_LD   136
#define S1_ABUF (64 * S1_LD)
#define S1_WBUF (128 * S1_LD)
#define S1_TOT  ((2 * S1_ABUF + 2 * S1_WBUF) * 2)   // 104448

__device__ __forceinline__ void s1_load_chunk(
    int j, uint32_t aBase, uint32_t wBase,
    const __half* __restrict__ A, const __half* __restrict__ W,
    int row0, int tid)
{
    #pragma unroll
    for (int it = 0; it < 4; it++) {               // A: 64 rows x 16 chunks
        int idx = tid + it * 256;
        int r = idx >> 4, c = idx & 15;
        cp16(aBase + (uint32_t)(r * S1_LD + c * 8) * 2,
             A + (size_t)(row0 + r) * IN_ + j * 128 + c * 8);
    }
    #pragma unroll
    for (int it = 0; it < 8; it++) {               // W: 128 rows x 16 chunks
        int idx = tid + it * 256;
        int r = idx >> 4, c = idx & 15;
        cp16(wBase + (uint32_t)(r * S1_LD + c * 8) * 2,
             W + (size_t)r * IN_ + j * 128 + c * 8);
    }
}

__global__ __launch_bounds__(256) void stage1_mma_kernel(
    const float* __restrict__ topic,
    const float* __restrict__ thw_i, const float* __restrict__ thb_i,
    const float* __restrict__ wb_i,
    const float* __restrict__ thw_h, const float* __restrict__ thb_h,
    const float* __restrict__ wb_h)
{
    extern __shared__ __half sm1[];
    __shared__ float sTheta[64][4];

    const int tid  = threadIdx.x;
    const int lane = tid & 31;
    const int wid  = tid >> 5;
    const int path = blockIdx.y;
    const int row0 = blockIdx.x * 64;

    const __half* __restrict__ A = g_xh[path];
    const __half* __restrict__ W = g_wch[path];
    const float* __restrict__ thw = path ? thw_h : thw_i;
    const float* __restrict__ thb = path ? thb_h : thb_i;
    const float* __restrict__ wb  = path ? wb_h  : wb_i;
    __half* __restrict__ outp = g_a2h[path];

    if (tid < 192) {
        int r = tid / 3, t = tid - r * 3;
        const float* tp = topic + (size_t)(row0 + r) * T_;
        sTheta[r][t] = thb[t] + tp[0]*thw[t*T_+0] + tp[1]*thw[t*T_+1] + tp[2]*thw[t*T_+2];
    }

    uint32_t aB[2] = { smem_u32(sm1), smem_u32(sm1 + S1_ABUF) };
    uint32_t wB[2] = { smem_u32(sm1 + 2 * S1_ABUF),
                       smem_u32(sm1 + 2 * S1_ABUF + S1_WBUF) };

    s1_load_chunk(0, aB[0], wB[0], A, W, row0, tid);
    CP_COMMIT();

    const int wm = (wid & 1) * 32;                 // 2 M-warps cover 64 rows
    const int wn = (wid >> 1) * 32;                // 4 N-warps cover 128 cols
    const int lr  = lane & 7;
    const int seg = lane >> 3;
    const int l16 = lane & 15;

    float acc[2][4][4];
    #pragma unroll
    for (int mt = 0; mt < 2; mt++)
        #pragma unroll
        for (int nt = 0; nt < 4; nt++)
            #pragma unroll
            for (int j = 0; j < 4; j++) acc[mt][nt][j] = 0.f;

    for (int j = 0; j < 8; j++) {
        const int bf = j & 1;
        if (j < 7) {
            s1_load_chunk(j + 1, aB[(j+1)&1], wB[(j+1)&1], A, W, row0, tid);
            CP_COMMIT();
            CP_WAIT(1);
        } else {
            CP_WAIT(0);
        }
        __syncthreads();

        #pragma unroll
        for (int s = 0; s < 8; s++) {
            const int acol = s * 16 + ((seg >> 1) << 3);
            const int bcol = s * 16 + ((l16 >> 3) << 3);

            uint32_t a[2][4];
            #pragma unroll
            for (int mt = 0; mt < 2; mt++) {
                int arow = wm + mt * 16 + lr + ((seg & 1) << 3);
                uint32_t addr = aB[bf] + (uint32_t)(arow * S1_LD + acol) * 2;
                asm volatile("ldmatrix.sync.aligned.m8n8.x4.shared.b16 {%0,%1,%2,%3}, [%4];"
                             : "=r"(a[mt][0]), "=r"(a[mt][1]),
                               "=r"(a[mt][2]), "=r"(a[mt][3])
                             : "r"(addr));
            }
            uint32_t b[4][2];
            #pragma unroll
            for (int nt = 0; nt < 4; nt++) {
                int brow = wn + nt * 8 + (l16 & 7);
                uint32_t addr = wB[bf] + (uint32_t)(brow * S1_LD + bcol) * 2;
                asm volatile("ldmatrix.sync.aligned.m8n8.x2.shared.b16 {%0,%1}, [%2];"
                             : "=r"(b[nt][0]), "=r"(b[nt][1])
                             : "r"(addr));
            }
            #pragma unroll
            for (int mt = 0; mt < 2; mt++)
                #pragma unroll
                for (int nt = 0; nt < 4; nt++) {
                    asm volatile(
                        "mma.sync.aligned.m16n8k16.row.col.f32.f16.f16.f32 "
                        "{%0,%1,%2,%3}, {%4,%5,%6,%7}, {%8,%9}, {%0,%1,%2,%3};"
                        : "+f"(acc[mt][nt][0]), "+f"(acc[mt][nt][1]),
                          "+f"(acc[mt][nt][2]), "+f"(acc[mt][nt][3])
                        : "r"(a[mt][0]), "r"(a[mt][1]), "r"(a[mt][2]), "r"(a[mt][3]),
                          "r"(b[nt][0]), "r"(b[nt][1]));
                }
        }
        __syncthreads();
    }

    // ---- epilogue: scale by theta·wb, write fp16 pairs ----
    const int em = lane >> 2;
    const int en = (lane & 3) * 2;
    #pragma unroll
    for (int nt = 0; nt < 4; nt++) {
        const int n = wn + nt * 8 + en;
        float w0a = wb[n*T_+0],     w1a = wb[n*T_+1],     w2a = wb[n*T_+2];
        float w0b = wb[(n+1)*T_+0], w1b = wb[(n+1)*T_+1], w2b = wb[(n+1)*T_+2];
        #pragma unroll
        for (int mt = 0; mt < 2; mt++) {
            #pragma unroll
            for (int half = 0; half < 2; half++) {
                int m = wm + mt * 16 + em + half * 8;
                float th0 = sTheta[m][0], th1 = sTheta[m][1], th2 = sTheta[m][2];
                float sc0 = th0*w0a + th1*w1a + th2*w2a;
                float sc1 = th0*w0b + th1*w1b + th2*w2b;
                float v0 = acc[mt][nt][half*2 + 0] * sc0;
                float v1 = acc[mt][nt][half*2 + 1] * sc1;
                *reinterpret_cast<__half2*>(&outp[(size_t)(row0 + m) * F_ + n]) =
                    __floats2half2_rn(v0, v1);
            }
        }
    }
}

// =====================================================================
// Stage 2: fp16 mma GEMM, single term, K=128. A-resident, W-streamed.
// Each CTA: 128-row block, NCT=4 col tiles; W double-buffered cp.async.
// grid = (8, 32, 2), 256 thr (8 warps 2x4), warp tile 64x32.
// Output gates stored fp16 (halves traffic; fits L2 for stage3).
// smem: A[128x136] + 2x W[128x136] fp16 = 104448 bytes.
// =====================================================================
#define S2_LD   136
#define S2_TILE (128 * S2_LD)
#define S2_TOT  (3 * S2_TILE * 2)      // 104448
#define NCT     4

__device__ __forceinline__ void s2_load_w(
    const __half* __restrict__ W, int col0, uint32_t base, int tid)
{
    #pragma unroll
    for (int it = 0; it < 8; it++) {
        int idx = tid + it * 256;
        int r = idx >> 4, c = idx & 15;
        cp16(base + (uint32_t)(r * S2_LD + c * 8) * 2,
             W + (size_t)(col0 + r) * F_ + c * 8);
    }
}

__global__ __launch_bounds__(256, 2) void stage2_mma_kernel()
{
    extern __shared__ __half sm2[];

    const int tid  = threadIdx.x;
    const int lane = tid & 31;
    const int wid  = tid >> 5;
    const int path = blockIdx.z;
    const int row0 = blockIdx.y * 128;
    const int ct0  = blockIdx.x * NCT;          // first col tile

    const __half* __restrict__ A = g_a2h[path];
    const __half* __restrict__ W = g_w2h[path];
    __half* __restrict__ O = g_gates[path];

    const uint32_t as_base = smem_u32(sm2);
    uint32_t wBuf[2] = { smem_u32(sm2 + S2_TILE), smem_u32(sm2 + 2 * S2_TILE) };

    // A tile (stays resident): 128 rows x 16 chunks
    #pragma unroll
    for (int it = 0; it < 8; it++) {
        int idx = tid + it * 256;
        int r = idx >> 4, c = idx & 15;
        cp16(as_base + (uint32_t)(r * S2_LD + c * 8) * 2,
             A + (size_t)(row0 + r) * F_ + c * 8);
    }
    s2_load_w(W, ct0 * 128, wBuf[0], tid);
    CP_COMMIT();                                 // group: A + W0

    const int wm = (wid & 1) * 64;               // 2 M-warps cover 128 rows
    const int wn = (wid >> 1) * 32;              // 4 N-warps cover 128 cols
    const int lr  = lane & 7;
    const int seg = lane >> 3;
    const int l16 = lane & 15;
    const int em = lane >> 2;
    const int en = (lane & 3) * 2;

    for (int it = 0; it < NCT; it++) {
        const int buf = it & 1;
        if (it + 1 < NCT) {
            s2_load_w(W, (ct0 + it + 1) * 128, wBuf[(it + 1) & 1], tid);
            CP_COMMIT();
            CP_WAIT(1);
        } else {
            CP_WAIT(0);
        }
        __syncthreads();

        float acc[4][4][4];
        #pragma unroll
        for (int mt = 0; mt < 4; mt++)
            #pragma unroll
            for (int nt = 0; nt < 4; nt++)
                #pragma unroll
                for (int j = 0; j < 4; j++) acc[mt][nt][j] = 0.f;

        const uint32_t bs_base = wBuf[buf];
        #pragma unroll
        for (int s = 0; s < 8; s++) {
            const int acol = s * 16 + ((seg >> 1) << 3);
            const int bcol = s * 16 + ((l16 >> 3) << 3);

            uint32_t a[4][4];
            #pragma unroll
            for (int mt = 0; mt < 4; mt++) {
                int arow = wm + mt * 16 + lr + ((seg & 1) << 3);
                uint32_t addr = as_base + (uint32_t)(arow * S2_LD + acol) * 2;
                asm volatile("ldmatrix.sync.aligned.m8n8.x4.shared.b16 {%0,%1,%2,%3}, [%4];"
                             : "=r"(a[mt][0]), "=r"(a[mt][1]),
                               "=r"(a[mt][2]), "=r"(a[mt][3])
                             : "r"(addr));
            }
            uint32_t b[4][2];
            #pragma unroll
            for (int nt = 0; nt < 4; nt++) {
                int brow = wn + nt * 8 + (l16 & 7);
                uint32_t addr = bs_base + (uint32_t)(brow * S2_LD + bcol) * 2;
                asm volatile("ldmatrix.sync.aligned.m8n8.x2.shared.b16 {%0,%1}, [%2];"
                             : "=r"(b[nt][0]), "=r"(b[nt][1])
                             : "r"(addr));
            }
            #pragma unroll
            for (int mt = 0; mt < 4; mt++)
                #pragma unroll
                for (int nt = 0; nt < 4; nt++) {
                    asm volatile(
                        "mma.sync.aligned.m16n8k16.row.col.f32.f16.f16.f32 "
                        "{%0,%1,%2,%3}, {%4,%5,%6,%7}, {%8,%9}, {%0,%1,%2,%3};"
                        : "+f"(acc[mt][nt][0]), "+f"(acc[mt][nt][1]),
                          "+f"(acc[mt][nt][2]), "+f"(acc[mt][nt][3])
                        : "r"(a[mt][0]), "r"(a[mt][1]), "r"(a[mt][2]), "r"(a[mt][3]),
                          "r"(b[nt][0]), "r"(b[nt][1]));
                }
        }

        // ---- epilogue for this col tile (fp16 stores) ----
        const int col0 = (ct0 + it) * 128;
        #pragma unroll
        for (int mt = 0; mt < 4; mt++) {
            #pragma unroll
            for (int nt = 0; nt < 4; nt++) {
                int m = row0 + wm + mt * 16 + em;
                int n = col0 + wn + nt * 8 + en;
                *reinterpret_cast<__half2*>(&O[(size_t)m * G_ + n]) =
                    __floats2half2_rn(acc[mt][nt][0], acc[mt][nt][1]);
                *reinterpret_cast<__half2*>(&O[(size_t)(m + 8) * G_ + n]) =
                    __floats2half2_rn(acc[mt][nt][2], acc[mt][nt][3]);
            }
        }
        __syncthreads();
    }
}

// =====================================================================
// Stage 3: per-row LN(igates)+LN(hgates), gates, cell update, LN(cell).
// Reads fp16 gates via uint4. One CTA (256 thr) per batch row.
// =====================================================================
__device__ __forceinline__ float sigm(float x) { return 1.f / (1.f + expf(-x)); }

__device__ __forceinline__ float2 block_reduce2(float s, float q, float* red)
{
    __syncthreads();
    #pragma unroll
    for (int o = 16; o > 0; o >>= 1) {
        s += __shfl_xor_sync(0xffffffffu, s, o);
        q += __shfl_xor_sync(0xffffffffu, q, o);
    }
    int w = threadIdx.x >> 5, l = threadIdx.x & 31;
    if (l == 0) { red[w] = s; red[8 + w] = q; }
    __syncthreads();
    if (w == 0) {
        s = (l < 8) ? red[l] : 0.f;
        q = (l < 8) ? red[8 + l] : 0.f;
        #pragma unroll
        for (int o = 4; o > 0; o >>= 1) {
            s += __shfl_xor_sync(0xffffffffu, s, o);
            q += __shfl_xor_sync(0xffffffffu, q, o);
        }
        if (l == 0) { red[0] = s; red[1] = q; }
    }
    __syncthreads();
    return make_float2(red[0], red[1]);
}

__device__ __forceinline__ void unpack8(const uint4& u, float4& lo, float4& hi)
{
    float2 f0 = __half22float2(*reinterpret_cast<const __half2*>(&u.x));
    float2 f1 = __half22float2(*reinterpret_cast<const __half2*>(&u.y));
    float2 f2 = __half22float2(*reinterpret_cast<const __half2*>(&u.z));
    float2 f3 = __half22float2(*reinterpret_cast<const __half2*>(&u.w));
    lo = make_float4(f0.x, f0.y, f1.x, f1.y);
    hi = make_float4(f2.x, f2.y, f3.x, f3.y);
}

__global__ __launch_bounds__(256) void stage3_kernel(
    const float* __restrict__ cx,
    const float* __restrict__ lniw, const float* __restrict__ lnib,
    const float* __restrict__ lnhw, const float* __restrict__ lnhb,
    const float* __restrict__ lncw, const float* __restrict__ lncb,
    float* __restrict__ out)
{
    __shared__ float4 s_ig[1024];
    __shared__ float4 s_hg[1024];
    __shared__ float red[16];

    const int r   = blockIdx.x;
    const int tid = threadIdx.x;
    const uint4* __restrict__ igv =
        reinterpret_cast<const uint4*>(g_gates[0] + (size_t)r * G_);
    const uint4* __restrict__ hgv =
        reinterpret_cast<const uint4*>(g_gates[1] + (size_t)r * G_);

    float s = 0.f, q = 0.f;
    #pragma unroll
    for (int i = 0; i < 2; i++) {
        int n = tid + i * 256;          // uint4 index; covers 512 * 8 halves
        float4 lo, hi;
        unpack8(igv[n], lo, hi);
        s_ig[2*n]   = lo;
        s_ig[2*n+1] = hi;
        s += lo.x + lo.y + lo.z + lo.w + hi.x + hi.y + hi.z + hi.w;
        q += lo.x*lo.x + lo.y*lo.y + lo.z*lo.z + lo.w*lo.w
           + hi.x*hi.x + hi.y*hi.y + hi.z*hi.z + hi.w*hi.w;
    }
    float2 ri = block_reduce2(s, q, red);
    float mu_i = ri.x * (1.f / G_);
    float rstd_i = rsqrtf(ri.y * (1.f / G_) - mu_i * mu_i + LN_EPS);

    s = 0.f; q = 0.f;
    #pragma unroll
    for (int i = 0; i < 2; i++) {
        int n = tid + i * 256;
        float4 lo, hi;
        unpack8(hgv[n], lo, hi);
        s_hg[2*n]   = lo;
        s_hg[2*n+1] = hi;
        s += lo.x + lo.y + lo.z + lo.w + hi.x + hi.y + hi.z + hi.w;
        q += lo.x*lo.x + lo.y*lo.y + lo.z*lo.z + lo.w*lo.w
           + hi.x*hi.x + hi.y*hi.y + hi.z*hi.z + hi.w*hi.w;
    }
    float2 rh = block_reduce2(s, q, red);
    float mu_h = rh.x * (1.f / G_);
    float rstd_h = rsqrtf(rh.y * (1.f / G_) - mu_h * mu_h + LN_EPS);

    const float4* lniw4 = reinterpret_cast<const float4*>(lniw);
    const float4* lnib4 = reinterpret_cast<const float4*>(lnib);
    const float4* lnhw4 = reinterpret_cast<const float4*>(lnhw);
    const float4* lnhb4 = reinterpret_cast<const float4*>(lnhb);

    float4 gi_v[4], gh_v[4], wi_v[4], bi_v[4], wh_v[4], bh_v[4];
    #pragma unroll
    for (int g = 0; g < 4; g++) {
        int n = tid + g * 256;
        gi_v[g] = s_ig[n];  gh_v[g] = s_hg[n];
        wi_v[g] = lniw4[n]; bi_v[g] = lnib4[n];
        wh_v[g] = lnhw4[n]; bh_v[g] = lnhb4[n];
    }
    float4 cxv = reinterpret_cast<const float4*>(cx + (size_t)r * H_)[tid];

    float cc[4], oo[4];
    float cs = 0.f, cq = 0.f;
    #pragma unroll
    for (int c = 0; c < 4; c++) {
        #define GVAL(g) ((f4c(gi_v[g],c) - mu_i) * rstd_i * f4c(wi_v[g],c) + f4c(bi_v[g],c) + \
                         (f4c(gh_v[g],c) - mu_h) * rstd_h * f4c(wh_v[g],c) + f4c(bh_v[g],c))
        float gi = sigm(GVAL(0));
        float gf = sigm(GVAL(1));
        float gg = tanhf(GVAL(2));
        float go = sigm(GVAL(3));
        #undef GVAL
        float c_ = gf * f4c(cxv, c) + gi * gg;
        cc[c] = c_; oo[c] = go;
        cs += c_; cq += c_ * c_;
    }
    float2 rc = block_reduce2(cs, cq, red);
    float mu_c = rc.x * (1.f / H_);
    float rstd_c = rsqrtf(rc.y * (1.f / H_) - mu_c * mu_c + LN_EPS);

    float4 wcv = reinterpret_cast<const float4*>(lncw)[tid];
    float4 bcv = reinterpret_cast<const float4*>(lncb)[tid];
    float4 hyv, cyv;
    #pragma unroll
    for (int c = 0; c < 4; c++) {
        float cy = (cc[c] - mu_c) * rstd_c * f4c(wcv, c) + f4c(bcv, c);
        reinterpret_cast<float*>(&cyv)[c] = cy;
        reinterpret_cast<float*>(&hyv)[c] = oo[c] * tanhf(cy);
    }
    float4* out4 = reinterpret_cast<float4*>(out);
    out4[(size_t)r * 256 + tid] = hyv;
    out4[(size_t)B_ * 256 + (size_t)r * 256 + tid] = cyv;
}

// =====================================================================
extern "C" void kernel_launch(void* const* d_in, const int* in_sizes, int n_in,
                              void* d_out, int out_size)
{
    const float* input_ = (const float*)d_in[0];
    const float* hx     = (const float*)d_in[1];
    const float* cx     = (const float*)d_in[2];
    const float* topic  = (const float*)d_in[3];
    const float* w_ih_a = (const float*)d_in[4];
    const float* w_ih_b = (const float*)d_in[5];
    const float* w_ih_c = (const float*)d_in[6];
    const float* w_hh_a = (const float*)d_in[7];
    const float* w_hh_b = (const float*)d_in[8];
    const float* w_hh_c = (const float*)d_in[9];
    const float* th_ih_w = (const float*)d_in[10];
    const float* th_ih_b = (const float*)d_in[11];
    const float* th_hh_w = (const float*)d_in[12];
    const float* th_hh_b = (const float*)d_in[13];
    const float* ln_i_w  = (const float*)d_in[14];
    const float* ln_i_b  = (const float*)d_in[15];
    const float* ln_h_w  = (const float*)d_in[16];
    const float* ln_h_b  = (const float*)d_in[17];
    const float* ln_c_w  = (const float*)d_in[18];
    const float* ln_c_b  = (const float*)d_in[19];

    cudaFuncSetAttribute(stage1_mma_kernel,
                         cudaFuncAttributeMaxDynamicSharedMemorySize, S1_TOT);
    cudaFuncSetAttribute(stage2_mma_kernel,
                         cudaFuncAttributeMaxDynamicSharedMemorySize, S2_TOT);

    convert_x_kernel<<<dim3(B_, 2), 256>>>(input_, hx);
    convert_wc_kernel<<<dim3(F_, 2), 256>>>(w_ih_c, w_hh_c);
    convert_wa_kernel<<<dim3(512, 2), 256>>>(w_ih_a, w_hh_a);

    stage1_mma_kernel<<<dim3(B_ / 64, 2), 256, S1_TOT>>>(
        topic, th_ih_w, th_ih_b, w_ih_b, th_hh_w, th_hh_b, w_hh_b);

    stage2_mma_kernel<<<dim3(G_ / 128 / NCT, B_ / 128, 2), 256, S2_TOT>>>();

    stage3_kernel<<<B_, 256>>>(cx, ln_i_w, ln_i_b, ln_h_w, ln_h_b,
                               ln_c_w, ln_c_b, (float*)d_out);
}

// round 11
// speedup vs baseline: 1.8475x; 1.0666x over previous
#include <cuda_runtime.h>
#include <cuda_bf16.h>
#include <cuda_fp16.h>
#include <math.h>
#include <stdint.h>

#define B_   4096
#define IN_  1024
#define H_   1024
#define F_   128
#define T_   3
#define G_   4096      // 4*H
#define LN_EPS 1e-5f

// ---------------- scratch (no allocations allowed) ----------------
__device__ __align__(16) __half g_xh[2][(size_t)B_ * IN_];   // x/hx fp16
__device__ __align__(16) __half g_wch[2][(size_t)F_ * IN_];  // wc fp16
__device__ __align__(16) __half g_a2h[2][(size_t)B_ * F_];   // stage1 out (fp16)
__device__ __align__(16) __half g_w2h[2][(size_t)G_ * F_];   // w_*_a  (fp16)
__device__ __align__(16) __half g_gates[2][(size_t)B_ * G_]; // ig / hg (fp16)

__device__ __forceinline__ uint32_t smem_u32(const void* p) {
    uint32_t a;
    asm("{ .reg .u64 t; cvta.to.shared.u64 t, %1; cvt.u32.u64 %0, t; }"
        : "=r"(a) : "l"(p));
    return a;
}
__device__ __forceinline__ void cp16(uint32_t dst, const void* src) {
    asm volatile("cp.async.cg.shared.global [%0], [%1], 16;"
                 :: "r"(dst), "l"(src));
}
#define CP_COMMIT()  asm volatile("cp.async.commit_group;")
#define CP_WAIT(n)   asm volatile("cp.async.wait_group %0;" :: "n"(n))

__device__ __forceinline__ float f4c(const float4& v, int c) {
    return reinterpret_cast<const float*>(&v)[c];
}
__device__ __forceinline__ float fexp2(float x) {
    float y; asm("ex2.approx.f32 %0, %1;" : "=f"(y) : "f"(x)); return y;
}
__device__ __forceinline__ float frcp(float x) {
    float y; asm("rcp.approx.f32 %0, %1;" : "=f"(y) : "f"(x)); return y;
}
// sigmoid / tanh on the MUFU ex2+rcp path (rel err ~1e-7)
__device__ __forceinline__ float sigm(float x) {
    return frcp(1.f + fexp2(-1.4426950408889634f * x));
}
__device__ __forceinline__ float tanh_fast(float x) {
    return 2.f * frcp(1.f + fexp2(-2.8853900817779268f * x)) - 1.f;
}

// =====================================================================
// convert_xwc: rows of 1024 fp32 -> fp16.  grid (B_+F_, 2) x 256
// row < B_ : x/hx -> g_xh ; else wc -> g_wch
// =====================================================================
__global__ __launch_bounds__(256) void convert_xwc_kernel(
    const float* __restrict__ xi, const float* __restrict__ xh,
    const float* __restrict__ wi, const float* __restrict__ wh)
{
    const int path = blockIdx.y, tid = threadIdx.x;
    int row = blockIdx.x;
    const float* src;
    __half* dst;
    if (row < B_) {
        src = (path ? xh : xi) + (size_t)row * IN_;
        dst = g_xh[path] + (size_t)row * IN_;
    } else {
        row -= B_;
        src = (path ? wh : wi) + (size_t)row * IN_;
        dst = g_wch[path] + (size_t)row * IN_;
    }
    float4 v = reinterpret_cast<const float4*>(src)[tid];
    __half2* d = reinterpret_cast<__half2*>(dst);
    d[tid*2]   = __floats2half2_rn(v.x, v.y);
    d[tid*2+1] = __floats2half2_rn(v.z, v.w);
}

// =====================================================================
// convert_wa: w_*_a fp32 [4096,128] -> fp16 [4096,128]. grid (512,2)x256
// =====================================================================
__global__ __launch_bounds__(256) void convert_wa_kernel(
    const float* __restrict__ wi, const float* __restrict__ wh)
{
    const int path = blockIdx.y;
    const int idx  = blockIdx.x * 256 + threadIdx.x;   // float4 index
    const float* w = path ? wh : wi;
    float4 v = reinterpret_cast<const float4*>(w)[idx];
    __half2* d = reinterpret_cast<__half2*>(g_w2h[path]);
    d[idx * 2]     = __floats2half2_rn(v.x, v.y);
    d[idx * 2 + 1] = __floats2half2_rn(v.z, v.w);
}

// =====================================================================
// Stage 1 (mma, fp16 single term): C[b,f] = (x @ wc^T)[b,f] * scale(b,f).
// Tile M=64 x N=128, K=1024 in chunks of 128 (x8), cp.async double buffer.
// grid (B_/64, 2) = 128 CTAs, 256 thr (8 warps: 2(M) x 4(N)).
// =====================================================================
#define S1_LD   136
#define S1_ABUF (64 * S1_LD)
#define S1_WBUF (128 * S1_LD)
#define S1_TOT  ((2 * S1_ABUF + 2 * S1_WBUF) * 2)   // 104448

__device__ __forceinline__ void s1_load_chunk(
    int j, uint32_t aBase, uint32_t wBase,
    const __half* __restrict__ A, const __half* __restrict__ W,
    int row0, int tid)
{
    #pragma unroll
    for (int it = 0; it < 4; it++) {               // A: 64 rows x 16 chunks
        int idx = tid + it * 256;
        int r = idx >> 4, c = idx & 15;
        cp16(aBase + (uint32_t)(r * S1_LD + c * 8) * 2,
             A + (size_t)(row0 + r) * IN_ + j * 128 + c * 8);
    }
    #pragma unroll
    for (int it = 0; it < 8; it++) {               // W: 128 rows x 16 chunks
        int idx = tid + it * 256;
        int r = idx >> 4, c = idx & 15;
        cp16(wBase + (uint32_t)(r * S1_LD + c * 8) * 2,
             W + (size_t)r * IN_ + j * 128 + c * 8);
    }
}

__global__ __launch_bounds__(256) void stage1_mma_kernel(
    const float* __restrict__ topic,
    const float* __restrict__ thw_i, const float* __restrict__ thb_i,
    const float* __restrict__ wb_i,
    const float* __restrict__ thw_h, const float* __restrict__ thb_h,
    const float* __restrict__ wb_h)
{
    extern __shared__ __half sm1[];
    __shared__ float sTheta[64][4];

    const int tid  = threadIdx.x;
    const int lane = tid & 31;
    const int wid  = tid >> 5;
    const int path = blockIdx.y;
    const int row0 = blockIdx.x * 64;

    const __half* __restrict__ A = g_xh[path];
    const __half* __restrict__ W = g_wch[path];
    const float* __restrict__ thw = path ? thw_h : thw_i;
    const float* __restrict__ thb = path ? thb_h : thb_i;
    const float* __restrict__ wb  = path ? wb_h  : wb_i;
    __half* __restrict__ outp = g_a2h[path];

    if (tid < 192) {
        int r = tid / 3, t = tid - r * 3;
        const float* tp = topic + (size_t)(row0 + r) * T_;
        sTheta[r][t] = thb[t] + tp[0]*thw[t*T_+0] + tp[1]*thw[t*T_+1] + tp[2]*thw[t*T_+2];
    }

    uint32_t aB[2] = { smem_u32(sm1), smem_u32(sm1 + S1_ABUF) };
    uint32_t wB[2] = { smem_u32(sm1 + 2 * S1_ABUF),
                       smem_u32(sm1 + 2 * S1_ABUF + S1_WBUF) };

    s1_load_chunk(0, aB[0], wB[0], A, W, row0, tid);
    CP_COMMIT();

    const int wm = (wid & 1) * 32;                 // 2 M-warps cover 64 rows
    const int wn = (wid >> 1) * 32;                // 4 N-warps cover 128 cols
    const int lr  = lane & 7;
    const int seg = lane >> 3;
    const int l16 = lane & 15;

    float acc[2][4][4];
    #pragma unroll
    for (int mt = 0; mt < 2; mt++)
        #pragma unroll
        for (int nt = 0; nt < 4; nt++)
            #pragma unroll
            for (int j = 0; j < 4; j++) acc[mt][nt][j] = 0.f;

    for (int j = 0; j < 8; j++) {
        const int bf = j & 1;
        if (j < 7) {
            s1_load_chunk(j + 1, aB[(j+1)&1], wB[(j+1)&1], A, W, row0, tid);
            CP_COMMIT();
            CP_WAIT(1);
        } else {
            CP_WAIT(0);
        }
        __syncthreads();

        #pragma unroll
        for (int s = 0; s < 8; s++) {
            const int acol = s * 16 + ((seg >> 1) << 3);
            const int bcol = s * 16 + ((l16 >> 3) << 3);

            uint32_t a[2][4];
            #pragma unroll
            for (int mt = 0; mt < 2; mt++) {
                int arow = wm + mt * 16 + lr + ((seg & 1) << 3);
                uint32_t addr = aB[bf] + (uint32_t)(arow * S1_LD + acol) * 2;
                asm volatile("ldmatrix.sync.aligned.m8n8.x4.shared.b16 {%0,%1,%2,%3}, [%4];"
                             : "=r"(a[mt][0]), "=r"(a[mt][1]),
                               "=r"(a[mt][2]), "=r"(a[mt][3])
                             : "r"(addr));
            }
            uint32_t b[4][2];
            #pragma unroll
            for (int nt = 0; nt < 4; nt++) {
                int brow = wn + nt * 8 + (l16 & 7);
                uint32_t addr = wB[bf] + (uint32_t)(brow * S1_LD + bcol) * 2;
                asm volatile("ldmatrix.sync.aligned.m8n8.x2.shared.b16 {%0,%1}, [%2];"
                             : "=r"(b[nt][0]), "=r"(b[nt][1])
                             : "r"(addr));
            }
            #pragma unroll
            for (int mt = 0; mt < 2; mt++)
                #pragma unroll
                for (int nt = 0; nt < 4; nt++) {
                    asm volatile(
                        "mma.sync.aligned.m16n8k16.row.col.f32.f16.f16.f32 "
                        "{%0,%1,%2,%3}, {%4,%5,%6,%7}, {%8,%9}, {%0,%1,%2,%3};"
                        : "+f"(acc[mt][nt][0]), "+f"(acc[mt][nt][1]),
                          "+f"(acc[mt][nt][2]), "+f"(acc[mt][nt][3])
                        : "r"(a[mt][0]), "r"(a[mt][1]), "r"(a[mt][2]), "r"(a[mt][3]),
                          "r"(b[nt][0]), "r"(b[nt][1]));
                }
        }
        __syncthreads();
    }

    // ---- epilogue: scale by theta·wb, write fp16 pairs ----
    const int em = lane >> 2;
    const int en = (lane & 3) * 2;
    #pragma unroll
    for (int nt = 0; nt < 4; nt++) {
        const int n = wn + nt * 8 + en;
        float w0a = wb[n*T_+0],     w1a = wb[n*T_+1],     w2a = wb[n*T_+2];
        float w0b = wb[(n+1)*T_+0], w1b = wb[(n+1)*T_+1], w2b = wb[(n+1)*T_+2];
        #pragma unroll
        for (int mt = 0; mt < 2; mt++) {
            #pragma unroll
            for (int half = 0; half < 2; half++) {
                int m = wm + mt * 16 + em + half * 8;
                float th0 = sTheta[m][0], th1 = sTheta[m][1], th2 = sTheta[m][2];
                float sc0 = th0*w0a + th1*w1a + th2*w2a;
                float sc1 = th0*w0b + th1*w1b + th2*w2b;
                float v0 = acc[mt][nt][half*2 + 0] * sc0;
                float v1 = acc[mt][nt][half*2 + 1] * sc1;
                *reinterpret_cast<__half2*>(&outp[(size_t)(row0 + m) * F_ + n]) =
                    __floats2half2_rn(v0, v1);
            }
        }
    }
}

// =====================================================================
// Stage 2: fp16 mma GEMM, single term, K=128. A-resident, W-streamed.
// Each CTA: 128-row block, NCT=8 col tiles; W double-buffered cp.async.
// grid = (4, 32, 2) = 256 CTAs, 256 thr (8 warps 2x4), warp tile 64x32.
// Output gates stored fp16. smem 104448 B (2 CTAs/SM).
// =====================================================================
#define S2_LD   136
#define S2_TILE (128 * S2_LD)
#define S2_TOT  (3 * S2_TILE * 2)      // 104448
#define NCT     8

__device__ __forceinline__ void s2_load_w(
    const __half* __restrict__ W, int col0, uint32_t base, int tid)
{
    #pragma unroll
    for (int it = 0; it < 8; it++) {
        int idx = tid + it * 256;
        int r = idx >> 4, c = idx & 15;
        cp16(base + (uint32_t)(r * S2_LD + c * 8) * 2,
             W + (size_t)(col0 + r) * F_ + c * 8);
    }
}

__global__ __launch_bounds__(256, 2) void stage2_mma_kernel()
{
    extern __shared__ __half sm2[];

    const int tid  = threadIdx.x;
    const int lane = tid & 31;
    const int wid  = tid >> 5;
    const int path = blockIdx.z;
    const int row0 = blockIdx.y * 128;
    const int ct0  = blockIdx.x * NCT;          // first col tile

    const __half* __restrict__ A = g_a2h[path];
    const __half* __restrict__ W = g_w2h[path];
    __half* __restrict__ O = g_gates[path];

    const uint32_t as_base = smem_u32(sm2);
    uint32_t wBuf[2] = { smem_u32(sm2 + S2_TILE), smem_u32(sm2 + 2 * S2_TILE) };

    // A tile (stays resident): 128 rows x 16 chunks
    #pragma unroll
    for (int it = 0; it < 8; it++) {
        int idx = tid + it * 256;
        int r = idx >> 4, c = idx & 15;
        cp16(as_base + (uint32_t)(r * S2_LD + c * 8) * 2,
             A + (size_t)(row0 + r) * F_ + c * 8);
    }
    s2_load_w(W, ct0 * 128, wBuf[0], tid);
    CP_COMMIT();                                 // group: A + W0

    const int wm = (wid & 1) * 64;               // 2 M-warps cover 128 rows
    const int wn = (wid >> 1) * 32;              // 4 N-warps cover 128 cols
    const int lr  = lane & 7;
    const int seg = lane >> 3;
    const int l16 = lane & 15;
    const int em = lane >> 2;
    const int en = (lane & 3) * 2;

    for (int it = 0; it < NCT; it++) {
        const int buf = it & 1;
        if (it + 1 < NCT) {
            s2_load_w(W, (ct0 + it + 1) * 128, wBuf[(it + 1) & 1], tid);
            CP_COMMIT();
            CP_WAIT(1);
        } else {
            CP_WAIT(0);
        }
        __syncthreads();

        float acc[4][4][4];
        #pragma unroll
        for (int mt = 0; mt < 4; mt++)
            #pragma unroll
            for (int nt = 0; nt < 4; nt++)
                #pragma unroll
                for (int j = 0; j < 4; j++) acc[mt][nt][j] = 0.f;

        const uint32_t bs_base = wBuf[buf];
        #pragma unroll
        for (int s = 0; s < 8; s++) {
            const int acol = s * 16 + ((seg >> 1) << 3);
            const int bcol = s * 16 + ((l16 >> 3) << 3);

            uint32_t a[4][4];
            #pragma unroll
            for (int mt = 0; mt < 4; mt++) {
                int arow = wm + mt * 16 + lr + ((seg & 1) << 3);
                uint32_t addr = as_base + (uint32_t)(arow * S2_LD + acol) * 2;
                asm volatile("ldmatrix.sync.aligned.m8n8.x4.shared.b16 {%0,%1,%2,%3}, [%4];"
                             : "=r"(a[mt][0]), "=r"(a[mt][1]),
                               "=r"(a[mt][2]), "=r"(a[mt][3])
                             : "r"(addr));
            }
            uint32_t b[4][2];
            #pragma unroll
            for (int nt = 0; nt < 4; nt++) {
                int brow = wn + nt * 8 + (l16 & 7);
                uint32_t addr = bs_base + (uint32_t)(brow * S2_LD + bcol) * 2;
                asm volatile("ldmatrix.sync.aligned.m8n8.x2.shared.b16 {%0,%1}, [%2];"
                             : "=r"(b[nt][0]), "=r"(b[nt][1])
                             : "r"(addr));
            }
            #pragma unroll
            for (int mt = 0; mt < 4; mt++)
                #pragma unroll
                for (int nt = 0; nt < 4; nt++) {
                    asm volatile(
                        "mma.sync.aligned.m16n8k16.row.col.f32.f16.f16.f32 "
                        "{%0,%1,%2,%3}, {%4,%5,%6,%7}, {%8,%9}, {%0,%1,%2,%3};"
                        : "+f"(acc[mt][nt][0]), "+f"(acc[mt][nt][1]),
                          "+f"(acc[mt][nt][2]), "+f"(acc[mt][nt][3])
                        : "r"(a[mt][0]), "r"(a[mt][1]), "r"(a[mt][2]), "r"(a[mt][3]),
                          "r"(b[nt][0]), "r"(b[nt][1]));
                }
        }

        // ---- epilogue for this col tile (fp16 stores) ----
        const int col0 = (ct0 + it) * 128;
        #pragma unroll
        for (int mt = 0; mt < 4; mt++) {
            #pragma unroll
            for (int nt = 0; nt < 4; nt++) {
                int m = row0 + wm + mt * 16 + em;
                int n = col0 + wn + nt * 8 + en;
                *reinterpret_cast<__half2*>(&O[(size_t)m * G_ + n]) =
                    __floats2half2_rn(acc[mt][nt][0], acc[mt][nt][1]);
                *reinterpret_cast<__half2*>(&O[(size_t)(m + 8) * G_ + n]) =
                    __floats2half2_rn(acc[mt][nt][2], acc[mt][nt][3]);
            }
        }
        __syncthreads();
    }
}

// =====================================================================
// Stage 3: per-row LN(igates)+LN(hgates), gates, cell update, LN(cell).
// fp16 gate reads; MUFU-path sigmoid/tanh. One CTA (256 thr) per row.
// =====================================================================
__device__ __forceinline__ float2 block_reduce2(float s, float q, float* red)
{
    __syncthreads();
    #pragma unroll
    for (int o = 16; o > 0; o >>= 1) {
        s += __shfl_xor_sync(0xffffffffu, s, o);
        q += __shfl_xor_sync(0xffffffffu, q, o);
    }
    int w = threadIdx.x >> 5, l = threadIdx.x & 31;
    if (l == 0) { red[w] = s; red[8 + w] = q; }
    __syncthreads();
    if (w == 0) {
        s = (l < 8) ? red[l] : 0.f;
        q = (l < 8) ? red[8 + l] : 0.f;
        #pragma unroll
        for (int o = 4; o > 0; o >>= 1) {
            s += __shfl_xor_sync(0xffffffffu, s, o);
            q += __shfl_xor_sync(0xffffffffu, q, o);
        }
        if (l == 0) { red[0] = s; red[1] = q; }
    }
    __syncthreads();
    return make_float2(red[0], red[1]);
}

__device__ __forceinline__ void unpack8(const uint4& u, float4& lo, float4& hi)
{
    float2 f0 = __half22float2(*reinterpret_cast<const __half2*>(&u.x));
    float2 f1 = __half22float2(*reinterpret_cast<const __half2*>(&u.y));
    float2 f2 = __half22float2(*reinterpret_cast<const __half2*>(&u.z));
    float2 f3 = __half22float2(*reinterpret_cast<const __half2*>(&u.w));
    lo = make_float4(f0.x, f0.y, f1.x, f1.y);
    hi = make_float4(f2.x, f2.y, f3.x, f3.y);
}

__global__ __launch_bounds__(256) void stage3_kernel(
    const float* __restrict__ cx,
    const float* __restrict__ lniw, const float* __restrict__ lnib,
    const float* __restrict__ lnhw, const float* __restrict__ lnhb,
    const float* __restrict__ lncw, const float* __restrict__ lncb,
    float* __restrict__ out)
{
    __shared__ float4 s_ig[1024];
    __shared__ float4 s_hg[1024];
    __shared__ float red[16];

    const int r   = blockIdx.x;
    const int tid = threadIdx.x;
    const uint4* __restrict__ igv =
        reinterpret_cast<const uint4*>(g_gates[0] + (size_t)r * G_);
    const uint4* __restrict__ hgv =
        reinterpret_cast<const uint4*>(g_gates[1] + (size_t)r * G_);

    float s = 0.f, q = 0.f;
    #pragma unroll
    for (int i = 0; i < 2; i++) {
        int n = tid + i * 256;
        float4 lo, hi;
        unpack8(igv[n], lo, hi);
        s_ig[2*n]   = lo;
        s_ig[2*n+1] = hi;
        s += lo.x + lo.y + lo.z + lo.w + hi.x + hi.y + hi.z + hi.w;
        q += lo.x*lo.x + lo.y*lo.y + lo.z*lo.z + lo.w*lo.w
           + hi.x*hi.x + hi.y*hi.y + hi.z*hi.z + hi.w*hi.w;
    }
    float2 ri = block_reduce2(s, q, red);
    float mu_i = ri.x * (1.f / G_);
    float rstd_i = rsqrtf(ri.y * (1.f / G_) - mu_i * mu_i + LN_EPS);

    s = 0.f; q = 0.f;
    #pragma unroll
    for (int i = 0; i < 2; i++) {
        int n = tid + i * 256;
        float4 lo, hi;
        unpack8(hgv[n], lo, hi);
        s_hg[2*n]   = lo;
        s_hg[2*n+1] = hi;
        s += lo.x + lo.y + lo.z + lo.w + hi.x + hi.y + hi.z + hi.w;
        q += lo.x*lo.x + lo.y*lo.y + lo.z*lo.z + lo.w*lo.w
           + hi.x*hi.x + hi.y*hi.y + hi.z*hi.z + hi.w*hi.w;
    }
    float2 rh = block_reduce2(s, q, red);
    float mu_h = rh.x * (1.f / G_);
    float rstd_h = rsqrtf(rh.y * (1.f / G_) - mu_h * mu_h + LN_EPS);

    const float4* lniw4 = reinterpret_cast<const float4*>(lniw);
    const float4* lnib4 = reinterpret_cast<const float4*>(lnib);
    const float4* lnhw4 = reinterpret_cast<const float4*>(lnhw);
    const float4* lnhb4 = reinterpret_cast<const float4*>(lnhb);

    float4 gi_v[4], gh_v[4], wi_v[4], bi_v[4], wh_v[4], bh_v[4];
    #pragma unroll
    for (int g = 0; g < 4; g++) {
        int n = tid + g * 256;
        gi_v[g] = s_ig[n];  gh_v[g] = s_hg[n];
        wi_v[g] = lniw4[n]; bi_v[g] = lnib4[n];
        wh_v[g] = lnhw4[n]; bh_v[g] = lnhb4[n];
    }
    float4 cxv = reinterpret_cast<const float4*>(cx + (size_t)r * H_)[tid];

    float cc[4], oo[4];
    float cs = 0.f, cq = 0.f;
    #pragma unroll
    for (int c = 0; c < 4; c++) {
        #define GVAL(g) ((f4c(gi_v[g],c) - mu_i) * rstd_i * f4c(wi_v[g],c) + f4c(bi_v[g],c) + \
                         (f4c(gh_v[g],c) - mu_h) * rstd_h * f4c(wh_v[g],c) + f4c(bh_v[g],c))
        float gi = sigm(GVAL(0));
        float gf = sigm(GVAL(1));
        float gg = tanh_fast(GVAL(2));
        float go = sigm(GVAL(3));
        #undef GVAL
        float c_ = gf * f4c(cxv, c) + gi * gg;
        cc[c] = c_; oo[c] = go;
        cs += c_; cq += c_ * c_;
    }
    float2 rc = block_reduce2(cs, cq, red);
    float mu_c = rc.x * (1.f / H_);
    float rstd_c = rsqrtf(rc.y * (1.f / H_) - mu_c * mu_c + LN_EPS);

    float4 wcv = reinterpret_cast<const float4*>(lncw)[tid];
    float4 bcv = reinterpret_cast<const float4*>(lncb)[tid];
    float4 hyv, cyv;
    #pragma unroll
    for (int c = 0; c < 4; c++) {
        float cy = (cc[c] - mu_c) * rstd_c * f4c(wcv, c) + f4c(bcv, c);
        reinterpret_cast<float*>(&cyv)[c] = cy;
        reinterpret_cast<float*>(&hyv)[c] = oo[c] * tanh_fast(cy);
    }
    float4* out4 = reinterpret_cast<float4*>(out);
    out4[(size_t)r * 256 + tid] = hyv;
    out4[(size_t)B_ * 256 + (size_t)r * 256 + tid] = cyv;
}

// =====================================================================
extern "C" void kernel_launch(void* const* d_in, const int* in_sizes, int n_in,
                              void* d_out, int out_size)
{
    const float* input_ = (const float*)d_in[0];
    const float* hx     = (const float*)d_in[1];
    const float* cx     = (const float*)d_in[2];
    const float* topic  = (const float*)d_in[3];
    const float* w_ih_a = (const float*)d_in[4];
    const float* w_ih_b = (const float*)d_in[5];
    const float* w_ih_c = (const float*)d_in[6];
    const float* w_hh_a = (const float*)d_in[7];
    const float* w_hh_b = (const float*)d_in[8];
    const float* w_hh_c = (const float*)d_in[9];
    const float* th_ih_w = (const float*)d_in[10];
    const float* th_ih_b = (const float*)d_in[11];
    const float* th_hh_w = (const float*)d_in[12];
    const float* th_hh_b = (const float*)d_in[13];
    const float* ln_i_w  = (const float*)d_in[14];
    const float* ln_i_b  = (const float*)d_in[15];
    const float* ln_h_w  = (const float*)d_in[16];
    const float* ln_h_b  = (const float*)d_in[17];
    const float* ln_c_w  = (const float*)d_in[18];
    const float* ln_c_b  = (const float*)d_in[19];

    cudaFuncSetAttribute(stage1_mma_kernel,
                         cudaFuncAttributeMaxDynamicSharedMemorySize, S1_TOT);
    cudaFuncSetAttribute(stage2_mma_kernel,
                         cudaFuncAttributeMaxDynamicSharedMemorySize, S2_TOT);

    convert_xwc_kernel<<<dim3(B_ + F_, 2), 256>>>(input_, hx, w_ih_c, w_hh_c);
    convert_wa_kernel<<<dim3(512, 2), 256>>>(w_ih_a, w_hh_a);

    stage1_mma_kernel<<<dim3(B_ / 64, 2), 256, S1_TOT>>>(
        topic, th_ih_w, th_ih_b, w_ih_b, th_hh_w, th_hh_b, w_hh_b);

    stage2_mma_kernel<<<dim3(G_ / 128 / NCT, B_ / 128, 2), 256, S2_TOT>>>();

    stage3_kernel<<<B_, 256>>>(cx, ln_i_w, ln_i_b, ln_h_w, ln_h_b,
                               ln_c_w, ln_c_b, (float*)d_out);
}

// round 12
// speedup vs baseline: 1.8568x; 1.0050x over previous
#include <cuda_runtime.h>
#include <cuda_bf16.h>
#include <cuda_fp16.h>
#include <math.h>
#include <stdint.h>

#define B_   4096
#define IN_  1024
#define H_   1024
#define F_   128
#define T_   3
#define G_   4096      // 4*H
#define LN_EPS 1e-5f

// ---------------- scratch (no allocations allowed) ----------------
__device__ __align__(16) __half g_xh[2][(size_t)B_ * IN_];   // x/hx fp16
__device__ __align__(16) __half g_wch[2][(size_t)F_ * IN_];  // wc fp16
__device__ __align__(16) __half g_a2h[2][(size_t)B_ * F_];   // stage1 out (fp16)
__device__ __align__(16) __half g_w2h[2][(size_t)G_ * F_];   // w_*_a  (fp16)
__device__ __align__(16) __half g_gates[2][(size_t)B_ * G_]; // ig / hg (fp16)

__device__ __forceinline__ uint32_t smem_u32(const void* p) {
    uint32_t a;
    asm("{ .reg .u64 t; cvta.to.shared.u64 t, %1; cvt.u32.u64 %0, t; }"
        : "=r"(a) : "l"(p));
    return a;
}
__device__ __forceinline__ void cp16(uint32_t dst, const void* src) {
    asm volatile("cp.async.cg.shared.global [%0], [%1], 16;"
                 :: "r"(dst), "l"(src));
}
#define CP_COMMIT()  asm volatile("cp.async.commit_group;")
#define CP_WAIT(n)   asm volatile("cp.async.wait_group %0;" :: "n"(n))

__device__ __forceinline__ float f4c(const float4& v, int c) {
    return reinterpret_cast<const float*>(&v)[c];
}
__device__ __forceinline__ float fexp2(float x) {
    float y; asm("ex2.approx.f32 %0, %1;" : "=f"(y) : "f"(x)); return y;
}
__device__ __forceinline__ float frcp(float x) {
    float y; asm("rcp.approx.f32 %0, %1;" : "=f"(y) : "f"(x)); return y;
}
__device__ __forceinline__ float sigm(float x) {
    return frcp(1.f + fexp2(-1.4426950408889634f * x));
}
__device__ __forceinline__ float tanh_fast(float x) {
    return 2.f * frcp(1.f + fexp2(-2.8853900817779268f * x)) - 1.f;
}

// =====================================================================
// convert_xwc: rows of 1024 fp32 -> fp16.  grid (B_+F_, 2) x 256
// =====================================================================
__global__ __launch_bounds__(256) void convert_xwc_kernel(
    const float* __restrict__ xi, const float* __restrict__ xh,
    const float* __restrict__ wi, const float* __restrict__ wh)
{
    const int path = blockIdx.y, tid = threadIdx.x;
    int row = blockIdx.x;
    const float* src;
    __half* dst;
    if (row < B_) {
        src = (path ? xh : xi) + (size_t)row * IN_;
        dst = g_xh[path] + (size_t)row * IN_;
    } else {
        row -= B_;
        src = (path ? wh : wi) + (size_t)row * IN_;
        dst = g_wch[path] + (size_t)row * IN_;
    }
    float4 v = reinterpret_cast<const float4*>(src)[tid];
    __half2* d = reinterpret_cast<__half2*>(dst);
    d[tid*2]   = __floats2half2_rn(v.x, v.y);
    d[tid*2+1] = __floats2half2_rn(v.z, v.w);
}

// =====================================================================
// convert_wa: w_*_a fp32 [4096,128] -> fp16 [4096,128]. grid (512,2)x256
// =====================================================================
__global__ __launch_bounds__(256) void convert_wa_kernel(
    const float* __restrict__ wi, const float* __restrict__ wh)
{
    const int path = blockIdx.y;
    const int idx  = blockIdx.x * 256 + threadIdx.x;
    const float* w = path ? wh : wi;
    float4 v = reinterpret_cast<const float4*>(w)[idx];
    __half2* d = reinterpret_cast<__half2*>(g_w2h[path]);
    d[idx * 2]     = __floats2half2_rn(v.x, v.y);
    d[idx * 2 + 1] = __floats2half2_rn(v.z, v.w);
}

// =====================================================================
// Stage 1 (mma, fp16): C[b,f] = (x @ wc^T)[b,f] * scale(b,f).
// Tile M=64 x N=128, K=1024 chunks of 128 (x8), cp.async double buffer.
// grid (B_/64, 2) = 128 CTAs, 256 thr (8 warps: 2(M) x 4(N)).
// =====================================================================
#define S1_LD   136
#define S1_ABUF (64 * S1_LD)
#define S1_WBUF (128 * S1_LD)
#define S1_TOT  ((2 * S1_ABUF + 2 * S1_WBUF) * 2)   // 104448

__device__ __forceinline__ void s1_load_chunk(
    int j, uint32_t aBase, uint32_t wBase,
    const __half* __restrict__ A, const __half* __restrict__ W,
    int row0, int tid)
{
    #pragma unroll
    for (int it = 0; it < 4; it++) {
        int idx = tid + it * 256;
        int r = idx >> 4, c = idx & 15;
        cp16(aBase + (uint32_t)(r * S1_LD + c * 8) * 2,
             A + (size_t)(row0 + r) * IN_ + j * 128 + c * 8);
    }
    #pragma unroll
    for (int it = 0; it < 8; it++) {
        int idx = tid + it * 256;
        int r = idx >> 4, c = idx & 15;
        cp16(wBase + (uint32_t)(r * S1_LD + c * 8) * 2,
             W + (size_t)r * IN_ + j * 128 + c * 8);
    }
}

__global__ __launch_bounds__(256) void stage1_mma_kernel(
    const float* __restrict__ topic,
    const float* __restrict__ thw_i, const float* __restrict__ thb_i,
    const float* __restrict__ wb_i,
    const float* __restrict__ thw_h, const float* __restrict__ thb_h,
    const float* __restrict__ wb_h)
{
    extern __shared__ __half sm1[];
    __shared__ float sTheta[64][4];

    const int tid  = threadIdx.x;
    const int lane = tid & 31;
    const int wid  = tid >> 5;
    const int path = blockIdx.y;
    const int row0 = blockIdx.x * 64;

    const __half* __restrict__ A = g_xh[path];
    const __half* __restrict__ W = g_wch[path];
    const float* __restrict__ thw = path ? thw_h : thw_i;
    const float* __restrict__ thb = path ? thb_h : thb_i;
    const float* __restrict__ wb  = path ? wb_h  : wb_i;
    __half* __restrict__ outp = g_a2h[path];

    if (tid < 192) {
        int r = tid / 3, t = tid - r * 3;
        const float* tp = topic + (size_t)(row0 + r) * T_;
        sTheta[r][t] = thb[t] + tp[0]*thw[t*T_+0] + tp[1]*thw[t*T_+1] + tp[2]*thw[t*T_+2];
    }

    uint32_t aB[2] = { smem_u32(sm1), smem_u32(sm1 + S1_ABUF) };
    uint32_t wB[2] = { smem_u32(sm1 + 2 * S1_ABUF),
                       smem_u32(sm1 + 2 * S1_ABUF + S1_WBUF) };

    s1_load_chunk(0, aB[0], wB[0], A, W, row0, tid);
    CP_COMMIT();

    const int wm = (wid & 1) * 32;
    const int wn = (wid >> 1) * 32;
    const int lr  = lane & 7;
    const int seg = lane >> 3;
    const int l16 = lane & 15;

    float acc[2][4][4];
    #pragma unroll
    for (int mt = 0; mt < 2; mt++)
        #pragma unroll
        for (int nt = 0; nt < 4; nt++)
            #pragma unroll
            for (int j = 0; j < 4; j++) acc[mt][nt][j] = 0.f;

    for (int j = 0; j < 8; j++) {
        const int bf = j & 1;
        if (j < 7) {
            s1_load_chunk(j + 1, aB[(j+1)&1], wB[(j+1)&1], A, W, row0, tid);
            CP_COMMIT();
            CP_WAIT(1);
        } else {
            CP_WAIT(0);
        }
        __syncthreads();

        #pragma unroll
        for (int s = 0; s < 8; s++) {
            const int acol = s * 16 + ((seg >> 1) << 3);
            const int bcol = s * 16 + ((l16 >> 3) << 3);

            uint32_t a[2][4];
            #pragma unroll
            for (int mt = 0; mt < 2; mt++) {
                int arow = wm + mt * 16 + lr + ((seg & 1) << 3);
                uint32_t addr = aB[bf] + (uint32_t)(arow * S1_LD + acol) * 2;
                asm volatile("ldmatrix.sync.aligned.m8n8.x4.shared.b16 {%0,%1,%2,%3}, [%4];"
                             : "=r"(a[mt][0]), "=r"(a[mt][1]),
                               "=r"(a[mt][2]), "=r"(a[mt][3])
                             : "r"(addr));
            }
            uint32_t b[4][2];
            #pragma unroll
            for (int nt = 0; nt < 4; nt++) {
                int brow = wn + nt * 8 + (l16 & 7);
                uint32_t addr = wB[bf] + (uint32_t)(brow * S1_LD + bcol) * 2;
                asm volatile("ldmatrix.sync.aligned.m8n8.x2.shared.b16 {%0,%1}, [%2];"
                             : "=r"(b[nt][0]), "=r"(b[nt][1])
                             : "r"(addr));
            }
            #pragma unroll
            for (int mt = 0; mt < 2; mt++)
                #pragma unroll
                for (int nt = 0; nt < 4; nt++) {
                    asm volatile(
                        "mma.sync.aligned.m16n8k16.row.col.f32.f16.f16.f32 "
                        "{%0,%1,%2,%3}, {%4,%5,%6,%7}, {%8,%9}, {%0,%1,%2,%3};"
                        : "+f"(acc[mt][nt][0]), "+f"(acc[mt][nt][1]),
                          "+f"(acc[mt][nt][2]), "+f"(acc[mt][nt][3])
                        : "r"(a[mt][0]), "r"(a[mt][1]), "r"(a[mt][2]), "r"(a[mt][3]),
                          "r"(b[nt][0]), "r"(b[nt][1]));
                }
        }
        __syncthreads();
    }

    const int em = lane >> 2;
    const int en = (lane & 3) * 2;
    #pragma unroll
    for (int nt = 0; nt < 4; nt++) {
        const int n = wn + nt * 8 + en;
        float w0a = wb[n*T_+0],     w1a = wb[n*T_+1],     w2a = wb[n*T_+2];
        float w0b = wb[(n+1)*T_+0], w1b = wb[(n+1)*T_+1], w2b = wb[(n+1)*T_+2];
        #pragma unroll
        for (int mt = 0; mt < 2; mt++) {
            #pragma unroll
            for (int half = 0; half < 2; half++) {
                int m = wm + mt * 16 + em + half * 8;
                float th0 = sTheta[m][0], th1 = sTheta[m][1], th2 = sTheta[m][2];
                float sc0 = th0*w0a + th1*w1a + th2*w2a;
                float sc1 = th0*w0b + th1*w1b + th2*w2b;
                float v0 = acc[mt][nt][half*2 + 0] * sc0;
                float v1 = acc[mt][nt][half*2 + 1] * sc1;
                *reinterpret_cast<__half2*>(&outp[(size_t)(row0 + m) * F_ + n]) =
                    __floats2half2_rn(v0, v1);
            }
        }
    }
}

// =====================================================================
// Stage 2: fp16 mma GEMM, K=128. A-resident, W-streamed.
// CTA tile 128 x 256, warp tile 64x64 (8 warps 2(M) x 4(N)).
// NCT=4 col tiles of 256; W double-buffered cp.async.
// grid = (4, 32, 2) = 256 CTAs, 256 thr.
// smem: A[128x136] + 2x W[256x136] fp16 = 174080 B (1 CTA/SM).
// =====================================================================
#define S2_LD    136
#define S2_ATILE (128 * S2_LD)
#define S2_WTILE (256 * S2_LD)
#define S2_TOT   ((S2_ATILE + 2 * S2_WTILE) * 2)    // 174080
#define NCT      4

__device__ __forceinline__ void s2_load_w(
    const __half* __restrict__ W, int col0, uint32_t base, int tid)
{
    #pragma unroll
    for (int it = 0; it < 16; it++) {
        int idx = tid + it * 256;
        int r = idx >> 4, c = idx & 15;
        cp16(base + (uint32_t)(r * S2_LD + c * 8) * 2,
             W + (size_t)(col0 + r) * F_ + c * 8);
    }
}

__global__ __launch_bounds__(256, 1) void stage2_mma_kernel()
{
    extern __shared__ __half sm2[];

    const int tid  = threadIdx.x;
    const int lane = tid & 31;
    const int wid  = tid >> 5;
    const int path = blockIdx.z;
    const int row0 = blockIdx.y * 128;
    const int ct0  = blockIdx.x * NCT;          // first 256-col tile

    const __half* __restrict__ A = g_a2h[path];
    const __half* __restrict__ W = g_w2h[path];
    __half* __restrict__ O = g_gates[path];

    const uint32_t as_base = smem_u32(sm2);
    uint32_t wBuf[2] = { smem_u32(sm2 + S2_ATILE),
                         smem_u32(sm2 + S2_ATILE + S2_WTILE) };

    // A tile (stays resident): 128 rows x 16 chunks
    #pragma unroll
    for (int it = 0; it < 8; it++) {
        int idx = tid + it * 256;
        int r = idx >> 4, c = idx & 15;
        cp16(as_base + (uint32_t)(r * S2_LD + c * 8) * 2,
             A + (size_t)(row0 + r) * F_ + c * 8);
    }
    s2_load_w(W, ct0 * 256, wBuf[0], tid);
    CP_COMMIT();

    const int wm = (wid & 1) * 64;               // 2 M-warps cover 128 rows
    const int wn = (wid >> 1) * 64;              // 4 N-warps cover 256 cols
    const int lr  = lane & 7;
    const int seg = lane >> 3;                   // 0..3
    const int em = lane >> 2;
    const int en = (lane & 3) * 2;

    for (int it = 0; it < NCT; it++) {
        const int buf = it & 1;
        if (it + 1 < NCT) {
            s2_load_w(W, (ct0 + it + 1) * 256, wBuf[(it + 1) & 1], tid);
            CP_COMMIT();
            CP_WAIT(1);
        } else {
            CP_WAIT(0);
        }
        __syncthreads();

        float acc[4][8][4];
        #pragma unroll
        for (int mt = 0; mt < 4; mt++)
            #pragma unroll
            for (int nt = 0; nt < 8; nt++)
                #pragma unroll
                for (int j = 0; j < 4; j++) acc[mt][nt][j] = 0.f;

        const uint32_t bs_base = wBuf[buf];
        #pragma unroll
        for (int s = 0; s < 8; s++) {
            const int acol = s * 16 + ((seg >> 1) << 3);

            uint32_t a[4][4];
            #pragma unroll
            for (int mt = 0; mt < 4; mt++) {
                int arow = wm + mt * 16 + lr + ((seg & 1) << 3);
                uint32_t addr = as_base + (uint32_t)(arow * S2_LD + acol) * 2;
                asm volatile("ldmatrix.sync.aligned.m8n8.x4.shared.b16 {%0,%1,%2,%3}, [%4];"
                             : "=r"(a[mt][0]), "=r"(a[mt][1]),
                               "=r"(a[mt][2]), "=r"(a[mt][3])
                             : "r"(addr));
            }
            // B: 4 x4 loads, each covers an nt-pair (16 rows x 16 cols).
            // lane group g: row = wn + ntp*16 + ((g>>1)<<3) + (lane&7),
            //               col = s*16 + ((g&1)<<3)
            uint32_t b[4][4];     // [ntp][b(2ntp,0), b(2ntp,1), b(2ntp+1,0), b(2ntp+1,1)]
            #pragma unroll
            for (int ntp = 0; ntp < 4; ntp++) {
                int brow = wn + ntp * 16 + ((seg >> 1) << 3) + lr;
                int bcol = s * 16 + ((seg & 1) << 3);
                uint32_t addr = bs_base + (uint32_t)(brow * S2_LD + bcol) * 2;
                asm volatile("ldmatrix.sync.aligned.m8n8.x4.shared.b16 {%0,%1,%2,%3}, [%4];"
                             : "=r"(b[ntp][0]), "=r"(b[ntp][1]),
                               "=r"(b[ntp][2]), "=r"(b[ntp][3])
                             : "r"(addr));
            }
            #pragma unroll
            for (int mt = 0; mt < 4; mt++)
                #pragma unroll
                for (int nt = 0; nt < 8; nt++) {
                    const uint32_t b0 = b[nt >> 1][(nt & 1) * 2 + 0];
                    const uint32_t b1 = b[nt >> 1][(nt & 1) * 2 + 1];
                    asm volatile(
                        "mma.sync.aligned.m16n8k16.row.col.f32.f16.f16.f32 "
                        "{%0,%1,%2,%3}, {%4,%5,%6,%7}, {%8,%9}, {%0,%1,%2,%3};"
                        : "+f"(acc[mt][nt][0]), "+f"(acc[mt][nt][1]),
                          "+f"(acc[mt][nt][2]), "+f"(acc[mt][nt][3])
                        : "r"(a[mt][0]), "r"(a[mt][1]), "r"(a[mt][2]), "r"(a[mt][3]),
                          "r"(b0), "r"(b1));
                }
        }

        // ---- epilogue for this 256-col tile (fp16 stores) ----
        const int col0 = (ct0 + it) * 256;
        #pragma unroll
        for (int mt = 0; mt < 4; mt++) {
            #pragma unroll
            for (int nt = 0; nt < 8; nt++) {
                int m = row0 + wm + mt * 16 + em;
                int n = col0 + wn + nt * 8 + en;
                *reinterpret_cast<__half2*>(&O[(size_t)m * G_ + n]) =
                    __floats2half2_rn(acc[mt][nt][0], acc[mt][nt][1]);
                *reinterpret_cast<__half2*>(&O[(size_t)(m + 8) * G_ + n]) =
                    __floats2half2_rn(acc[mt][nt][2], acc[mt][nt][3]);
            }
        }
        __syncthreads();
    }
}

// =====================================================================
// Stage 3: per-row LN(igates)+LN(hgates), gates, cell update, LN(cell).
// =====================================================================
__device__ __forceinline__ float2 block_reduce2(float s, float q, float* red)
{
    __syncthreads();
    #pragma unroll
    for (int o = 16; o > 0; o >>= 1) {
        s += __shfl_xor_sync(0xffffffffu, s, o);
        q += __shfl_xor_sync(0xffffffffu, q, o);
    }
    int w = threadIdx.x >> 5, l = threadIdx.x & 31;
    if (l == 0) { red[w] = s; red[8 + w] = q; }
    __syncthreads();
    if (w == 0) {
        s = (l < 8) ? red[l] : 0.f;
        q = (l < 8) ? red[8 + l] : 0.f;
        #pragma unroll
        for (int o = 4; o > 0; o >>= 1) {
            s += __shfl_xor_sync(0xffffffffu, s, o);
            q += __shfl_xor_sync(0xffffffffu, q, o);
        }
        if (l == 0) { red[0] = s; red[1] = q; }
    }
    __syncthreads();
    return make_float2(red[0], red[1]);
}

__device__ __forceinline__ void unpack8(const uint4& u, float4& lo, float4& hi)
{
    float2 f0 = __half22float2(*reinterpret_cast<const __half2*>(&u.x));
    float2 f1 = __half22float2(*reinterpret_cast<const __half2*>(&u.y));
    float2 f2 = __half22float2(*reinterpret_cast<const __half2*>(&u.z));
    float2 f3 = __half22float2(*reinterpret_cast<const __half2*>(&u.w));
    lo = make_float4(f0.x, f0.y, f1.x, f1.y);
    hi = make_float4(f2.x, f2.y, f3.x, f3.y);
}

__global__ __launch_bounds__(256) void stage3_kernel(
    const float* __restrict__ cx,
    const float* __restrict__ lniw, const float* __restrict__ lnib,
    const float* __restrict__ lnhw, const float* __restrict__ lnhb,
    const float* __restrict__ lncw, const float* __restrict__ lncb,
    float* __restrict__ out)
{
    __shared__ float4 s_ig[1024];
    __shared__ float4 s_hg[1024];
    __shared__ float red[16];

    const int r   = blockIdx.x;
    const int tid = threadIdx.x;
    const uint4* __restrict__ igv =
        reinterpret_cast<const uint4*>(g_gates[0] + (size_t)r * G_);
    const uint4* __restrict__ hgv =
        reinterpret_cast<const uint4*>(g_gates[1] + (size_t)r * G_);

    float s = 0.f, q = 0.f;
    #pragma unroll
    for (int i = 0; i < 2; i++) {
        int n = tid + i * 256;
        float4 lo, hi;
        unpack8(igv[n], lo, hi);
        s_ig[2*n]   = lo;
        s_ig[2*n+1] = hi;
        s += lo.x + lo.y + lo.z + lo.w + hi.x + hi.y + hi.z + hi.w;
        q += lo.x*lo.x + lo.y*lo.y + lo.z*lo.z + lo.w*lo.w
           + hi.x*hi.x + hi.y*hi.y + hi.z*hi.z + hi.w*hi.w;
    }
    float2 ri = block_reduce2(s, q, red);
    float mu_i = ri.x * (1.f / G_);
    float rstd_i = rsqrtf(ri.y * (1.f / G_) - mu_i * mu_i + LN_EPS);

    s = 0.f; q = 0.f;
    #pragma unroll
    for (int i = 0; i < 2; i++) {
        int n = tid + i * 256;
        float4 lo, hi;
        unpack8(hgv[n], lo, hi);
        s_hg[2*n]   = lo;
        s_hg[2*n+1] = hi;
        s += lo.x + lo.y + lo.z + lo.w + hi.x + hi.y + hi.z + hi.w;
        q += lo.x*lo.x + lo.y*lo.y + lo.z*lo.z + lo.w*lo.w
           + hi.x*hi.x + hi.y*hi.y + hi.z*hi.z + hi.w*hi.w;
    }
    float2 rh = block_reduce2(s, q, red);
    float mu_h = rh.x * (1.f / G_);
    float rstd_h = rsqrtf(rh.y * (1.f / G_) - mu_h * mu_h + LN_EPS);

    const float4* lniw4 = reinterpret_cast<const float4*>(lniw);
    const float4* lnib4 = reinterpret_cast<const float4*>(lnib);
    const float4* lnhw4 = reinterpret_cast<const float4*>(lnhw);
    const float4* lnhb4 = reinterpret_cast<const float4*>(lnhb);

    float4 gi_v[4], gh_v[4], wi_v[4], bi_v[4], wh_v[4], bh_v[4];
    #pragma unroll
    for (int g = 0; g < 4; g++) {
        int n = tid + g * 256;
        gi_v[g] = s_ig[n];  gh_v[g] = s_hg[n];
        wi_v[g] = lniw4[n]; bi_v[g] = lnib4[n];
        wh_v[g] = lnhw4[n]; bh_v[g] = lnhb4[n];
    }
    float4 cxv = reinterpret_cast<const float4*>(cx + (size_t)r * H_)[tid];

    float cc[4], oo[4];
    float cs = 0.f, cq = 0.f;
    #pragma unroll
    for (int c = 0; c < 4; c++) {
        #define GVAL(g) ((f4c(gi_v[g],c) - mu_i) * rstd_i * f4c(wi_v[g],c) + f4c(bi_v[g],c) + \
                         (f4c(gh_v[g],c) - mu_h) * rstd_h * f4c(wh_v[g],c) + f4c(bh_v[g],c))
        float gi = sigm(GVAL(0));
        float gf = sigm(GVAL(1));
        float gg = tanh_fast(GVAL(2));
        float go = sigm(GVAL(3));
        #undef GVAL
        float c_ = gf * f4c(cxv, c) + gi * gg;
        cc[c] = c_; oo[c] = go;
        cs += c_; cq += c_ * c_;
    }
    float2 rc = block_reduce2(cs, cq, red);
    float mu_c = rc.x * (1.f / H_);
    float rstd_c = rsqrtf(rc.y * (1.f / H_) - mu_c * mu_c + LN_EPS);

    float4 wcv = reinterpret_cast<const float4*>(lncw)[tid];
    float4 bcv = reinterpret_cast<const float4*>(lncb)[tid];
    float4 hyv, cyv;
    #pragma unroll
    for (int c = 0; c < 4; c++) {
        float cy = (cc[c] - mu_c) * rstd_c * f4c(wcv, c) + f4c(bcv, c);
        reinterpret_cast<float*>(&cyv)[c] = cy;
        reinterpret_cast<float*>(&hyv)[c] = oo[c] * tanh_fast(cy);
    }
    float4* out4 = reinterpret_cast<float4*>(out);
    out4[(size_t)r * 256 + tid] = hyv;
    out4[(size_t)B_ * 256 + (size_t)r * 256 + tid] = cyv;
}

// =====================================================================
extern "C" void kernel_launch(void* const* d_in, const int* in_sizes, int n_in,
                              void* d_out, int out_size)
{
    const float* input_ = (const float*)d_in[0];
    const float* hx     = (const float*)d_in[1];
    const float* cx     = (const float*)d_in[2];
    const float* topic  = (const float*)d_in[3];
    const float* w_ih_a = (const float*)d_in[4];
    const float* w_ih_b = (const float*)d_in[5];
    const float* w_ih_c = (const float*)d_in[6];
    const float* w_hh_a = (const float*)d_in[7];
    const float* w_hh_b = (const float*)d_in[8];
    const float* w_hh_c = (const float*)d_in[9];
    const float* th_ih_w = (const float*)d_in[10];
    const float* th_ih_b = (const float*)d_in[11];
    const float* th_hh_w = (const float*)d_in[12];
    const float* th_hh_b = (const float*)d_in[13];
    const float* ln_i_w  = (const float*)d_in[14];
    const float* ln_i_b  = (const float*)d_in[15];
    const float* ln_h_w  = (const float*)d_in[16];
    const float* ln_h_b  = (const float*)d_in[17];
    const float* ln_c_w  = (const float*)d_in[18];
    const float* ln_c_b  = (const float*)d_in[19];

    cudaFuncSetAttribute(stage1_mma_kernel,
                         cudaFuncAttributeMaxDynamicSharedMemorySize, S1_TOT);
    cudaFuncSetAttribute(stage2_mma_kernel,
                         cudaFuncAttributeMaxDynamicSharedMemorySize, S2_TOT);

    convert_xwc_kernel<<<dim3(B_ + F_, 2), 256>>>(input_, hx, w_ih_c, w_hh_c);
    convert_wa_kernel<<<dim3(512, 2), 256>>>(w_ih_a, w_hh_a);

    stage1_mma_kernel<<<dim3(B_ / 64, 2), 256, S1_TOT>>>(
        topic, th_ih_w, th_ih_b, w_ih_b, th_hh_w, th_hh_b, w_hh_b);

    stage2_mma_kernel<<<dim3(G_ / 256 / NCT, B_ / 128, 2), 256, S2_TOT>>>();

    stage3_kernel<<<B_, 256>>>(cx, ln_i_w, ln_i_b, ln_h_w, ln_h_b,
                               ln_c_w, ln_c_b, (float*)d_out);
}

// round 13
// speedup vs baseline: 2.0834x; 1.1220x over previous
#include <cuda_runtime.h>
#include <cuda_bf16.h>
#include <cuda_fp16.h>
#include <math.h>
#include <stdint.h>

#define B_   4096
#define IN_  1024
#define H_   1024
#define F_   128
#define T_   3
#define G_   4096      // 4*H
#define LN_EPS 1e-5f

// ---------------- scratch (no allocations allowed) ----------------
__device__ __align__(16) __half g_xh[2][(size_t)B_ * IN_];   // x/hx fp16
__device__ __align__(16) __half g_wch[2][(size_t)F_ * IN_];  // wc fp16
__device__ __align__(16) __half g_a2h[2][(size_t)B_ * F_];   // stage1 out (fp16)
__device__ __align__(16) __half g_w2h[2][(size_t)G_ * F_];   // w_*_a  (fp16)
__device__ __align__(16) __half g_gates[2][(size_t)B_ * G_]; // ig / hg (fp16)

__device__ __forceinline__ uint32_t smem_u32(const void* p) {
    uint32_t a;
    asm("{ .reg .u64 t; cvta.to.shared.u64 t, %1; cvt.u32.u64 %0, t; }"
        : "=r"(a) : "l"(p));
    return a;
}
__device__ __forceinline__ void cp16(uint32_t dst, const void* src) {
    asm volatile("cp.async.cg.shared.global [%0], [%1], 16;"
                 :: "r"(dst), "l"(src));
}
#define CP_COMMIT()  asm volatile("cp.async.commit_group;")
#define CP_WAIT(n)   asm volatile("cp.async.wait_group %0;" :: "n"(n))

__device__ __forceinline__ float f4c(const float4& v, int c) {
    return reinterpret_cast<const float*>(&v)[c];
}
__device__ __forceinline__ float fexp2(float x) {
    float y; asm("ex2.approx.f32 %0, %1;" : "=f"(y) : "f"(x)); return y;
}
__device__ __forceinline__ float frcp(float x) {
    float y; asm("rcp.approx.f32 %0, %1;" : "=f"(y) : "f"(x)); return y;
}
__device__ __forceinline__ float sigm(float x) {
    return frcp(1.f + fexp2(-1.4426950408889634f * x));
}
__device__ __forceinline__ float tanh_fast(float x) {
    return 2.f * frcp(1.f + fexp2(-2.8853900817779268f * x)) - 1.f;
}

// =====================================================================
// convert_all: one flat fp32 -> fp16 pass over all 6 segments.
// grid 9472 x 256; each thread one float4 -> half2 pair.
// =====================================================================
#define CV_X   (B_ * IN_ / 4)          // 1048576 float4 per path
#define CV_WC  (F_ * IN_ / 4)          // 32768
#define CV_WA  (G_ * F_ / 4)           // 131072
#define CV_TOT (2 * CV_X + 2 * CV_WC + 2 * CV_WA)   // 2424832 = 9472*256

__global__ __launch_bounds__(256) void convert_all_kernel(
    const float* __restrict__ xi, const float* __restrict__ xh,
    const float* __restrict__ wci, const float* __restrict__ wch,
    const float* __restrict__ wai, const float* __restrict__ wah)
{
    int idx = blockIdx.x * 256 + threadIdx.x;
    const float* src;
    __half* dst;
    if (idx < 2 * CV_X) {
        int p = idx >= CV_X; int off = idx - p * CV_X;
        src = (p ? xh : xi) + off * 4;  dst = g_xh[p] + off * 4;
    } else if (idx < 2 * CV_X + 2 * CV_WC) {
        idx -= 2 * CV_X;
        int p = idx >= CV_WC; int off = idx - p * CV_WC;
        src = (p ? wch : wci) + off * 4;  dst = g_wch[p] + off * 4;
    } else {
        idx -= 2 * CV_X + 2 * CV_WC;
        int p = idx >= CV_WA; int off = idx - p * CV_WA;
        src = (p ? wah : wai) + off * 4;  dst = g_w2h[p] + off * 4;
    }
    float4 v = *reinterpret_cast<const float4*>(src);
    __half2* d = reinterpret_cast<__half2*>(dst);
    d[0] = __floats2half2_rn(v.x, v.y);
    d[1] = __floats2half2_rn(v.z, v.w);
}

// =====================================================================
// Stage 1 (mma, fp16): C[b,f] = (x @ wc^T)[b,f] * scale(b,f).
// Tile M=64 x N=128, K=1024 chunks of 128 (x8), cp.async double buffer.
// grid (B_/64, 2) = 128 CTAs, 256 thr (8 warps: 2(M) x 4(N)).
// =====================================================================
#define S1_LD   136
#define S1_ABUF (64 * S1_LD)
#define S1_WBUF (128 * S1_LD)
#define S1_TOT  ((2 * S1_ABUF + 2 * S1_WBUF) * 2)   // 104448

__device__ __forceinline__ void s1_load_chunk(
    int j, uint32_t aBase, uint32_t wBase,
    const __half* __restrict__ A, const __half* __restrict__ W,
    int row0, int tid)
{
    #pragma unroll
    for (int it = 0; it < 4; it++) {
        int idx = tid + it * 256;
        int r = idx >> 4, c = idx & 15;
        cp16(aBase + (uint32_t)(r * S1_LD + c * 8) * 2,
             A + (size_t)(row0 + r) * IN_ + j * 128 + c * 8);
    }
    #pragma unroll
    for (int it = 0; it < 8; it++) {
        int idx = tid + it * 256;
        int r = idx >> 4, c = idx & 15;
        cp16(wBase + (uint32_t)(r * S1_LD + c * 8) * 2,
             W + (size_t)r * IN_ + j * 128 + c * 8);
    }
}

__global__ __launch_bounds__(256) void stage1_mma_kernel(
    const float* __restrict__ topic,
    const float* __restrict__ thw_i, const float* __restrict__ thb_i,
    const float* __restrict__ wb_i,
    const float* __restrict__ thw_h, const float* __restrict__ thb_h,
    const float* __restrict__ wb_h)
{
    extern __shared__ __half sm1[];
    __shared__ float sTheta[64][4];

    const int tid  = threadIdx.x;
    const int lane = tid & 31;
    const int wid  = tid >> 5;
    const int path = blockIdx.y;
    const int row0 = blockIdx.x * 64;

    const __half* __restrict__ A = g_xh[path];
    const __half* __restrict__ W = g_wch[path];
    const float* __restrict__ thw = path ? thw_h : thw_i;
    const float* __restrict__ thb = path ? thb_h : thb_i;
    const float* __restrict__ wb  = path ? wb_h  : wb_i;
    __half* __restrict__ outp = g_a2h[path];

    if (tid < 192) {
        int r = tid / 3, t = tid - r * 3;
        const float* tp = topic + (size_t)(row0 + r) * T_;
        sTheta[r][t] = thb[t] + tp[0]*thw[t*T_+0] + tp[1]*thw[t*T_+1] + tp[2]*thw[t*T_+2];
    }

    uint32_t aB[2] = { smem_u32(sm1), smem_u32(sm1 + S1_ABUF) };
    uint32_t wB[2] = { smem_u32(sm1 + 2 * S1_ABUF),
                       smem_u32(sm1 + 2 * S1_ABUF + S1_WBUF) };

    s1_load_chunk(0, aB[0], wB[0], A, W, row0, tid);
    CP_COMMIT();

    const int wm = (wid & 1) * 32;
    const int wn = (wid >> 1) * 32;
    const int lr  = lane & 7;
    const int seg = lane >> 3;
    const int l16 = lane & 15;

    float acc[2][4][4];
    #pragma unroll
    for (int mt = 0; mt < 2; mt++)
        #pragma unroll
        for (int nt = 0; nt < 4; nt++)
            #pragma unroll
            for (int j = 0; j < 4; j++) acc[mt][nt][j] = 0.f;

    for (int j = 0; j < 8; j++) {
        const int bf = j & 1;
        if (j < 7) {
            s1_load_chunk(j + 1, aB[(j+1)&1], wB[(j+1)&1], A, W, row0, tid);
            CP_COMMIT();
            CP_WAIT(1);
        } else {
            CP_WAIT(0);
        }
        __syncthreads();

        #pragma unroll
        for (int s = 0; s < 8; s++) {
            const int acol = s * 16 + ((seg >> 1) << 3);
            const int bcol = s * 16 + ((l16 >> 3) << 3);

            uint32_t a[2][4];
            #pragma unroll
            for (int mt = 0; mt < 2; mt++) {
                int arow = wm + mt * 16 + lr + ((seg & 1) << 3);
                uint32_t addr = aB[bf] + (uint32_t)(arow * S1_LD + acol) * 2;
                asm volatile("ldmatrix.sync.aligned.m8n8.x4.shared.b16 {%0,%1,%2,%3}, [%4];"
                             : "=r"(a[mt][0]), "=r"(a[mt][1]),
                               "=r"(a[mt][2]), "=r"(a[mt][3])
                             : "r"(addr));
            }
            uint32_t b[4][2];
            #pragma unroll
            for (int nt = 0; nt < 4; nt++) {
                int brow = wn + nt * 8 + (l16 & 7);
                uint32_t addr = wB[bf] + (uint32_t)(brow * S1_LD + bcol) * 2;
                asm volatile("ldmatrix.sync.aligned.m8n8.x2.shared.b16 {%0,%1}, [%2];"
                             : "=r"(b[nt][0]), "=r"(b[nt][1])
                             : "r"(addr));
            }
            #pragma unroll
            for (int mt = 0; mt < 2; mt++)
                #pragma unroll
                for (int nt = 0; nt < 4; nt++) {
                    asm volatile(
                        "mma.sync.aligned.m16n8k16.row.col.f32.f16.f16.f32 "
                        "{%0,%1,%2,%3}, {%4,%5,%6,%7}, {%8,%9}, {%0,%1,%2,%3};"
                        : "+f"(acc[mt][nt][0]), "+f"(acc[mt][nt][1]),
                          "+f"(acc[mt][nt][2]), "+f"(acc[mt][nt][3])
                        : "r"(a[mt][0]), "r"(a[mt][1]), "r"(a[mt][2]), "r"(a[mt][3]),
                          "r"(b[nt][0]), "r"(b[nt][1]));
                }
        }
        __syncthreads();
    }

    const int em = lane >> 2;
    const int en = (lane & 3) * 2;
    #pragma unroll
    for (int nt = 0; nt < 4; nt++) {
        const int n = wn + nt * 8 + en;
        float w0a = wb[n*T_+0],     w1a = wb[n*T_+1],     w2a = wb[n*T_+2];
        float w0b = wb[(n+1)*T_+0], w1b = wb[(n+1)*T_+1], w2b = wb[(n+1)*T_+2];
        #pragma unroll
        for (int mt = 0; mt < 2; mt++) {
            #pragma unroll
            for (int half = 0; half < 2; half++) {
                int m = wm + mt * 16 + em + half * 8;
                float th0 = sTheta[m][0], th1 = sTheta[m][1], th2 = sTheta[m][2];
                float sc0 = th0*w0a + th1*w1a + th2*w2a;
                float sc1 = th0*w0b + th1*w1b + th2*w2b;
                float v0 = acc[mt][nt][half*2 + 0] * sc0;
                float v1 = acc[mt][nt][half*2 + 1] * sc1;
                *reinterpret_cast<__half2*>(&outp[(size_t)(row0 + m) * F_ + n]) =
                    __floats2half2_rn(v0, v1);
            }
        }
    }
}

// =====================================================================
// Stage 2: fp16 mma GEMM, K=128. A-resident, W-streamed.
// CTA tile 128 x 256, warp tile 64x64 (8 warps 2(M) x 4(N)).
// NCT=4 col tiles of 256; W double-buffered cp.async.
// grid = (4, 32, 2) = 256 CTAs, 256 thr. smem 174080 B.
// =====================================================================
#define S2_LD    136
#define S2_ATILE (128 * S2_LD)
#define S2_WTILE (256 * S2_LD)
#define S2_TOT   ((S2_ATILE + 2 * S2_WTILE) * 2)    // 174080
#define NCT      4

__device__ __forceinline__ void s2_load_w(
    const __half* __restrict__ W, int col0, uint32_t base, int tid)
{
    #pragma unroll
    for (int it = 0; it < 16; it++) {
        int idx = tid + it * 256;
        int r = idx >> 4, c = idx & 15;
        cp16(base + (uint32_t)(r * S2_LD + c * 8) * 2,
             W + (size_t)(col0 + r) * F_ + c * 8);
    }
}

__global__ __launch_bounds__(256, 1) void stage2_mma_kernel()
{
    extern __shared__ __half sm2[];

    const int tid  = threadIdx.x;
    const int lane = tid & 31;
    const int wid  = tid >> 5;
    const int path = blockIdx.z;
    const int row0 = blockIdx.y * 128;
    const int ct0  = blockIdx.x * NCT;

    const __half* __restrict__ A = g_a2h[path];
    const __half* __restrict__ W = g_w2h[path];
    __half* __restrict__ O = g_gates[path];

    const uint32_t as_base = smem_u32(sm2);
    uint32_t wBuf[2] = { smem_u32(sm2 + S2_ATILE),
                         smem_u32(sm2 + S2_ATILE + S2_WTILE) };

    #pragma unroll
    for (int it = 0; it < 8; it++) {
        int idx = tid + it * 256;
        int r = idx >> 4, c = idx & 15;
        cp16(as_base + (uint32_t)(r * S2_LD + c * 8) * 2,
             A + (size_t)(row0 + r) * F_ + c * 8);
    }
    s2_load_w(W, ct0 * 256, wBuf[0], tid);
    CP_COMMIT();

    const int wm = (wid & 1) * 64;
    const int wn = (wid >> 1) * 64;
    const int lr  = lane & 7;
    const int seg = lane >> 3;
    const int em = lane >> 2;
    const int en = (lane & 3) * 2;

    for (int it = 0; it < NCT; it++) {
        const int buf = it & 1;
        if (it + 1 < NCT) {
            s2_load_w(W, (ct0 + it + 1) * 256, wBuf[(it + 1) & 1], tid);
            CP_COMMIT();
            CP_WAIT(1);
        } else {
            CP_WAIT(0);
        }
        __syncthreads();

        float acc[4][8][4];
        #pragma unroll
        for (int mt = 0; mt < 4; mt++)
            #pragma unroll
            for (int nt = 0; nt < 8; nt++)
                #pragma unroll
                for (int j = 0; j < 4; j++) acc[mt][nt][j] = 0.f;

        const uint32_t bs_base = wBuf[buf];
        #pragma unroll
        for (int s = 0; s < 8; s++) {
            const int acol = s * 16 + ((seg >> 1) << 3);

            uint32_t a[4][4];
            #pragma unroll
            for (int mt = 0; mt < 4; mt++) {
                int arow = wm + mt * 16 + lr + ((seg & 1) << 3);
                uint32_t addr = as_base + (uint32_t)(arow * S2_LD + acol) * 2;
                asm volatile("ldmatrix.sync.aligned.m8n8.x4.shared.b16 {%0,%1,%2,%3}, [%4];"
                             : "=r"(a[mt][0]), "=r"(a[mt][1]),
                               "=r"(a[mt][2]), "=r"(a[mt][3])
                             : "r"(addr));
            }
            uint32_t b[4][4];
            #pragma unroll
            for (int ntp = 0; ntp < 4; ntp++) {
                int brow = wn + ntp * 16 + ((seg >> 1) << 3) + lr;
                int bcol = s * 16 + ((seg & 1) << 3);
                uint32_t addr = bs_base + (uint32_t)(brow * S2_LD + bcol) * 2;
                asm volatile("ldmatrix.sync.aligned.m8n8.x4.shared.b16 {%0,%1,%2,%3}, [%4];"
                             : "=r"(b[ntp][0]), "=r"(b[ntp][1]),
                               "=r"(b[ntp][2]), "=r"(b[ntp][3])
                             : "r"(addr));
            }
            #pragma unroll
            for (int mt = 0; mt < 4; mt++)
                #pragma unroll
                for (int nt = 0; nt < 8; nt++) {
                    const uint32_t b0 = b[nt >> 1][(nt & 1) * 2 + 0];
                    const uint32_t b1 = b[nt >> 1][(nt & 1) * 2 + 1];
                    asm volatile(
                        "mma.sync.aligned.m16n8k16.row.col.f32.f16.f16.f32 "
                        "{%0,%1,%2,%3}, {%4,%5,%6,%7}, {%8,%9}, {%0,%1,%2,%3};"
                        : "+f"(acc[mt][nt][0]), "+f"(acc[mt][nt][1]),
                          "+f"(acc[mt][nt][2]), "+f"(acc[mt][nt][3])
                        : "r"(a[mt][0]), "r"(a[mt][1]), "r"(a[mt][2]), "r"(a[mt][3]),
                          "r"(b0), "r"(b1));
                }
        }

        const int col0 = (ct0 + it) * 256;
        #pragma unroll
        for (int mt = 0; mt < 4; mt++) {
            #pragma unroll
            for (int nt = 0; nt < 8; nt++) {
                int m = row0 + wm + mt * 16 + em;
                int n = col0 + wn + nt * 8 + en;
                *reinterpret_cast<__half2*>(&O[(size_t)m * G_ + n]) =
                    __floats2half2_rn(acc[mt][nt][0], acc[mt][nt][1]);
                *reinterpret_cast<__half2*>(&O[(size_t)(m + 8) * G_ + n]) =
                    __floats2half2_rn(acc[mt][nt][2], acc[mt][nt][3]);
            }
        }
        __syncthreads();
    }
}

// =====================================================================
// Stage 3: per-row LN(igates)+LN(hgates), gates, cell update, LN(cell).
// Single-pass gate load (MLP 4), 4-way combined reduce.
// =====================================================================
__device__ __forceinline__ float4 block_reduce4(
    float a, float b, float c, float d, float* red)
{
    __syncthreads();
    #pragma unroll
    for (int o = 16; o > 0; o >>= 1) {
        a += __shfl_xor_sync(0xffffffffu, a, o);
        b += __shfl_xor_sync(0xffffffffu, b, o);
        c += __shfl_xor_sync(0xffffffffu, c, o);
        d += __shfl_xor_sync(0xffffffffu, d, o);
    }
    int w = threadIdx.x >> 5, l = threadIdx.x & 31;
    if (l == 0) { red[w] = a; red[8+w] = b; red[16+w] = c; red[24+w] = d; }
    __syncthreads();
    if (w == 0) {
        a = (l < 8) ? red[l]      : 0.f;
        b = (l < 8) ? red[8 + l]  : 0.f;
        c = (l < 8) ? red[16 + l] : 0.f;
        d = (l < 8) ? red[24 + l] : 0.f;
        #pragma unroll
        for (int o = 4; o > 0; o >>= 1) {
            a += __shfl_xor_sync(0xffffffffu, a, o);
            b += __shfl_xor_sync(0xffffffffu, b, o);
            c += __shfl_xor_sync(0xffffffffu, c, o);
            d += __shfl_xor_sync(0xffffffffu, d, o);
        }
        if (l == 0) { red[0] = a; red[1] = b; red[2] = c; red[3] = d; }
    }
    __syncthreads();
    return make_float4(red[0], red[1], red[2], red[3]);
}

__device__ __forceinline__ float2 block_reduce2(float s, float q, float* red)
{
    __syncthreads();
    #pragma unroll
    for (int o = 16; o > 0; o >>= 1) {
        s += __shfl_xor_sync(0xffffffffu, s, o);
        q += __shfl_xor_sync(0xffffffffu, q, o);
    }
    int w = threadIdx.x >> 5, l = threadIdx.x & 31;
    if (l == 0) { red[w] = s; red[8 + w] = q; }
    __syncthreads();
    if (w == 0) {
        s = (l < 8) ? red[l] : 0.f;
        q = (l < 8) ? red[8 + l] : 0.f;
        #pragma unroll
        for (int o = 4; o > 0; o >>= 1) {
            s += __shfl_xor_sync(0xffffffffu, s, o);
            q += __shfl_xor_sync(0xffffffffu, q, o);
        }
        if (l == 0) { red[0] = s; red[1] = q; }
    }
    __syncthreads();
    return make_float2(red[0], red[1]);
}

__device__ __forceinline__ void unpack8(const uint4& u, float4& lo, float4& hi)
{
    float2 f0 = __half22float2(*reinterpret_cast<const __half2*>(&u.x));
    float2 f1 = __half22float2(*reinterpret_cast<const __half2*>(&u.y));
    float2 f2 = __half22float2(*reinterpret_cast<const __half2*>(&u.z));
    float2 f3 = __half22float2(*reinterpret_cast<const __half2*>(&u.w));
    lo = make_float4(f0.x, f0.y, f1.x, f1.y);
    hi = make_float4(f2.x, f2.y, f3.x, f3.y);
}

__global__ __launch_bounds__(256) void stage3_kernel(
    const float* __restrict__ cx,
    const float* __restrict__ lniw, const float* __restrict__ lnib,
    const float* __restrict__ lnhw, const float* __restrict__ lnhb,
    const float* __restrict__ lncw, const float* __restrict__ lncb,
    float* __restrict__ out)
{
    __shared__ float4 s_ig[1024];
    __shared__ float4 s_hg[1024];
    __shared__ float red[32];

    const int r   = blockIdx.x;
    const int tid = threadIdx.x;
    const uint4* __restrict__ igv =
        reinterpret_cast<const uint4*>(g_gates[0] + (size_t)r * G_);
    const uint4* __restrict__ hgv =
        reinterpret_cast<const uint4*>(g_gates[1] + (size_t)r * G_);

    // front-batched loads: 4 x LDG.128 gates + 1 x LDG.128 cx (MLP 5)
    uint4 uig[2], uhg[2];
    #pragma unroll
    for (int i = 0; i < 2; i++) {
        uig[i] = igv[tid + i * 256];
        uhg[i] = hgv[tid + i * 256];
    }
    float4 cxv = reinterpret_cast<const float4*>(cx + (size_t)r * H_)[tid];

    float si = 0.f, qi = 0.f, sh = 0.f, qh = 0.f;
    #pragma unroll
    for (int i = 0; i < 2; i++) {
        int n = tid + i * 256;
        float4 lo, hi;
        unpack8(uig[i], lo, hi);
        s_ig[2*n] = lo; s_ig[2*n+1] = hi;
        si += lo.x + lo.y + lo.z + lo.w + hi.x + hi.y + hi.z + hi.w;
        qi += lo.x*lo.x + lo.y*lo.y + lo.z*lo.z + lo.w*lo.w
            + hi.x*hi.x + hi.y*hi.y + hi.z*hi.z + hi.w*hi.w;
        unpack8(uhg[i], lo, hi);
        s_hg[2*n] = lo; s_hg[2*n+1] = hi;
        sh += lo.x + lo.y + lo.z + lo.w + hi.x + hi.y + hi.z + hi.w;
        qh += lo.x*lo.x + lo.y*lo.y + lo.z*lo.z + lo.w*lo.w
            + hi.x*hi.x + hi.y*hi.y + hi.z*hi.z + hi.w*hi.w;
    }
    float4 rr = block_reduce4(si, qi, sh, qh, red);
    float mu_i = rr.x * (1.f / G_);
    float rstd_i = rsqrtf(rr.y * (1.f / G_) - mu_i * mu_i + LN_EPS);
    float mu_h = rr.z * (1.f / G_);
    float rstd_h = rsqrtf(rr.w * (1.f / G_) - mu_h * mu_h + LN_EPS);

    const float4* lniw4 = reinterpret_cast<const float4*>(lniw);
    const float4* lnib4 = reinterpret_cast<const float4*>(lnib);
    const float4* lnhw4 = reinterpret_cast<const float4*>(lnhw);
    const float4* lnhb4 = reinterpret_cast<const float4*>(lnhb);

    float4 gi_v[4], gh_v[4], wi_v[4], bi_v[4], wh_v[4], bh_v[4];
    #pragma unroll
    for (int g = 0; g < 4; g++) {
        int n = tid + g * 256;
        gi_v[g] = s_ig[n];  gh_v[g] = s_hg[n];
        wi_v[g] = lniw4[n]; bi_v[g] = lnib4[n];
        wh_v[g] = lnhw4[n]; bh_v[g] = lnhb4[n];
    }

    float cc[4], oo[4];
    float cs = 0.f, cq = 0.f;
    #pragma unroll
    for (int c = 0; c < 4; c++) {
        #define GVAL(g) ((f4c(gi_v[g],c) - mu_i) * rstd_i * f4c(wi_v[g],c) + f4c(bi_v[g],c) + \
                         (f4c(gh_v[g],c) - mu_h) * rstd_h * f4c(wh_v[g],c) + f4c(bh_v[g],c))
        float gi = sigm(GVAL(0));
        float gf = sigm(GVAL(1));
        float gg = tanh_fast(GVAL(2));
        float go = sigm(GVAL(3));
        #undef GVAL
        float c_ = gf * f4c(cxv, c) + gi * gg;
        cc[c] = c_; oo[c] = go;
        cs += c_; cq += c_ * c_;
    }
    float2 rc = block_reduce2(cs, cq, red);
    float mu_c = rc.x * (1.f / H_);
    float rstd_c = rsqrtf(rc.y * (1.f / H_) - mu_c * mu_c + LN_EPS);

    float4 wcv = reinterpret_cast<const float4*>(lncw)[tid];
    float4 bcv = reinterpret_cast<const float4*>(lncb)[tid];
    float4 hyv, cyv;
    #pragma unroll
    for (int c = 0; c < 4; c++) {
        float cy = (cc[c] - mu_c) * rstd_c * f4c(wcv, c) + f4c(bcv, c);
        reinterpret_cast<float*>(&cyv)[c] = cy;
        reinterpret_cast<float*>(&hyv)[c] = oo[c] * tanh_fast(cy);
    }
    float4* out4 = reinterpret_cast<float4*>(out);
    out4[(size_t)r * 256 + tid] = hyv;
    out4[(size_t)B_ * 256 + (size_t)r * 256 + tid] = cyv;
}

// =====================================================================
extern "C" void kernel_launch(void* const* d_in, const int* in_sizes, int n_in,
                              void* d_out, int out_size)
{
    const float* input_ = (const float*)d_in[0];
    const float* hx     = (const float*)d_in[1];
    const float* cx     = (const float*)d_in[2];
    const float* topic  = (const float*)d_in[3];
    const float* w_ih_a = (const float*)d_in[4];
    const float* w_ih_b = (const float*)d_in[5];
    const float* w_ih_c = (const float*)d_in[6];
    const float* w_hh_a = (const float*)d_in[7];
    const float* w_hh_b = (const float*)d_in[8];
    const float* w_hh_c = (const float*)d_in[9];
    const float* th_ih_w = (const float*)d_in[10];
    const float* th_ih_b = (const float*)d_in[11];
    const float* th_hh_w = (const float*)d_in[12];
    const float* th_hh_b = (const float*)d_in[13];
    const float* ln_i_w  = (const float*)d_in[14];
    const float* ln_i_b  = (const float*)d_in[15];
    const float* ln_h_w  = (const float*)d_in[16];
    const float* ln_h_b  = (const float*)d_in[17];
    const float* ln_c_w  = (const float*)d_in[18];
    const float* ln_c_b  = (const float*)d_in[19];

    cudaFuncSetAttribute(stage1_mma_kernel,
                         cudaFuncAttributeMaxDynamicSharedMemorySize, S1_TOT);
    cudaFuncSetAttribute(stage2_mma_kernel,
                         cudaFuncAttributeMaxDynamicSharedMemorySize, S2_TOT);

    convert_all_kernel<<<CV_TOT / 256, 256>>>(
        input_, hx, w_ih_c, w_hh_c, w_ih_a, w_hh_a);

    stage1_mma_kernel<<<dim3(B_ / 64, 2), 256, S1_TOT>>>(
        topic, th_ih_w, th_ih_b, w_ih_b, th_hh_w, th_hh_b, w_hh_b);

    stage2_mma_kernel<<<dim3(G_ / 256 / NCT, B_ / 128, 2), 256, S2_TOT>>>();

    stage3_kernel<<<B_, 256>>>(cx, ln_i_w, ln_i_b, ln_h_w, ln_h_b,
                               ln_c_w, ln_c_b, (float*)d_out);
}

// round 14
// speedup vs baseline: 2.3234x; 1.1152x over previous
#include <cuda_runtime.h>
#include <cuda_bf16.h>
#include <cuda_fp16.h>
#include <math.h>
#include <stdint.h>

#define B_   4096
#define IN_  1024
#define H_   1024
#define F_   128
#define T_   3
#define G_   4096      // 4*H
#define LN_EPS 1e-5f

// ---------------- scratch (no allocations allowed) ----------------
__device__ __align__(16) __half g_xh[2][(size_t)B_ * IN_];   // x/hx fp16
__device__ __align__(16) __half g_wch[2][(size_t)F_ * IN_];  // wc fp16
__device__ __align__(16) __half g_a2h[2][(size_t)B_ * F_];   // stage1 out (fp16)
__device__ __align__(16) __half g_w2h[2][(size_t)G_ * F_];   // w_*_a  (fp16)
__device__ __align__(16) __half g_gates[2][(size_t)B_ * G_]; // ig / hg (fp16)

__device__ __forceinline__ uint32_t smem_u32(const void* p) {
    uint32_t a;
    asm("{ .reg .u64 t; cvta.to.shared.u64 t, %1; cvt.u32.u64 %0, t; }"
        : "=r"(a) : "l"(p));
    return a;
}
__device__ __forceinline__ void cp16(uint32_t dst, const void* src) {
    asm volatile("cp.async.cg.shared.global [%0], [%1], 16;"
                 :: "r"(dst), "l"(src));
}
#define CP_COMMIT()  asm volatile("cp.async.commit_group;")
#define CP_WAIT(n)   asm volatile("cp.async.wait_group %0;" :: "n"(n))

__device__ __forceinline__ float f4c(const float4& v, int c) {
    return reinterpret_cast<const float*>(&v)[c];
}
__device__ __forceinline__ float fexp2(float x) {
    float y; asm("ex2.approx.f32 %0, %1;" : "=f"(y) : "f"(x)); return y;
}
__device__ __forceinline__ float frcp(float x) {
    float y; asm("rcp.approx.f32 %0, %1;" : "=f"(y) : "f"(x)); return y;
}
__device__ __forceinline__ float sigm(float x) {
    return frcp(1.f + fexp2(-1.4426950408889634f * x));
}
__device__ __forceinline__ float tanh_fast(float x) {
    return 2.f * frcp(1.f + fexp2(-2.8853900817779268f * x)) - 1.f;
}

// =====================================================================
// convert_all: one flat fp32 -> fp16 pass over all 6 segments.
// =====================================================================
#define CV_X   (B_ * IN_ / 4)
#define CV_WC  (F_ * IN_ / 4)
#define CV_WA  (G_ * F_ / 4)
#define CV_TOT (2 * CV_X + 2 * CV_WC + 2 * CV_WA)   // 2424832 = 9472*256

__global__ __launch_bounds__(256) void convert_all_kernel(
    const float* __restrict__ xi, const float* __restrict__ xh,
    const float* __restrict__ wci, const float* __restrict__ wch,
    const float* __restrict__ wai, const float* __restrict__ wah)
{
    int idx = blockIdx.x * 256 + threadIdx.x;
    const float* src;
    __half* dst;
    if (idx < 2 * CV_X) {
        int p = idx >= CV_X; int off = idx - p * CV_X;
        src = (p ? xh : xi) + off * 4;  dst = g_xh[p] + off * 4;
    } else if (idx < 2 * CV_X + 2 * CV_WC) {
        idx -= 2 * CV_X;
        int p = idx >= CV_WC; int off = idx - p * CV_WC;
        src = (p ? wch : wci) + off * 4;  dst = g_wch[p] + off * 4;
    } else {
        idx -= 2 * CV_X + 2 * CV_WC;
        int p = idx >= CV_WA; int off = idx - p * CV_WA;
        src = (p ? wah : wai) + off * 4;  dst = g_w2h[p] + off * 4;
    }
    float4 v = *reinterpret_cast<const float4*>(src);
    __half2* d = reinterpret_cast<__half2*>(dst);
    d[0] = __floats2half2_rn(v.x, v.y);
    d[1] = __floats2half2_rn(v.z, v.w);
}

// =====================================================================
// Stage 1 (mma, fp16): C[b,f] = (x @ wc^T)[b,f] * scale(b,f).
// Tile M=64 x N=128, K=1024 chunks of 128 (x8), cp.async double buffer.
// grid (B_/64, 2) = 128 CTAs, 256 thr (8 warps: 2(M) x 4(N)).
// =====================================================================
#define S1_LD   136
#define S1_ABUF (64 * S1_LD)
#define S1_WBUF (128 * S1_LD)
#define S1_TOT  ((2 * S1_ABUF + 2 * S1_WBUF) * 2)   // 104448

__device__ __forceinline__ void s1_load_chunk(
    int j, uint32_t aBase, uint32_t wBase,
    const __half* __restrict__ A, const __half* __restrict__ W,
    int row0, int tid)
{
    #pragma unroll
    for (int it = 0; it < 4; it++) {
        int idx = tid + it * 256;
        int r = idx >> 4, c = idx & 15;
        cp16(aBase + (uint32_t)(r * S1_LD + c * 8) * 2,
             A + (size_t)(row0 + r) * IN_ + j * 128 + c * 8);
    }
    #pragma unroll
    for (int it = 0; it < 8; it++) {
        int idx = tid + it * 256;
        int r = idx >> 4, c = idx & 15;
        cp16(wBase + (uint32_t)(r * S1_LD + c * 8) * 2,
             W + (size_t)r * IN_ + j * 128 + c * 8);
    }
}

__global__ __launch_bounds__(256) void stage1_mma_kernel(
    const float* __restrict__ topic,
    const float* __restrict__ thw_i, const float* __restrict__ thb_i,
    const float* __restrict__ wb_i,
    const float* __restrict__ thw_h, const float* __restrict__ thb_h,
    const float* __restrict__ wb_h)
{
    extern __shared__ __half sm1[];
    __shared__ float sTheta[64][4];

    const int tid  = threadIdx.x;
    const int lane = tid & 31;
    const int wid  = tid >> 5;
    const int path = blockIdx.y;
    const int row0 = blockIdx.x * 64;

    const __half* __restrict__ A = g_xh[path];
    const __half* __restrict__ W = g_wch[path];
    const float* __restrict__ thw = path ? thw_h : thw_i;
    const float* __restrict__ thb = path ? thb_h : thb_i;
    const float* __restrict__ wb  = path ? wb_h  : wb_i;
    __half* __restrict__ outp = g_a2h[path];

    if (tid < 192) {
        int r = tid / 3, t = tid - r * 3;
        const float* tp = topic + (size_t)(row0 + r) * T_;
        sTheta[r][t] = thb[t] + tp[0]*thw[t*T_+0] + tp[1]*thw[t*T_+1] + tp[2]*thw[t*T_+2];
    }

    uint32_t aB[2] = { smem_u32(sm1), smem_u32(sm1 + S1_ABUF) };
    uint32_t wB[2] = { smem_u32(sm1 + 2 * S1_ABUF),
                       smem_u32(sm1 + 2 * S1_ABUF + S1_WBUF) };

    s1_load_chunk(0, aB[0], wB[0], A, W, row0, tid);
    CP_COMMIT();

    const int wm = (wid & 1) * 32;
    const int wn = (wid >> 1) * 32;
    const int lr  = lane & 7;
    const int seg = lane >> 3;
    const int l16 = lane & 15;

    float acc[2][4][4];
    #pragma unroll
    for (int mt = 0; mt < 2; mt++)
        #pragma unroll
        for (int nt = 0; nt < 4; nt++)
            #pragma unroll
            for (int j = 0; j < 4; j++) acc[mt][nt][j] = 0.f;

    for (int j = 0; j < 8; j++) {
        const int bf = j & 1;
        if (j < 7) {
            s1_load_chunk(j + 1, aB[(j+1)&1], wB[(j+1)&1], A, W, row0, tid);
            CP_COMMIT();
            CP_WAIT(1);
        } else {
            CP_WAIT(0);
        }
        __syncthreads();

        #pragma unroll
        for (int s = 0; s < 8; s++) {
            const int acol = s * 16 + ((seg >> 1) << 3);
            const int bcol = s * 16 + ((l16 >> 3) << 3);

            uint32_t a[2][4];
            #pragma unroll
            for (int mt = 0; mt < 2; mt++) {
                int arow = wm + mt * 16 + lr + ((seg & 1) << 3);
                uint32_t addr = aB[bf] + (uint32_t)(arow * S1_LD + acol) * 2;
                asm volatile("ldmatrix.sync.aligned.m8n8.x4.shared.b16 {%0,%1,%2,%3}, [%4];"
                             : "=r"(a[mt][0]), "=r"(a[mt][1]),
                               "=r"(a[mt][2]), "=r"(a[mt][3])
                             : "r"(addr));
            }
            uint32_t b[4][2];
            #pragma unroll
            for (int nt = 0; nt < 4; nt++) {
                int brow = wn + nt * 8 + (l16 & 7);
                uint32_t addr = wB[bf] + (uint32_t)(brow * S1_LD + bcol) * 2;
                asm volatile("ldmatrix.sync.aligned.m8n8.x2.shared.b16 {%0,%1}, [%2];"
                             : "=r"(b[nt][0]), "=r"(b[nt][1])
                             : "r"(addr));
            }
            #pragma unroll
            for (int mt = 0; mt < 2; mt++)
                #pragma unroll
                for (int nt = 0; nt < 4; nt++) {
                    asm volatile(
                        "mma.sync.aligned.m16n8k16.row.col.f32.f16.f16.f32 "
                        "{%0,%1,%2,%3}, {%4,%5,%6,%7}, {%8,%9}, {%0,%1,%2,%3};"
                        : "+f"(acc[mt][nt][0]), "+f"(acc[mt][nt][1]),
                          "+f"(acc[mt][nt][2]), "+f"(acc[mt][nt][3])
                        : "r"(a[mt][0]), "r"(a[mt][1]), "r"(a[mt][2]), "r"(a[mt][3]),
                          "r"(b[nt][0]), "r"(b[nt][1]));
                }
        }
        __syncthreads();
    }

    const int em = lane >> 2;
    const int en = (lane & 3) * 2;
    #pragma unroll
    for (int nt = 0; nt < 4; nt++) {
        const int n = wn + nt * 8 + en;
        float w0a = wb[n*T_+0],     w1a = wb[n*T_+1],     w2a = wb[n*T_+2];
        float w0b = wb[(n+1)*T_+0], w1b = wb[(n+1)*T_+1], w2b = wb[(n+1)*T_+2];
        #pragma unroll
        for (int mt = 0; mt < 2; mt++) {
            #pragma unroll
            for (int half = 0; half < 2; half++) {
                int m = wm + mt * 16 + em + half * 8;
                float th0 = sTheta[m][0], th1 = sTheta[m][1], th2 = sTheta[m][2];
                float sc0 = th0*w0a + th1*w1a + th2*w2a;
                float sc1 = th0*w0b + th1*w1b + th2*w2b;
                float v0 = acc[mt][nt][half*2 + 0] * sc0;
                float v1 = acc[mt][nt][half*2 + 1] * sc1;
                *reinterpret_cast<__half2*>(&outp[(size_t)(row0 + m) * F_ + n]) =
                    __floats2half2_rn(v0, v1);
            }
        }
    }
}

// =====================================================================
// Stage 2: fp16 mma GEMM, K=128. A-resident, W-streamed.
// CTA tile 128 x 256, warp tile 64x64 (8 warps 2(M) x 4(N)).
// NCT=4 col tiles of 256; W double-buffered cp.async.
// grid = (4, 32, 2) = 256 CTAs, 256 thr. smem 174080 B.
// =====================================================================
#define S2_LD    136
#define S2_ATILE (128 * S2_LD)
#define S2_WTILE (256 * S2_LD)
#define S2_TOT   ((S2_ATILE + 2 * S2_WTILE) * 2)    // 174080
#define NCT      4

__device__ __forceinline__ void s2_load_w(
    const __half* __restrict__ W, int col0, uint32_t base, int tid)
{
    #pragma unroll
    for (int it = 0; it < 16; it++) {
        int idx = tid + it * 256;
        int r = idx >> 4, c = idx & 15;
        cp16(base + (uint32_t)(r * S2_LD + c * 8) * 2,
             W + (size_t)(col0 + r) * F_ + c * 8);
    }
}

__global__ __launch_bounds__(256, 1) void stage2_mma_kernel()
{
    extern __shared__ __half sm2[];

    const int tid  = threadIdx.x;
    const int lane = tid & 31;
    const int wid  = tid >> 5;
    const int path = blockIdx.z;
    const int row0 = blockIdx.y * 128;
    const int ct0  = blockIdx.x * NCT;

    const __half* __restrict__ A = g_a2h[path];
    const __half* __restrict__ W = g_w2h[path];
    __half* __restrict__ O = g_gates[path];

    const uint32_t as_base = smem_u32(sm2);
    uint32_t wBuf[2] = { smem_u32(sm2 + S2_ATILE),
                         smem_u32(sm2 + S2_ATILE + S2_WTILE) };

    #pragma unroll
    for (int it = 0; it < 8; it++) {
        int idx = tid + it * 256;
        int r = idx >> 4, c = idx & 15;
        cp16(as_base + (uint32_t)(r * S2_LD + c * 8) * 2,
             A + (size_t)(row0 + r) * F_ + c * 8);
    }
    s2_load_w(W, ct0 * 256, wBuf[0], tid);
    CP_COMMIT();

    const int wm = (wid & 1) * 64;
    const int wn = (wid >> 1) * 64;
    const int lr  = lane & 7;
    const int seg = lane >> 3;
    const int em = lane >> 2;
    const int en = (lane & 3) * 2;

    for (int it = 0; it < NCT; it++) {
        const int buf = it & 1;
        if (it + 1 < NCT) {
            s2_load_w(W, (ct0 + it + 1) * 256, wBuf[(it + 1) & 1], tid);
            CP_COMMIT();
            CP_WAIT(1);
        } else {
            CP_WAIT(0);
        }
        __syncthreads();

        float acc[4][8][4];
        #pragma unroll
        for (int mt = 0; mt < 4; mt++)
            #pragma unroll
            for (int nt = 0; nt < 8; nt++)
                #pragma unroll
                for (int j = 0; j < 4; j++) acc[mt][nt][j] = 0.f;

        const uint32_t bs_base = wBuf[buf];
        #pragma unroll
        for (int s = 0; s < 8; s++) {
            const int acol = s * 16 + ((seg >> 1) << 3);

            uint32_t a[4][4];
            #pragma unroll
            for (int mt = 0; mt < 4; mt++) {
                int arow = wm + mt * 16 + lr + ((seg & 1) << 3);
                uint32_t addr = as_base + (uint32_t)(arow * S2_LD + acol) * 2;
                asm volatile("ldmatrix.sync.aligned.m8n8.x4.shared.b16 {%0,%1,%2,%3}, [%4];"
                             : "=r"(a[mt][0]), "=r"(a[mt][1]),
                               "=r"(a[mt][2]), "=r"(a[mt][3])
                             : "r"(addr));
            }
            uint32_t b[4][4];
            #pragma unroll
            for (int ntp = 0; ntp < 4; ntp++) {
                int brow = wn + ntp * 16 + ((seg >> 1) << 3) + lr;
                int bcol = s * 16 + ((seg & 1) << 3);
                uint32_t addr = bs_base + (uint32_t)(brow * S2_LD + bcol) * 2;
                asm volatile("ldmatrix.sync.aligned.m8n8.x4.shared.b16 {%0,%1,%2,%3}, [%4];"
                             : "=r"(b[ntp][0]), "=r"(b[ntp][1]),
                               "=r"(b[ntp][2]), "=r"(b[ntp][3])
                             : "r"(addr));
            }
            #pragma unroll
            for (int mt = 0; mt < 4; mt++)
                #pragma unroll
                for (int nt = 0; nt < 8; nt++) {
                    const uint32_t b0 = b[nt >> 1][(nt & 1) * 2 + 0];
                    const uint32_t b1 = b[nt >> 1][(nt & 1) * 2 + 1];
                    asm volatile(
                        "mma.sync.aligned.m16n8k16.row.col.f32.f16.f16.f32 "
                        "{%0,%1,%2,%3}, {%4,%5,%6,%7}, {%8,%9}, {%0,%1,%2,%3};"
                        : "+f"(acc[mt][nt][0]), "+f"(acc[mt][nt][1]),
                          "+f"(acc[mt][nt][2]), "+f"(acc[mt][nt][3])
                        : "r"(a[mt][0]), "r"(a[mt][1]), "r"(a[mt][2]), "r"(a[mt][3]),
                          "r"(b0), "r"(b1));
                }
        }

        const int col0 = (ct0 + it) * 256;
        #pragma unroll
        for (int mt = 0; mt < 4; mt++) {
            #pragma unroll
            for (int nt = 0; nt < 8; nt++) {
                int m = row0 + wm + mt * 16 + em;
                int n = col0 + wn + nt * 8 + en;
                *reinterpret_cast<__half2*>(&O[(size_t)m * G_ + n]) =
                    __floats2half2_rn(acc[mt][nt][0], acc[mt][nt][1]);
                *reinterpret_cast<__half2*>(&O[(size_t)(m + 8) * G_ + n]) =
                    __floats2half2_rn(acc[mt][nt][2], acc[mt][nt][3]);
            }
        }
        __syncthreads();
    }
}

// =====================================================================
// Stage 3: register-resident. Thread tid owns hidden units tid*4..+3;
// loads its 4 gate-groups from ig and hg directly (uint2, coalesced),
// reduces LN stats straight from registers. No smem staging.
// =====================================================================
__device__ __forceinline__ float4 block_reduce4(
    float a, float b, float c, float d, float* red)
{
    __syncthreads();
    #pragma unroll
    for (int o = 16; o > 0; o >>= 1) {
        a += __shfl_xor_sync(0xffffffffu, a, o);
        b += __shfl_xor_sync(0xffffffffu, b, o);
        c += __shfl_xor_sync(0xffffffffu, c, o);
        d += __shfl_xor_sync(0xffffffffu, d, o);
    }
    int w = threadIdx.x >> 5, l = threadIdx.x & 31;
    if (l == 0) { red[w] = a; red[8+w] = b; red[16+w] = c; red[24+w] = d; }
    __syncthreads();
    if (w == 0) {
        a = (l < 8) ? red[l]      : 0.f;
        b = (l < 8) ? red[8 + l]  : 0.f;
        c = (l < 8) ? red[16 + l] : 0.f;
        d = (l < 8) ? red[24 + l] : 0.f;
        #pragma unroll
        for (int o = 4; o > 0; o >>= 1) {
            a += __shfl_xor_sync(0xffffffffu, a, o);
            b += __shfl_xor_sync(0xffffffffu, b, o);
            c += __shfl_xor_sync(0xffffffffu, c, o);
            d += __shfl_xor_sync(0xffffffffu, d, o);
        }
        if (l == 0) { red[0] = a; red[1] = b; red[2] = c; red[3] = d; }
    }
    __syncthreads();
    return make_float4(red[0], red[1], red[2], red[3]);
}

__device__ __forceinline__ float2 block_reduce2(float s, float q, float* red)
{
    __syncthreads();
    #pragma unroll
    for (int o = 16; o > 0; o >>= 1) {
        s += __shfl_xor_sync(0xffffffffu, s, o);
        q += __shfl_xor_sync(0xffffffffu, q, o);
    }
    int w = threadIdx.x >> 5, l = threadIdx.x & 31;
    if (l == 0) { red[w] = s; red[8 + w] = q; }
    __syncthreads();
    if (w == 0) {
        s = (l < 8) ? red[l] : 0.f;
        q = (l < 8) ? red[8 + l] : 0.f;
        #pragma unroll
        for (int o = 4; o > 0; o >>= 1) {
            s += __shfl_xor_sync(0xffffffffu, s, o);
            q += __shfl_xor_sync(0xffffffffu, q, o);
        }
        if (l == 0) { red[0] = s; red[1] = q; }
    }
    __syncthreads();
    return make_float2(red[0], red[1]);
}

__device__ __forceinline__ float4 unpack4(const uint2& u)
{
    float2 f0 = __half22float2(*reinterpret_cast<const __half2*>(&u.x));
    float2 f1 = __half22float2(*reinterpret_cast<const __half2*>(&u.y));
    return make_float4(f0.x, f0.y, f1.x, f1.y);
}

__global__ __launch_bounds__(256) void stage3_kernel(
    const float* __restrict__ cx,
    const float* __restrict__ lniw, const float* __restrict__ lnib,
    const float* __restrict__ lnhw, const float* __restrict__ lnhb,
    const float* __restrict__ lncw, const float* __restrict__ lncb,
    float* __restrict__ out)
{
    __shared__ float red[32];

    const int r   = blockIdx.x;
    const int tid = threadIdx.x;
    const int j   = tid * 4;               // hidden base this thread owns
    const __half* __restrict__ ig = g_gates[0] + (size_t)r * G_;
    const __half* __restrict__ hg = g_gates[1] + (size_t)r * G_;

    // front-batched loads: 8 x LDG.64 + 1 x LDG.128 (MLP 9)
    uint2 uig[4], uhg[4];
    #pragma unroll
    for (int g = 0; g < 4; g++) {
        uig[g] = *reinterpret_cast<const uint2*>(ig + g * H_ + j);
        uhg[g] = *reinterpret_cast<const uint2*>(hg + g * H_ + j);
    }
    float4 cxv = reinterpret_cast<const float4*>(cx + (size_t)r * H_)[tid];

    float4 gi_v[4], gh_v[4];
    float si = 0.f, qi = 0.f, sh = 0.f, qh = 0.f;
    #pragma unroll
    for (int g = 0; g < 4; g++) {
        gi_v[g] = unpack4(uig[g]);
        gh_v[g] = unpack4(uhg[g]);
        si += gi_v[g].x + gi_v[g].y + gi_v[g].z + gi_v[g].w;
        qi += gi_v[g].x*gi_v[g].x + gi_v[g].y*gi_v[g].y
            + gi_v[g].z*gi_v[g].z + gi_v[g].w*gi_v[g].w;
        sh += gh_v[g].x + gh_v[g].y + gh_v[g].z + gh_v[g].w;
        qh += gh_v[g].x*gh_v[g].x + gh_v[g].y*gh_v[g].y
            + gh_v[g].z*gh_v[g].z + gh_v[g].w*gh_v[g].w;
    }
    float4 rr = block_reduce4(si, qi, sh, qh, red);
    float mu_i = rr.x * (1.f / G_);
    float rstd_i = rsqrtf(rr.y * (1.f / G_) - mu_i * mu_i + LN_EPS);
    float mu_h = rr.z * (1.f / G_);
    float rstd_h = rsqrtf(rr.w * (1.f / G_) - mu_h * mu_h + LN_EPS);

    const float4* lniw4 = reinterpret_cast<const float4*>(lniw);
    const float4* lnib4 = reinterpret_cast<const float4*>(lnib);
    const float4* lnhw4 = reinterpret_cast<const float4*>(lnhw);
    const float4* lnhb4 = reinterpret_cast<const float4*>(lnhb);

    float4 wi_v[4], bi_v[4], wh_v[4], bh_v[4];
    #pragma unroll
    for (int g = 0; g < 4; g++) {
        int n = g * 256 + tid;             // float4 index of (g*1024 + j)
        wi_v[g] = lniw4[n]; bi_v[g] = lnib4[n];
        wh_v[g] = lnhw4[n]; bh_v[g] = lnhb4[n];
    }

    float cc[4], oo[4];
    float cs = 0.f, cq = 0.f;
    #pragma unroll
    for (int c = 0; c < 4; c++) {
        #define GVAL(g) ((f4c(gi_v[g],c) - mu_i) * rstd_i * f4c(wi_v[g],c) + f4c(bi_v[g],c) + \
                         (f4c(gh_v[g],c) - mu_h) * rstd_h * f4c(wh_v[g],c) + f4c(bh_v[g],c))
        float gi = sigm(GVAL(0));
        float gf = sigm(GVAL(1));
        float gg = tanh_fast(GVAL(2));
        float go = sigm(GVAL(3));
        #undef GVAL
        float c_ = gf * f4c(cxv, c) + gi * gg;
        cc[c] = c_; oo[c] = go;
        cs += c_; cq += c_ * c_;
    }
    float2 rc = block_reduce2(cs, cq, red);
    float mu_c = rc.x * (1.f / H_);
    float rstd_c = rsqrtf(rc.y * (1.f / H_) - mu_c * mu_c + LN_EPS);

    float4 wcv = reinterpret_cast<const float4*>(lncw)[tid];
    float4 bcv = reinterpret_cast<const float4*>(lncb)[tid];
    float4 hyv, cyv;
    #pragma unroll
    for (int c = 0; c < 4; c++) {
        float cy = (cc[c] - mu_c) * rstd_c * f4c(wcv, c) + f4c(bcv, c);
        reinterpret_cast<float*>(&cyv)[c] = cy;
        reinterpret_cast<float*>(&hyv)[c] = oo[c] * tanh_fast(cy);
    }
    float4* out4 = reinterpret_cast<float4*>(out);
    out4[(size_t)r * 256 + tid] = hyv;
    out4[(size_t)B_ * 256 + (size_t)r * 256 + tid] = cyv;
}

// =====================================================================
extern "C" void kernel_launch(void* const* d_in, const int* in_sizes, int n_in,
                              void* d_out, int out_size)
{
    const float* input_ = (const float*)d_in[0];
    const float* hx     = (const float*)d_in[1];
    const float* cx     = (const float*)d_in[2];
    const float* topic  = (const float*)d_in[3];
    const float* w_ih_a = (const float*)d_in[4];
    const float* w_ih_b = (const float*)d_in[5];
    const float* w_ih_c = (const float*)d_in[6];
    const float* w_hh_a = (const float*)d_in[7];
    const float* w_hh_b = (const float*)d_in[8];
    const float* w_hh_c = (const float*)d_in[9];
    const float* th_ih_w = (const float*)d_in[10];
    const float* th_ih_b = (const float*)d_in[11];
    const float* th_hh_w = (const float*)d_in[12];
    const float* th_hh_b = (const float*)d_in[13];
    const float* ln_i_w  = (const float*)d_in[14];
    const float* ln_i_b  = (const float*)d_in[15];
    const float* ln_h_w  = (const float*)d_in[16];
    const float* ln_h_b  = (const float*)d_in[17];
    const float* ln_c_w  = (const float*)d_in[18];
    const float* ln_c_b  = (const float*)d_in[19];

    cudaFuncSetAttribute(stage1_mma_kernel,
                         cudaFuncAttributeMaxDynamicSharedMemorySize, S1_TOT);
    cudaFuncSetAttribute(stage2_mma_kernel,
                         cudaFuncAttributeMaxDynamicSharedMemorySize, S2_TOT);

    convert_all_kernel<<<CV_TOT / 256, 256>>>(
        input_, hx, w_ih_c, w_hh_c, w_ih_a, w_hh_a);

    stage1_mma_kernel<<<dim3(B_ / 64, 2), 256, S1_TOT>>>(
        topic, th_ih_w, th_ih_b, w_ih_b, th_hh_w, th_hh_b, w_hh_b);

    stage2_mma_kernel<<<dim3(G_ / 256 / NCT, B_ / 128, 2), 256, S2_TOT>>>();

    stage3_kernel<<<B_, 256>>>(cx, ln_i_w, ln_i_b, ln_h_w, ln_h_b,
                               ln_c_w, ln_c_b, (float*)d_out);
}

// round 15
// speedup vs baseline: 2.3694x; 1.0198x over previous
#include <cuda_runtime.h>
#include <cuda_bf16.h>
#include <cuda_fp16.h>
#include <math.h>
#include <stdint.h>

#define B_   4096
#define IN_  1024
#define H_   1024
#define F_   128
#define T_   3
#define G_   4096      // 4*H
#define LN_EPS 1e-5f

// ---------------- scratch (no allocations allowed) ----------------
__device__ __align__(16) __half g_wch[2][(size_t)F_ * IN_];  // wc fp16
__device__ __align__(16) __half g_a2h[2][(size_t)B_ * F_];   // stage1 out (fp16)
__device__ __align__(16) __half g_w2h[2][(size_t)G_ * F_];   // w_*_a  (fp16)
__device__ __align__(16) __half g_gates[2][(size_t)B_ * G_]; // ig / hg (fp16)

__device__ __forceinline__ uint32_t smem_u32(const void* p) {
    uint32_t a;
    asm("{ .reg .u64 t; cvta.to.shared.u64 t, %1; cvt.u32.u64 %0, t; }"
        : "=r"(a) : "l"(p));
    return a;
}
__device__ __forceinline__ void cp16(uint32_t dst, const void* src) {
    asm volatile("cp.async.cg.shared.global [%0], [%1], 16;"
                 :: "r"(dst), "l"(src));
}
#define CP_COMMIT()  asm volatile("cp.async.commit_group;")
#define CP_WAIT(n)   asm volatile("cp.async.wait_group %0;" :: "n"(n))

__device__ __forceinline__ float f4c(const float4& v, int c) {
    return reinterpret_cast<const float*>(&v)[c];
}
__device__ __forceinline__ float fexp2(float x) {
    float y; asm("ex2.approx.f32 %0, %1;" : "=f"(y) : "f"(x)); return y;
}
__device__ __forceinline__ float frcp(float x) {
    float y; asm("rcp.approx.f32 %0, %1;" : "=f"(y) : "f"(x)); return y;
}
__device__ __forceinline__ float sigm(float x) {
    return frcp(1.f + fexp2(-1.4426950408889634f * x));
}
__device__ __forceinline__ float tanh_fast(float x) {
    return 2.f * frcp(1.f + fexp2(-2.8853900817779268f * x)) - 1.f;
}

// =====================================================================
// convert_all: flat fp32 -> fp16 for wc + wa only (x/hx folded into s1).
// grid 1280 x 256.
// =====================================================================
#define CV_WC  (F_ * IN_ / 4)          // 32768
#define CV_WA  (G_ * F_ / 4)           // 131072
#define CV_TOT (2 * CV_WC + 2 * CV_WA) // 327680 = 1280*256

__global__ __launch_bounds__(256) void convert_all_kernel(
    const float* __restrict__ wci, const float* __restrict__ wch,
    const float* __restrict__ wai, const float* __restrict__ wah)
{
    int idx = blockIdx.x * 256 + threadIdx.x;
    const float* src;
    __half* dst;
    if (idx < 2 * CV_WC) {
        int p = idx >= CV_WC; int off = idx - p * CV_WC;
        src = (p ? wch : wci) + off * 4;  dst = g_wch[p] + off * 4;
    } else {
        idx -= 2 * CV_WC;
        int p = idx >= CV_WA; int off = idx - p * CV_WA;
        src = (p ? wah : wai) + off * 4;  dst = g_w2h[p] + off * 4;
    }
    float4 v = *reinterpret_cast<const float4*>(src);
    __half2* d = reinterpret_cast<__half2*>(dst);
    d[0] = __floats2half2_rn(v.x, v.y);
    d[1] = __floats2half2_rn(v.z, v.w);
}

// =====================================================================
// Stage 1 (mma, fp16): C[b,f] = (x @ wc^T)[b,f] * scale(b,f).
// A (x/hx) read as fp32 from gmem, converted to fp16 on smem store
// (register-prefetched one chunk ahead). W double-buffered cp.async.
// Tile M=64 x N=128, K=1024 chunks of 128 (x8).
// grid (B_/64, 2) = 128 CTAs, 256 thr (8 warps: 2(M) x 4(N)).
// smem: A 64x136 (single) + 2x W 128x136 = 87040 bytes.
// =====================================================================
#define S1_LD   136
#define S1_ABUF (64 * S1_LD)
#define S1_WBUF (128 * S1_LD)
#define S1_TOT  ((S1_ABUF + 2 * S1_WBUF) * 2)   // 87040

__device__ __forceinline__ void s1_lda(
    float4* areg, const float* __restrict__ Xf, int row0, int j, int tid)
{
    int r = tid >> 2, q = tid & 3;
    const float4* src = reinterpret_cast<const float4*>(
        Xf + (size_t)(row0 + r) * IN_ + j * 128 + q * 32);
    #pragma unroll
    for (int i = 0; i < 8; i++) areg[i] = src[i];
}

__device__ __forceinline__ void s1_sta(
    const float4* areg, __half* As, int tid)
{
    int r = tid >> 2, q = tid & 3;
    __half2 tmp[16];
    #pragma unroll
    for (int i = 0; i < 8; i++) {
        tmp[2*i]   = __floats2half2_rn(areg[i].x, areg[i].y);
        tmp[2*i+1] = __floats2half2_rn(areg[i].z, areg[i].w);
    }
    uint4* dst = reinterpret_cast<uint4*>(As + r * S1_LD + q * 32);
    const uint4* s = reinterpret_cast<const uint4*>(tmp);
    #pragma unroll
    for (int i = 0; i < 4; i++) dst[i] = s[i];
}

__device__ __forceinline__ void s1_load_w(
    int j, uint32_t wBase, const __half* __restrict__ W, int tid)
{
    #pragma unroll
    for (int it = 0; it < 8; it++) {
        int idx = tid + it * 256;
        int r = idx >> 4, c = idx & 15;
        cp16(wBase + (uint32_t)(r * S1_LD + c * 8) * 2,
             W + (size_t)r * IN_ + j * 128 + c * 8);
    }
}

__global__ __launch_bounds__(256) void stage1_mma_kernel(
    const float* __restrict__ x_i, const float* __restrict__ x_h,
    const float* __restrict__ topic,
    const float* __restrict__ thw_i, const float* __restrict__ thb_i,
    const float* __restrict__ wb_i,
    const float* __restrict__ thw_h, const float* __restrict__ thb_h,
    const float* __restrict__ wb_h)
{
    extern __shared__ __half sm1[];
    __shared__ float sTheta[64][4];

    const int tid  = threadIdx.x;
    const int lane = tid & 31;
    const int wid  = tid >> 5;
    const int path = blockIdx.y;
    const int row0 = blockIdx.x * 64;

    const float* __restrict__ Xf = path ? x_h : x_i;
    const __half* __restrict__ W = g_wch[path];
    const float* __restrict__ thw = path ? thw_h : thw_i;
    const float* __restrict__ thb = path ? thb_h : thb_i;
    const float* __restrict__ wb  = path ? wb_h  : wb_i;
    __half* __restrict__ outp = g_a2h[path];

    if (tid < 192) {
        int r = tid / 3, t = tid - r * 3;
        const float* tp = topic + (size_t)(row0 + r) * T_;
        sTheta[r][t] = thb[t] + tp[0]*thw[t*T_+0] + tp[1]*thw[t*T_+1] + tp[2]*thw[t*T_+2];
    }

    __half* Asm = sm1;
    const uint32_t as_base = smem_u32(sm1);
    uint32_t wB[2] = { smem_u32(sm1 + S1_ABUF),
                       smem_u32(sm1 + S1_ABUF + S1_WBUF) };

    float4 areg[8];
    s1_lda(areg, Xf, row0, 0, tid);
    s1_load_w(0, wB[0], W, tid);
    CP_COMMIT();

    const int wm = (wid & 1) * 32;
    const int wn = (wid >> 1) * 32;
    const int lr  = lane & 7;
    const int seg = lane >> 3;
    const int l16 = lane & 15;

    float acc[2][4][4];
    #pragma unroll
    for (int mt = 0; mt < 2; mt++)
        #pragma unroll
        for (int nt = 0; nt < 4; nt++)
            #pragma unroll
            for (int j = 0; j < 4; j++) acc[mt][nt][j] = 0.f;

    for (int j = 0; j < 8; j++) {
        const int bf = j & 1;
        s1_sta(areg, Asm, tid);
        if (j < 7) {
            s1_lda(areg, Xf, row0, j + 1, tid);      // prefetch next A (fp32)
            s1_load_w(j + 1, wB[(j+1)&1], W, tid);
            CP_COMMIT();
            CP_WAIT(1);
        } else {
            CP_WAIT(0);
        }
        __syncthreads();

        #pragma unroll
        for (int s = 0; s < 8; s++) {
            const int acol = s * 16 + ((seg >> 1) << 3);
            const int bcol = s * 16 + ((l16 >> 3) << 3);

            uint32_t a[2][4];
            #pragma unroll
            for (int mt = 0; mt < 2; mt++) {
                int arow = wm + mt * 16 + lr + ((seg & 1) << 3);
                uint32_t addr = as_base + (uint32_t)(arow * S1_LD + acol) * 2;
                asm volatile("ldmatrix.sync.aligned.m8n8.x4.shared.b16 {%0,%1,%2,%3}, [%4];"
                             : "=r"(a[mt][0]), "=r"(a[mt][1]),
                               "=r"(a[mt][2]), "=r"(a[mt][3])
                             : "r"(addr));
            }
            uint32_t b[4][2];
            #pragma unroll
            for (int nt = 0; nt < 4; nt++) {
                int brow = wn + nt * 8 + (l16 & 7);
                uint32_t addr = wB[bf] + (uint32_t)(brow * S1_LD + bcol) * 2;
                asm volatile("ldmatrix.sync.aligned.m8n8.x2.shared.b16 {%0,%1}, [%2];"
                             : "=r"(b[nt][0]), "=r"(b[nt][1])
                             : "r"(addr));
            }
            #pragma unroll
            for (int mt = 0; mt < 2; mt++)
                #pragma unroll
                for (int nt = 0; nt < 4; nt++) {
                    asm volatile(
                        "mma.sync.aligned.m16n8k16.row.col.f32.f16.f16.f32 "
                        "{%0,%1,%2,%3}, {%4,%5,%6,%7}, {%8,%9}, {%0,%1,%2,%3};"
                        : "+f"(acc[mt][nt][0]), "+f"(acc[mt][nt][1]),
                          "+f"(acc[mt][nt][2]), "+f"(acc[mt][nt][3])
                        : "r"(a[mt][0]), "r"(a[mt][1]), "r"(a[mt][2]), "r"(a[mt][3]),
                          "r"(b[nt][0]), "r"(b[nt][1]));
                }
        }
        __syncthreads();
    }

    const int em = lane >> 2;
    const int en = (lane & 3) * 2;
    #pragma unroll
    for (int nt = 0; nt < 4; nt++) {
        const int n = wn + nt * 8 + en;
        float w0a = wb[n*T_+0],     w1a = wb[n*T_+1],     w2a = wb[n*T_+2];
        float w0b = wb[(n+1)*T_+0], w1b = wb[(n+1)*T_+1], w2b = wb[(n+1)*T_+2];
        #pragma unroll
        for (int mt = 0; mt < 2; mt++) {
            #pragma unroll
            for (int half = 0; half < 2; half++) {
                int m = wm + mt * 16 + em + half * 8;
                float th0 = sTheta[m][0], th1 = sTheta[m][1], th2 = sTheta[m][2];
                float sc0 = th0*w0a + th1*w1a + th2*w2a;
                float sc1 = th0*w0b + th1*w1b + th2*w2b;
                float v0 = acc[mt][nt][half*2 + 0] * sc0;
                float v1 = acc[mt][nt][half*2 + 1] * sc1;
                *reinterpret_cast<__half2*>(&outp[(size_t)(row0 + m) * F_ + n]) =
                    __floats2half2_rn(v0, v1);
            }
        }
    }
}

// =====================================================================
// Stage 2: fp16 mma GEMM, K=128. A-resident, W-streamed.
// CTA tile 128 x 256, warp tile 64x64 (8 warps 2(M) x 4(N)).
// NCT=4 col tiles of 256; W double-buffered cp.async.
// grid = (4, 32, 2) = 256 CTAs, 256 thr. smem 174080 B.
// =====================================================================
#define S2_LD    136
#define S2_ATILE (128 * S2_LD)
#define S2_WTILE (256 * S2_LD)
#define S2_TOT   ((S2_ATILE + 2 * S2_WTILE) * 2)    // 174080
#define NCT      4

__device__ __forceinline__ void s2_load_w(
    const __half* __restrict__ W, int col0, uint32_t base, int tid)
{
    #pragma unroll
    for (int it = 0; it < 16; it++) {
        int idx = tid + it * 256;
        int r = idx >> 4, c = idx & 15;
        cp16(base + (uint32_t)(r * S2_LD + c * 8) * 2,
             W + (size_t)(col0 + r) * F_ + c * 8);
    }
}

__global__ __launch_bounds__(256, 1) void stage2_mma_kernel()
{
    extern __shared__ __half sm2[];

    const int tid  = threadIdx.x;
    const int lane = tid & 31;
    const int wid  = tid >> 5;
    const int path = blockIdx.z;
    const int row0 = blockIdx.y * 128;
    const int ct0  = blockIdx.x * NCT;

    const __half* __restrict__ A = g_a2h[path];
    const __half* __restrict__ W = g_w2h[path];
    __half* __restrict__ O = g_gates[path];

    const uint32_t as_base = smem_u32(sm2);
    uint32_t wBuf[2] = { smem_u32(sm2 + S2_ATILE),
                         smem_u32(sm2 + S2_ATILE + S2_WTILE) };

    #pragma unroll
    for (int it = 0; it < 8; it++) {
        int idx = tid + it * 256;
        int r = idx >> 4, c = idx & 15;
        cp16(as_base + (uint32_t)(r * S2_LD + c * 8) * 2,
             A + (size_t)(row0 + r) * F_ + c * 8);
    }
    s2_load_w(W, ct0 * 256, wBuf[0], tid);
    CP_COMMIT();

    const int wm = (wid & 1) * 64;
    const int wn = (wid >> 1) * 64;
    const int lr  = lane & 7;
    const int seg = lane >> 3;
    const int em = lane >> 2;
    const int en = (lane & 3) * 2;

    for (int it = 0; it < NCT; it++) {
        const int buf = it & 1;
        if (it + 1 < NCT) {
            s2_load_w(W, (ct0 + it + 1) * 256, wBuf[(it + 1) & 1], tid);
            CP_COMMIT();
            CP_WAIT(1);
        } else {
            CP_WAIT(0);
        }
        __syncthreads();

        float acc[4][8][4];
        #pragma unroll
        for (int mt = 0; mt < 4; mt++)
            #pragma unroll
            for (int nt = 0; nt < 8; nt++)
                #pragma unroll
                for (int j = 0; j < 4; j++) acc[mt][nt][j] = 0.f;

        const uint32_t bs_base = wBuf[buf];
        #pragma unroll
        for (int s = 0; s < 8; s++) {
            const int acol = s * 16 + ((seg >> 1) << 3);

            uint32_t a[4][4];
            #pragma unroll
            for (int mt = 0; mt < 4; mt++) {
                int arow = wm + mt * 16 + lr + ((seg & 1) << 3);
                uint32_t addr = as_base + (uint32_t)(arow * S2_LD + acol) * 2;
                asm volatile("ldmatrix.sync.aligned.m8n8.x4.shared.b16 {%0,%1,%2,%3}, [%4];"
                             : "=r"(a[mt][0]), "=r"(a[mt][1]),
                               "=r"(a[mt][2]), "=r"(a[mt][3])
                             : "r"(addr));
            }
            uint32_t b[4][4];
            #pragma unroll
            for (int ntp = 0; ntp < 4; ntp++) {
                int brow = wn + ntp * 16 + ((seg >> 1) << 3) + lr;
                int bcol = s * 16 + ((seg & 1) << 3);
                uint32_t addr = bs_base + (uint32_t)(brow * S2_LD + bcol) * 2;
                asm volatile("ldmatrix.sync.aligned.m8n8.x4.shared.b16 {%0,%1,%2,%3}, [%4];"
                             : "=r"(b[ntp][0]), "=r"(b[ntp][1]),
                               "=r"(b[ntp][2]), "=r"(b[ntp][3])
                             : "r"(addr));
            }
            #pragma unroll
            for (int mt = 0; mt < 4; mt++)
                #pragma unroll
                for (int nt = 0; nt < 8; nt++) {
                    const uint32_t b0 = b[nt >> 1][(nt & 1) * 2 + 0];
                    const uint32_t b1 = b[nt >> 1][(nt & 1) * 2 + 1];
                    asm volatile(
                        "mma.sync.aligned.m16n8k16.row.col.f32.f16.f16.f32 "
                        "{%0,%1,%2,%3}, {%4,%5,%6,%7}, {%8,%9}, {%0,%1,%2,%3};"
                        : "+f"(acc[mt][nt][0]), "+f"(acc[mt][nt][1]),
                          "+f"(acc[mt][nt][2]), "+f"(acc[mt][nt][3])
                        : "r"(a[mt][0]), "r"(a[mt][1]), "r"(a[mt][2]), "r"(a[mt][3]),
                          "r"(b0), "r"(b1));
                }
        }

        const int col0 = (ct0 + it) * 256;
        #pragma unroll
        for (int mt = 0; mt < 4; mt++) {
            #pragma unroll
            for (int nt = 0; nt < 8; nt++) {
                int m = row0 + wm + mt * 16 + em;
                int n = col0 + wn + nt * 8 + en;
                *reinterpret_cast<__half2*>(&O[(size_t)m * G_ + n]) =
                    __floats2half2_rn(acc[mt][nt][0], acc[mt][nt][1]);
                *reinterpret_cast<__half2*>(&O[(size_t)(m + 8) * G_ + n]) =
                    __floats2half2_rn(acc[mt][nt][2], acc[mt][nt][3]);
            }
        }
        __syncthreads();
    }
}

// =====================================================================
// Stage 3: register-resident, min 3 CTAs/SM for latency-chain overlap.
// =====================================================================
__device__ __forceinline__ float4 block_reduce4(
    float a, float b, float c, float d, float* red)
{
    __syncthreads();
    #pragma unroll
    for (int o = 16; o > 0; o >>= 1) {
        a += __shfl_xor_sync(0xffffffffu, a, o);
        b += __shfl_xor_sync(0xffffffffu, b, o);
        c += __shfl_xor_sync(0xffffffffu, c, o);
        d += __shfl_xor_sync(0xffffffffu, d, o);
    }
    int w = threadIdx.x >> 5, l = threadIdx.x & 31;
    if (l == 0) { red[w] = a; red[8+w] = b; red[16+w] = c; red[24+w] = d; }
    __syncthreads();
    if (w == 0) {
        a = (l < 8) ? red[l]      : 0.f;
        b = (l < 8) ? red[8 + l]  : 0.f;
        c = (l < 8) ? red[16 + l] : 0.f;
        d = (l < 8) ? red[24 + l] : 0.f;
        #pragma unroll
        for (int o = 4; o > 0; o >>= 1) {
            a += __shfl_xor_sync(0xffffffffu, a, o);
            b += __shfl_xor_sync(0xffffffffu, b, o);
            c += __shfl_xor_sync(0xffffffffu, c, o);
            d += __shfl_xor_sync(0xffffffffu, d, o);
        }
        if (l == 0) { red[0] = a; red[1] = b; red[2] = c; red[3] = d; }
    }
    __syncthreads();
    return make_float4(red[0], red[1], red[2], red[3]);
}

__device__ __forceinline__ float2 block_reduce2(float s, float q, float* red)
{
    __syncthreads();
    #pragma unroll
    for (int o = 16; o > 0; o >>= 1) {
        s += __shfl_xor_sync(0xffffffffu, s, o);
        q += __shfl_xor_sync(0xffffffffu, q, o);
    }
    int w = threadIdx.x >> 5, l = threadIdx.x & 31;
    if (l == 0) { red[w] = s; red[8 + w] = q; }
    __syncthreads();
    if (w == 0) {
        s = (l < 8) ? red[l] : 0.f;
        q = (l < 8) ? red[8 + l] : 0.f;
        #pragma unroll
        for (int o = 4; o > 0; o >>= 1) {
            s += __shfl_xor_sync(0xffffffffu, s, o);
            q += __shfl_xor_sync(0xffffffffu, q, o);
        }
        if (l == 0) { red[0] = s; red[1] = q; }
    }
    __syncthreads();
    return make_float2(red[0], red[1]);
}

__device__ __forceinline__ float4 unpack4(const uint2& u)
{
    float2 f0 = __half22float2(*reinterpret_cast<const __half2*>(&u.x));
    float2 f1 = __half22float2(*reinterpret_cast<const __half2*>(&u.y));
    return make_float4(f0.x, f0.y, f1.x, f1.y);
}

__global__ __launch_bounds__(256, 3) void stage3_kernel(
    const float* __restrict__ cx,
    const float* __restrict__ lniw, const float* __restrict__ lnib,
    const float* __restrict__ lnhw, const float* __restrict__ lnhb,
    const float* __restrict__ lncw, const float* __restrict__ lncb,
    float* __restrict__ out)
{
    __shared__ float red[32];

    const int r   = blockIdx.x;
    const int tid = threadIdx.x;
    const int j   = tid * 4;
    const __half* __restrict__ ig = g_gates[0] + (size_t)r * G_;
    const __half* __restrict__ hg = g_gates[1] + (size_t)r * G_;

    uint2 uig[4], uhg[4];
    #pragma unroll
    for (int g = 0; g < 4; g++) {
        uig[g] = *reinterpret_cast<const uint2*>(ig + g * H_ + j);
        uhg[g] = *reinterpret_cast<const uint2*>(hg + g * H_ + j);
    }
    float4 cxv = reinterpret_cast<const float4*>(cx + (size_t)r * H_)[tid];

    float4 gi_v[4], gh_v[4];
    float si = 0.f, qi = 0.f, sh = 0.f, qh = 0.f;
    #pragma unroll
    for (int g = 0; g < 4; g++) {
        gi_v[g] = unpack4(uig[g]);
        gh_v[g] = unpack4(uhg[g]);
        si += gi_v[g].x + gi_v[g].y + gi_v[g].z + gi_v[g].w;
        qi += gi_v[g].x*gi_v[g].x + gi_v[g].y*gi_v[g].y
            + gi_v[g].z*gi_v[g].z + gi_v[g].w*gi_v[g].w;
        sh += gh_v[g].x + gh_v[g].y + gh_v[g].z + gh_v[g].w;
        qh += gh_v[g].x*gh_v[g].x + gh_v[g].y*gh_v[g].y
            + gh_v[g].z*gh_v[g].z + gh_v[g].w*gh_v[g].w;
    }
    float4 rr = block_reduce4(si, qi, sh, qh, red);
    float mu_i = rr.x * (1.f / G_);
    float rstd_i = rsqrtf(rr.y * (1.f / G_) - mu_i * mu_i + LN_EPS);
    float mu_h = rr.z * (1.f / G_);
    float rstd_h = rsqrtf(rr.w * (1.f / G_) - mu_h * mu_h + LN_EPS);

    const float4* lniw4 = reinterpret_cast<const float4*>(lniw);
    const float4* lnib4 = reinterpret_cast<const float4*>(lnib);
    const float4* lnhw4 = reinterpret_cast<const float4*>(lnhw);
    const float4* lnhb4 = reinterpret_cast<const float4*>(lnhb);

    float4 wi_v[4], bi_v[4], wh_v[4], bh_v[4];
    #pragma unroll
    for (int g = 0; g < 4; g++) {
        int n = g * 256 + tid;
        wi_v[g] = lniw4[n]; bi_v[g] = lnib4[n];
        wh_v[g] = lnhw4[n]; bh_v[g] = lnhb4[n];
    }

    float cc[4], oo[4];
    float cs = 0.f, cq = 0.f;
    #pragma unroll
    for (int c = 0; c < 4; c++) {
        #define GVAL(g) ((f4c(gi_v[g],c) - mu_i) * rstd_i * f4c(wi_v[g],c) + f4c(bi_v[g],c) + \
                         (f4c(gh_v[g],c) - mu_h) * rstd_h * f4c(wh_v[g],c) + f4c(bh_v[g],c))
        float gi = sigm(GVAL(0));
        float gf = sigm(GVAL(1));
        float gg = tanh_fast(GVAL(2));
        float go = sigm(GVAL(3));
        #undef GVAL
        float c_ = gf * f4c(cxv, c) + gi * gg;
        cc[c] = c_; oo[c] = go;
        cs += c_; cq += c_ * c_;
    }
    float2 rc = block_reduce2(cs, cq, red);
    float mu_c = rc.x * (1.f / H_);
    float rstd_c = rsqrtf(rc.y * (1.f / H_) - mu_c * mu_c + LN_EPS);

    float4 wcv = reinterpret_cast<const float4*>(lncw)[tid];
    float4 bcv = reinterpret_cast<const float4*>(lncb)[tid];
    float4 hyv, cyv;
    #pragma unroll
    for (int c = 0; c < 4; c++) {
        float cy = (cc[c] - mu_c) * rstd_c * f4c(wcv, c) + f4c(bcv, c);
        reinterpret_cast<float*>(&cyv)[c] = cy;
        reinterpret_cast<float*>(&hyv)[c] = oo[c] * tanh_fast(cy);
    }
    float4* out4 = reinterpret_cast<float4*>(out);
    out4[(size_t)r * 256 + tid] = hyv;
    out4[(size_t)B_ * 256 + (size_t)r * 256 + tid] = cyv;
}

// =====================================================================
extern "C" void kernel_launch(void* const* d_in, const int* in_sizes, int n_in,
                              void* d_out, int out_size)
{
    const float* input_ = (const float*)d_in[0];
    const float* hx     = (const float*)d_in[1];
    const float* cx     = (const float*)d_in[2];
    const float* topic  = (const float*)d_in[3];
    const float* w_ih_a = (const float*)d_in[4];
    const float* w_ih_b = (const float*)d_in[5];
    const float* w_ih_c = (const float*)d_in[6];
    const float* w_hh_a = (const float*)d_in[7];
    const float* w_hh_b = (const float*)d_in[8];
    const float* w_hh_c = (const float*)d_in[9];
    const float* th_ih_w = (const float*)d_in[10];
    const float* th_ih_b = (const float*)d_in[11];
    const float* th_hh_w = (const float*)d_in[12];
    const float* th_hh_b = (const float*)d_in[13];
    const float* ln_i_w  = (const float*)d_in[14];
    const float* ln_i_b  = (const float*)d_in[15];
    const float* ln_h_w  = (const float*)d_in[16];
    const float* ln_h_b  = (const float*)d_in[17];
    const float* ln_c_w  = (const float*)d_in[18];
    const float* ln_c_b  = (const float*)d_in[19];

    cudaFuncSetAttribute(stage1_mma_kernel,
                         cudaFuncAttributeMaxDynamicSharedMemorySize, S1_TOT);
    cudaFuncSetAttribute(stage2_mma_kernel,
                         cudaFuncAttributeMaxDynamicSharedMemorySize, S2_TOT);

    convert_all_kernel<<<CV_TOT / 256, 256>>>(w_ih_c, w_hh_c, w_ih_a, w_hh_a);

    stage1_mma_kernel<<<dim3(B_ / 64, 2), 256, S1_TOT>>>(
        input_, hx, topic, th_ih_w, th_ih_b, w_ih_b, th_hh_w, th_hh_b, w_hh_b);

    stage2_mma_kernel<<<dim3(G_ / 256 / NCT, B_ / 128, 2), 256, S2_TOT>>>();

    stage3_kernel<<<B_, 256>>>(cx, ln_i_w, ln_i_b, ln_h_w, ln_h_b,
                               ln_c_w, ln_c_b, (float*)d_out);
}